// round 6
// baseline (speedup 1.0000x reference)
#include <cuda_runtime.h>
#include <cuda_bf16.h>
#include <cstdint>

#define FDIM 128
#define HDIM 256
#define E_EDGES 262144
#define T_TRIP 393216
#define NPAD 20096  // 20000 padded to 157*128

#define SA_HI 0
#define SA_MID (16 * 1024)
#define SB_HI (32 * 1024)
#define SB_MID (48 * 1024)
#define STAGE_BYTES (64 * 1024)
#define SMEM_GEMM (2 * STAGE_BYTES)

__device__ __nv_bfloat16 g_x_hi[(size_t)T_TRIP * HDIM];
__device__ __nv_bfloat16 g_x_mid[(size_t)T_TRIP * HDIM];
__device__ __nv_bfloat16 g_y_hi[(size_t)T_TRIP * HDIM];
__device__ __nv_bfloat16 g_y_mid[(size_t)T_TRIP * HDIM];
__device__ __nv_bfloat16 g_h_hi[(size_t)NPAD * FDIM];
__device__ __nv_bfloat16 g_h_mid[(size_t)NPAD * FDIM];
__device__ float g_P[5ull * NPAD * HDIM];  // Pea,Peb,Pta,Ptb,Ptc
#define PSZ ((size_t)NPAD * HDIM)
// weight slices (elements), each slice is [256][KP] bf16
#define E0A 0
#define E0B 32768
#define E0C 65536
#define E1 98304
#define E2 163840
#define T0A 229376
#define T0B 262144
#define T0C 294912
#define T0D 327680
#define T1 393216
#define T2 458752
__device__ __nv_bfloat16 g_w_hi[524288];
__device__ __nv_bfloat16 g_w_mid[524288];

__device__ __forceinline__ uint32_t smem_u32(const void* p) {
    uint32_t a;
    asm("{ .reg .u64 t; cvta.to.shared.u64 t, %1; cvt.u32.u64 %0, t; }" : "=r"(a) : "l"(p));
    return a;
}
__device__ __forceinline__ void cp16(uint32_t d, const void* s) {
    asm volatile("cp.async.cg.shared.global [%0], [%1], 16;" :: "r"(d), "l"(s));
}
#define CP_COMMIT() asm volatile("cp.async.commit_group;" ::: "memory")
#define CP_WAIT0() asm volatile("cp.async.wait_group 0;" ::: "memory")
#define CP_WAIT1() asm volatile("cp.async.wait_group 1;" ::: "memory")
#define LDSM4(r0, r1, r2, r3, a) \
    asm volatile("ldmatrix.sync.aligned.m8n8.x4.shared.b16 {%0,%1,%2,%3}, [%4];" \
                 : "=r"(r0), "=r"(r1), "=r"(r2), "=r"(r3) : "r"(a))

__device__ __forceinline__ void mma_bf16(float c[4], const uint32_t a[4], const uint32_t b[2]) {
    asm volatile(
        "mma.sync.aligned.m16n8k16.row.col.f32.bf16.bf16.f32 "
        "{%0,%1,%2,%3}, {%4,%5,%6,%7}, {%8,%9}, {%0,%1,%2,%3};"
        : "+f"(c[0]), "+f"(c[1]), "+f"(c[2]), "+f"(c[3])
        : "r"(a[0]), "r"(a[1]), "r"(a[2]), "r"(a[3]), "r"(b[0]), "r"(b[1]));
}
__device__ __forceinline__ float silu_f(float x) { return x / (1.0f + __expf(-x)); }
__device__ __forceinline__ uint32_t pkbf2(__nv_bfloat16 a, __nv_bfloat16 b) {
    __nv_bfloat162 v(a, b);
    return *reinterpret_cast<uint32_t*>(&v);
}
__device__ __forceinline__ void silu_split2(float v0, float v1, uint32_t* oh, uint32_t* om) {
    float a0 = silu_f(v0), a1 = silu_f(v1);
    __nv_bfloat16 h0 = __float2bfloat16_rn(a0), h1 = __float2bfloat16_rn(a1);
    *oh = pkbf2(h0, h1);
    *om = pkbf2(__float2bfloat16_rn(a0 - __bfloat162float(h0)),
                __float2bfloat16_rn(a1 - __bfloat162float(h1)));
}
__device__ __forceinline__ void split_store(char* base_hi, char* base_mid, uint32_t off, float v) {
    __nv_bfloat16 h = __float2bfloat16_rn(v);
    *(__nv_bfloat16*)(base_hi + off) = h;
    *(__nv_bfloat16*)(base_mid + off) = __float2bfloat16_rn(v - __bfloat162float(h));
}

// ---- MMA compute over one 64-K chunk in a stage (shared by all GEMM kernels)
struct Frag {
    int a_row, a_kh, b_row, b_kh;
};
__device__ __forceinline__ void mma_chunk(uint32_t stage, int wm, int wn, const Frag& f,
                                          float acc[2][8][4]) {
#pragma unroll
    for (int ks = 0; ks < 4; ks++) {
        uint32_t aHf[2][4], aMf[2][4], bHf[8][2], bMf[8][2];
#pragma unroll
        for (int mt = 0; mt < 2; mt++) {
            int r = wm + mt * 16 + f.a_row;
            uint32_t off = r * 128 + (((ks * 2 + f.a_kh) ^ (r & 7)) << 4);
            LDSM4(aHf[mt][0], aHf[mt][1], aHf[mt][2], aHf[mt][3], stage + SA_HI + off);
            LDSM4(aMf[mt][0], aMf[mt][1], aMf[mt][2], aMf[mt][3], stage + SA_MID + off);
        }
#pragma unroll
        for (int np = 0; np < 4; np++) {
            int r = wn + np * 16 + f.b_row;
            uint32_t off = r * 128 + (((ks * 2 + f.b_kh) ^ (r & 7)) << 4);
            uint32_t r0, r1, r2, r3;
            LDSM4(r0, r1, r2, r3, stage + SB_HI + off);
            bHf[np * 2][0] = r0; bHf[np * 2][1] = r1;
            bHf[np * 2 + 1][0] = r2; bHf[np * 2 + 1][1] = r3;
            LDSM4(r0, r1, r2, r3, stage + SB_MID + off);
            bMf[np * 2][0] = r0; bMf[np * 2][1] = r1;
            bMf[np * 2 + 1][0] = r2; bMf[np * 2 + 1][1] = r3;
        }
#pragma unroll
        for (int mt = 0; mt < 2; mt++)
#pragma unroll
            for (int nt = 0; nt < 8; nt++) {
                mma_bf16(acc[mt][nt], aHf[mt], bHf[nt]);
                mma_bf16(acc[mt][nt], aHf[mt], bMf[nt]);
                mma_bf16(acc[mt][nt], aMf[mt], bHf[nt]);
            }
    }
}

__device__ __forceinline__ void load_chunk(uint32_t stage, int t, size_t koff,
                                           const char* aH, const char* aM,
                                           const char* bH, const char* bM, size_t ldb) {
#pragma unroll
    for (int i = 0; i < 4; i++) {
        int idx = t + i * 256;
        int r = idx >> 3, c16 = idx & 7;
        uint32_t doff = r * 128 + ((c16 ^ (r & 7)) << 4);
        size_t soff = (size_t)r * ldb + koff + c16 * 16;
        cp16(stage + SA_HI + doff, aH + soff);
        cp16(stage + SA_MID + doff, aM + soff);
        cp16(stage + SB_HI + doff, bH + soff);
        cp16(stage + SB_MID + doff, bM + soff);
    }
    CP_COMMIT();
}

__global__ void prep_h_kernel(const float* __restrict__ h,
                              __nv_bfloat16* __restrict__ hi, __nv_bfloat16* __restrict__ mid) {
    size_t idx = (size_t)blockIdx.x * 256 + threadIdx.x;
    int row = (int)(idx >> 7);
    float v = (row < 20000) ? h[idx] : 0.0f;
    __nv_bfloat16 hh = __float2bfloat16_rn(v);
    hi[idx] = hh;
    mid[idx] = __float2bfloat16_rn(v - __bfloat162float(hh));
}

__global__ void prep_w_kernel(const float* __restrict__ W, int K, int KP,
                              __nv_bfloat16* __restrict__ hi, __nv_bfloat16* __restrict__ mid) {
    int idx = blockIdx.x * 256 + threadIdx.x;
    int n = idx / KP, k = idx % KP;
    float v = (k < K) ? W[(size_t)k * HDIM + n] : 0.0f;
    __nv_bfloat16 h = __float2bfloat16_rn(v);
    hi[idx] = h;
    mid[idx] = __float2bfloat16_rn(v - __bfloat162float(h));
}

// C = A @ B^T (EPI=1: raw f32) or silu+limb-split (EPI=0). A:[rows,ld], B slice [256,ld].
template <int EPI>
__global__ void __launch_bounds__(256, 1) gemm_kernel(
    const __nv_bfloat16* __restrict__ Ahi, const __nv_bfloat16* __restrict__ Amid,
    const __nv_bfloat16* __restrict__ Bhi, const __nv_bfloat16* __restrict__ Bmid,
    int ld, int nchunks, void* __restrict__ C1, void* __restrict__ C2) {
    extern __shared__ char smem[];
    uint32_t sb = smem_u32(smem);
    int t = threadIdx.x, lane = t & 31, w = t >> 5;
    int row0 = blockIdx.y * 128, n0cta = blockIdx.x * 128;
    int wm = (w & 3) * 32, wn = (w >> 2) * 64;

    const char* aH = (const char*)(Ahi + (size_t)row0 * ld);
    const char* aM = (const char*)(Amid + (size_t)row0 * ld);
    const char* bH = (const char*)(Bhi + (size_t)n0cta * ld);
    const char* bM = (const char*)(Bmid + (size_t)n0cta * ld);
    const size_t ldb = (size_t)ld * 2;

    float acc[2][8][4];
#pragma unroll
    for (int i = 0; i < 2; i++)
#pragma unroll
        for (int j = 0; j < 8; j++)
#pragma unroll
            for (int q = 0; q < 4; q++) acc[i][j][q] = 0.0f;

    Frag f{lane & 15, lane >> 4, (lane & 7) + ((lane >> 4) << 3), (lane >> 3) & 1};

    load_chunk(sb, t, 0, aH, aM, bH, bM, ldb);
    for (int c = 0; c < nchunks; c++) {
        int nxt = c + 1;
        if (nxt < nchunks) {
            load_chunk(sb + (nxt & 1) * STAGE_BYTES, t, (size_t)nxt * 128, aH, aM, bH, bM, ldb);
            CP_WAIT1();
        } else {
            CP_WAIT0();
        }
        __syncthreads();
        mma_chunk(sb + (c & 1) * STAGE_BYTES, wm, wn, f, acc);
        __syncthreads();
    }

    int mrow = lane >> 2, ncol = (lane & 3) * 2;
#pragma unroll
    for (int mt = 0; mt < 2; mt++)
#pragma unroll
        for (int nt = 0; nt < 8; nt++) {
            int r = row0 + wm + mt * 16 + mrow;
            int cc = n0cta + wn + nt * 8 + ncol;
            if (EPI == 0) {
                uint32_t oh, om;
                silu_split2(acc[mt][nt][0], acc[mt][nt][1], &oh, &om);
                *(uint32_t*)((__nv_bfloat16*)C1 + (size_t)r * HDIM + cc) = oh;
                *(uint32_t*)((__nv_bfloat16*)C2 + (size_t)r * HDIM + cc) = om;
                silu_split2(acc[mt][nt][2], acc[mt][nt][3], &oh, &om);
                *(uint32_t*)((__nv_bfloat16*)C1 + (size_t)(r + 8) * HDIM + cc) = oh;
                *(uint32_t*)((__nv_bfloat16*)C2 + (size_t)(r + 8) * HDIM + cc) = om;
            } else {
                *(float2*)((float*)C1 + (size_t)r * HDIM + cc) =
                    make_float2(acc[mt][nt][0], acc[mt][nt][1]);
                *(float2*)((float*)C1 + (size_t)(r + 8) * HDIM + cc) =
                    make_float2(acc[mt][nt][2], acc[mt][nt][3]);
            }
        }
}

// L0: C = silu(rbf@W0c^T + Pa[iA] + Pb[iB] (+ Pc[iC])). A tile built in SMEM.
// MODE 0: edges, CH=2 (K=128: rbf100+pad). MODE 1: trips, CH=4 (rbf100|rbf100|cos|sin|pad).
template <int MODE>
__global__ void __launch_bounds__(256, 1) l0_kernel(
    const float* __restrict__ rA, const float* __restrict__ rB,
    const float* __restrict__ cosv, const float* __restrict__ sinv,
    const float* __restrict__ mu,
    const int* __restrict__ iA, const int* __restrict__ iB, const int* __restrict__ iC,
    const __nv_bfloat16* __restrict__ Bhi, const __nv_bfloat16* __restrict__ Bmid,
    const float* __restrict__ Pa, const float* __restrict__ Pb, const float* __restrict__ Pc,
    __nv_bfloat16* __restrict__ Chi, __nv_bfloat16* __restrict__ Cmid) {
    const int CH = MODE ? 4 : 2;
    const int KP = CH * 64;
    extern __shared__ char smem[];
    uint32_t sb = smem_u32(smem);
    int t = threadIdx.x, lane = t & 31, w = t >> 5;
    int row0 = blockIdx.y * 128, n0cta = blockIdx.x * 128;
    int wm = (w & 3) * 32, wn = (w >> 2) * 64;

    const char* bH = (const char*)(Bhi + (size_t)n0cta * KP);
    const char* bM = (const char*)(Bmid + (size_t)n0cta * KP);
    const size_t ldb = (size_t)KP * 2;

    // per-thread build params (row fixed per thread)
    int brow = t >> 1, kb = (t & 1) * 32;
    float ra = rA[row0 + brow];
    float rb = MODE ? rB[row0 + brow] : 0.0f;
    float cv = MODE ? cosv[row0 + brow] : 0.0f;
    float sv = MODE ? sinv[row0 + brow] : 0.0f;

    auto build_A = [&](int c, int s) {
        char* ah = smem + s * STAGE_BYTES + SA_HI;
        char* am = smem + s * STAGE_BYTES + SA_MID;
#pragma unroll
        for (int j = 0; j < 32; j++) {
            int kk = kb + j, k = c * 64 + kk;
            float v = 0.0f;
            if (MODE == 0) {
                if (k < 100) { float d = __ldg(mu + k) - ra; v = __expf(-10.0f * d * d); }
            } else {
                if (k < 100)      { float d = __ldg(mu + k) - ra; v = __expf(-10.0f * d * d); }
                else if (k < 200) { float d = __ldg(mu + k - 100) - rb; v = __expf(-10.0f * d * d); }
                else if (k == 200) v = cv;
                else if (k == 201) v = sv;
            }
            uint32_t off = brow * 128 + (((kk >> 3) ^ (brow & 7)) << 4) + ((kk & 7) * 2);
            split_store(ah, am, off, v);
        }
    };
    auto load_B = [&](int c, int s) {
        uint32_t stage = sb + s * STAGE_BYTES;
#pragma unroll
        for (int i = 0; i < 4; i++) {
            int idx = t + i * 256;
            int r = idx >> 3, c16 = idx & 7;
            uint32_t doff = r * 128 + ((c16 ^ (r & 7)) << 4);
            size_t soff = (size_t)r * ldb + (size_t)c * 128 + c16 * 16;
            cp16(stage + SB_HI + doff, bH + soff);
            cp16(stage + SB_MID + doff, bM + soff);
        }
        CP_COMMIT();
    };

    float acc[2][8][4];
#pragma unroll
    for (int i = 0; i < 2; i++)
#pragma unroll
        for (int j = 0; j < 8; j++)
#pragma unroll
            for (int q = 0; q < 4; q++) acc[i][j][q] = 0.0f;
    Frag f{lane & 15, lane >> 4, (lane & 7) + ((lane >> 4) << 3), (lane >> 3) & 1};

    build_A(0, 0);
    load_B(0, 0);
    for (int c = 0; c < CH; c++) {
        int nxt = c + 1;
        if (nxt < CH) {
            build_A(nxt, nxt & 1);
            load_B(nxt, nxt & 1);
            CP_WAIT1();
        } else {
            CP_WAIT0();
        }
        __syncthreads();
        mma_chunk(sb + (c & 1) * STAGE_BYTES, wm, wn, f, acc);
        __syncthreads();
    }

    // epilogue: + gathered P rows, silu, split
    int mrow = lane >> 2, ncol = (lane & 3) * 2;
    const float* pa[4];
    const float* pb[4];
    const float* pc[4];
#pragma unroll
    for (int rr = 0; rr < 4; rr++) {
        int r = row0 + wm + (rr >> 1) * 16 + (rr & 1) * 8 + mrow;
        pa[rr] = Pa + (size_t)iA[r] * HDIM;
        pb[rr] = Pb + (size_t)iB[r] * HDIM;
        if (MODE) pc[rr] = Pc + (size_t)iC[r] * HDIM;
    }
#pragma unroll
    for (int mt = 0; mt < 2; mt++)
#pragma unroll
        for (int nt = 0; nt < 8; nt++) {
            int cc = n0cta + wn + nt * 8 + ncol;
#pragma unroll
            for (int sr = 0; sr < 2; sr++) {
                int rr = mt * 2 + sr;
                int r = row0 + wm + mt * 16 + sr * 8 + mrow;
                float2 ga = *(const float2*)(pa[rr] + cc);
                float2 gb = *(const float2*)(pb[rr] + cc);
                float v0 = acc[mt][nt][sr * 2 + 0] + ga.x + gb.x;
                float v1 = acc[mt][nt][sr * 2 + 1] + ga.y + gb.y;
                if (MODE) {
                    float2 gc = *(const float2*)(pc[rr] + cc);
                    v0 += gc.x;
                    v1 += gc.y;
                }
                uint32_t oh, om;
                silu_split2(v0, v1, &oh, &om);
                *(uint32_t*)(Chi + (size_t)r * HDIM + cc) = oh;
                *(uint32_t*)(Cmid + (size_t)r * HDIM + cc) = om;
            }
        }
}

__global__ void __launch_bounds__(256) out_kernel(
    const __nv_bfloat16* __restrict__ Xhi, const __nv_bfloat16* __restrict__ Xmid,
    const float* __restrict__ W3, const float* __restrict__ b3, float* __restrict__ out) {
    __shared__ float Ws[HDIM * 3];
    int t = threadIdx.x;
    for (int i = t; i < HDIM * 3; i += 256) Ws[i] = W3[i];
    __syncthreads();
    int row = blockIdx.x * 8 + (t >> 5);
    int lane = t & 31;
    const uint32_t* ph = (const uint32_t*)Xhi + (size_t)row * 128;
    const uint32_t* pm = (const uint32_t*)Xmid + (size_t)row * 128;
    float s0 = 0.f, s1 = 0.f, s2 = 0.f;
#pragma unroll
    for (int i = 0; i < 4; i++) {
        uint32_t uh = ph[lane + i * 32], um = pm[lane + i * 32];
        __nv_bfloat162 bh = *reinterpret_cast<__nv_bfloat162*>(&uh);
        __nv_bfloat162 bm = *reinterpret_cast<__nv_bfloat162*>(&um);
        float x0 = __bfloat162float(bh.x) + __bfloat162float(bm.x);
        float x1 = __bfloat162float(bh.y) + __bfloat162float(bm.y);
        int k = 2 * (lane + i * 32);
        s0 = fmaf(x0, Ws[k * 3 + 0], s0); s1 = fmaf(x0, Ws[k * 3 + 1], s1);
        s2 = fmaf(x0, Ws[k * 3 + 2], s2);
        s0 = fmaf(x1, Ws[k * 3 + 3], s0); s1 = fmaf(x1, Ws[k * 3 + 4], s1);
        s2 = fmaf(x1, Ws[k * 3 + 5], s2);
    }
#pragma unroll
    for (int o = 16; o; o >>= 1) {
        s0 += __shfl_down_sync(0xffffffffu, s0, o);
        s1 += __shfl_down_sync(0xffffffffu, s1, o);
        s2 += __shfl_down_sync(0xffffffffu, s2, o);
    }
    if (lane == 0) {
        out[(size_t)row * 3 + 0] = s0 + b3[0];
        out[(size_t)row * 3 + 1] = s1 + b3[1];
        out[(size_t)row * 3 + 2] = s2 + b3[2];
    }
}

extern "C" void kernel_launch(void* const* d_in, const int* in_sizes, int n_in,
                              void* d_out, int out_size) {
    const float* h = (const float*)d_in[0];
    const int* src = (const int*)d_in[1];
    const int* dst = (const int*)d_in[2];
    const float* enorm = (const float*)d_in[3];
    const int* tsrc = (const int*)d_in[4];
    const int* tdi = (const int*)d_in[5];
    const int* tdj = (const int*)d_in[6];
    const float* nij = (const float*)d_in[7];
    const float* nik = (const float*)d_in[8];
    const float* cosv = (const float*)d_in[9];
    const float* sinv = (const float*)d_in[10];
    const float* mu = (const float*)d_in[11];
    const float* eW0 = (const float*)d_in[12];
    const float* eW1 = (const float*)d_in[13];
    const float* eW2 = (const float*)d_in[14];
    const float* eW3 = (const float*)d_in[15];
    const float* eb3 = (const float*)d_in[16];
    const float* tW0 = (const float*)d_in[17];
    const float* tW1 = (const float*)d_in[18];
    const float* tW2 = (const float*)d_in[19];
    const float* tW3 = (const float*)d_in[20];
    const float* tb3 = (const float*)d_in[21];
    float* out = (float*)d_out;

    __nv_bfloat16 *xH, *xM, *yH, *yM, *hH, *hM, *wH, *wM;
    float* P;
    cudaGetSymbolAddress((void**)&xH, g_x_hi);
    cudaGetSymbolAddress((void**)&xM, g_x_mid);
    cudaGetSymbolAddress((void**)&yH, g_y_hi);
    cudaGetSymbolAddress((void**)&yM, g_y_mid);
    cudaGetSymbolAddress((void**)&hH, g_h_hi);
    cudaGetSymbolAddress((void**)&hM, g_h_mid);
    cudaGetSymbolAddress((void**)&wH, g_w_hi);
    cudaGetSymbolAddress((void**)&wM, g_w_mid);
    cudaGetSymbolAddress((void**)&P, g_P);
    float *Pea = P, *Peb = P + PSZ, *Pta = P + 2 * PSZ, *Ptb = P + 3 * PSZ, *Ptc = P + 4 * PSZ;

    cudaFuncSetAttribute(gemm_kernel<0>, cudaFuncAttributeMaxDynamicSharedMemorySize, SMEM_GEMM);
    cudaFuncSetAttribute(gemm_kernel<1>, cudaFuncAttributeMaxDynamicSharedMemorySize, SMEM_GEMM);
    cudaFuncSetAttribute(l0_kernel<0>, cudaFuncAttributeMaxDynamicSharedMemorySize, SMEM_GEMM);
    cudaFuncSetAttribute(l0_kernel<1>, cudaFuncAttributeMaxDynamicSharedMemorySize, SMEM_GEMM);

    prep_h_kernel<<<(NPAD * FDIM) / 256, 256>>>(h, hH, hM);
    prep_w_kernel<<<128, 256>>>(eW0, 128, 128, wH + E0A, wM + E0A);
    prep_w_kernel<<<128, 256>>>(eW0 + 32768, 128, 128, wH + E0B, wM + E0B);
    prep_w_kernel<<<128, 256>>>(eW0 + 65536, 100, 128, wH + E0C, wM + E0C);
    prep_w_kernel<<<256, 256>>>(eW1, 256, 256, wH + E1, wM + E1);
    prep_w_kernel<<<256, 256>>>(eW2, 256, 256, wH + E2, wM + E2);
    prep_w_kernel<<<128, 256>>>(tW0, 128, 128, wH + T0A, wM + T0A);
    prep_w_kernel<<<128, 256>>>(tW0 + 32768, 128, 128, wH + T0B, wM + T0B);
    prep_w_kernel<<<128, 256>>>(tW0 + 65536, 128, 128, wH + T0C, wM + T0C);
    prep_w_kernel<<<256, 256>>>(tW0 + 98304, 202, 256, wH + T0D, wM + T0D);
    prep_w_kernel<<<256, 256>>>(tW1, 256, 256, wH + T1, wM + T1);
    prep_w_kernel<<<256, 256>>>(tW2, 256, 256, wH + T2, wM + T2);

    dim3 gp(2, NPAD / 128);
    gemm_kernel<1><<<gp, 256, SMEM_GEMM>>>(hH, hM, wH + E0A, wM + E0A, 128, 2, Pea, nullptr);
    gemm_kernel<1><<<gp, 256, SMEM_GEMM>>>(hH, hM, wH + E0B, wM + E0B, 128, 2, Peb, nullptr);
    gemm_kernel<1><<<gp, 256, SMEM_GEMM>>>(hH, hM, wH + T0A, wM + T0A, 128, 2, Pta, nullptr);
    gemm_kernel<1><<<gp, 256, SMEM_GEMM>>>(hH, hM, wH + T0B, wM + T0B, 128, 2, Ptb, nullptr);
    gemm_kernel<1><<<gp, 256, SMEM_GEMM>>>(hH, hM, wH + T0C, wM + T0C, 128, 2, Ptc, nullptr);

    dim3 ge(2, E_EDGES / 128), gt(2, T_TRIP / 128);
    l0_kernel<0><<<ge, 256, SMEM_GEMM>>>(enorm, nullptr, nullptr, nullptr, mu,
                                         src, dst, nullptr, wH + E0C, wM + E0C,
                                         Pea, Peb, nullptr, xH, xM);
    gemm_kernel<0><<<ge, 256, SMEM_GEMM>>>(xH, xM, wH + E1, wM + E1, 256, 4, yH, yM);
    gemm_kernel<0><<<ge, 256, SMEM_GEMM>>>(yH, yM, wH + E2, wM + E2, 256, 4, xH, xM);
    out_kernel<<<E_EDGES / 8, 256>>>(xH, xM, eW3, eb3, out);

    l0_kernel<1><<<gt, 256, SMEM_GEMM>>>(nij, nik, cosv, sinv, mu,
                                         tsrc, tdi, tdj, wH + T0D, wM + T0D,
                                         Pta, Ptb, Ptc, xH, xM);
    gemm_kernel<0><<<gt, 256, SMEM_GEMM>>>(xH, xM, wH + T1, wM + T1, 256, 4, yH, yM);
    gemm_kernel<0><<<gt, 256, SMEM_GEMM>>>(yH, yM, wH + T2, wM + T2, 256, 4, xH, xM);
    out_kernel<<<T_TRIP / 8, 256>>>(xH, xM, tW3, tb3, out + (size_t)E_EDGES * 3);
}

// round 7
// speedup vs baseline: 1.0022x; 1.0022x over previous
#include <cuda_runtime.h>
#include <cuda_bf16.h>
#include <cstdint>

#define FDIM 128
#define HDIM 256
#define E_EDGES 262144
#define T_TRIP 393216
#define NPAD 20096  // 20000 padded to 157*128

#define SA_HI 0
#define SA_MID (16 * 1024)
#define SB_HI (32 * 1024)
#define SB_MID (48 * 1024)
#define STAGE_BYTES (64 * 1024)
#define SMEM_GEMM (2 * STAGE_BYTES)

__device__ __nv_bfloat16 g_x_hi[(size_t)T_TRIP * HDIM];
__device__ __nv_bfloat16 g_x_mid[(size_t)T_TRIP * HDIM];
__device__ __nv_bfloat16 g_y_hi[(size_t)T_TRIP * HDIM];
__device__ __nv_bfloat16 g_y_mid[(size_t)T_TRIP * HDIM];
__device__ __nv_bfloat16 g_h_hi[(size_t)NPAD * FDIM];
__device__ __nv_bfloat16 g_h_mid[(size_t)NPAD * FDIM];
__device__ float g_P[5ull * NPAD * HDIM];  // Pea,Peb,Pta,Ptb,Ptc
#define PSZ ((size_t)NPAD * HDIM)
// weight slices (elements), each slice is [256][KP] bf16
#define E0A 0
#define E0B 32768
#define E0C 65536
#define E1 98304
#define E2 163840
#define T0A 229376
#define T0B 262144
#define T0C 294912
#define T0D 327680
#define T1 393216
#define T2 458752
__device__ __nv_bfloat16 g_w_hi[524288];
__device__ __nv_bfloat16 g_w_mid[524288];

__device__ __forceinline__ uint32_t smem_u32(const void* p) {
    uint32_t a;
    asm("{ .reg .u64 t; cvta.to.shared.u64 t, %1; cvt.u32.u64 %0, t; }" : "=r"(a) : "l"(p));
    return a;
}
__device__ __forceinline__ void cp16(uint32_t d, const void* s) {
    asm volatile("cp.async.cg.shared.global [%0], [%1], 16;" :: "r"(d), "l"(s));
}
#define CP_COMMIT() asm volatile("cp.async.commit_group;" ::: "memory")
#define CP_WAIT0() asm volatile("cp.async.wait_group 0;" ::: "memory")
#define CP_WAIT1() asm volatile("cp.async.wait_group 1;" ::: "memory")
#define LDSM4(r0, r1, r2, r3, a) \
    asm volatile("ldmatrix.sync.aligned.m8n8.x4.shared.b16 {%0,%1,%2,%3}, [%4];" \
                 : "=r"(r0), "=r"(r1), "=r"(r2), "=r"(r3) : "r"(a))

__device__ __forceinline__ void mma_bf16(float c[4], const uint32_t a[4], const uint32_t b[2]) {
    asm volatile(
        "mma.sync.aligned.m16n8k16.row.col.f32.bf16.bf16.f32 "
        "{%0,%1,%2,%3}, {%4,%5,%6,%7}, {%8,%9}, {%0,%1,%2,%3};"
        : "+f"(c[0]), "+f"(c[1]), "+f"(c[2]), "+f"(c[3])
        : "r"(a[0]), "r"(a[1]), "r"(a[2]), "r"(a[3]), "r"(b[0]), "r"(b[1]));
}
__device__ __forceinline__ float silu_f(float x) { return x / (1.0f + __expf(-x)); }
__device__ __forceinline__ uint32_t pkbf2(__nv_bfloat16 a, __nv_bfloat16 b) {
    __nv_bfloat162 v(a, b);
    return *reinterpret_cast<uint32_t*>(&v);
}
__device__ __forceinline__ void silu_split2(float v0, float v1, uint32_t* oh, uint32_t* om) {
    float a0 = silu_f(v0), a1 = silu_f(v1);
    __nv_bfloat16 h0 = __float2bfloat16_rn(a0), h1 = __float2bfloat16_rn(a1);
    *oh = pkbf2(h0, h1);
    *om = pkbf2(__float2bfloat16_rn(a0 - __bfloat162float(h0)),
                __float2bfloat16_rn(a1 - __bfloat162float(h1)));
}
__device__ __forceinline__ void split_store(char* base_hi, char* base_mid, uint32_t off, float v) {
    __nv_bfloat16 h = __float2bfloat16_rn(v);
    *(__nv_bfloat16*)(base_hi + off) = h;
    *(__nv_bfloat16*)(base_mid + off) = __float2bfloat16_rn(v - __bfloat162float(h));
}

// ---- MMA compute over one 64-K chunk in a stage (shared by all GEMM kernels)
struct Frag {
    int a_row, a_kh, b_row, b_kh;
};
__device__ __forceinline__ void mma_chunk(uint32_t stage, int wm, int wn, const Frag& f,
                                          float acc[2][8][4]) {
#pragma unroll
    for (int ks = 0; ks < 4; ks++) {
        uint32_t aHf[2][4], aMf[2][4], bHf[8][2], bMf[8][2];
#pragma unroll
        for (int mt = 0; mt < 2; mt++) {
            int r = wm + mt * 16 + f.a_row;
            uint32_t off = r * 128 + (((ks * 2 + f.a_kh) ^ (r & 7)) << 4);
            LDSM4(aHf[mt][0], aHf[mt][1], aHf[mt][2], aHf[mt][3], stage + SA_HI + off);
            LDSM4(aMf[mt][0], aMf[mt][1], aMf[mt][2], aMf[mt][3], stage + SA_MID + off);
        }
#pragma unroll
        for (int np = 0; np < 4; np++) {
            int r = wn + np * 16 + f.b_row;
            uint32_t off = r * 128 + (((ks * 2 + f.b_kh) ^ (r & 7)) << 4);
            uint32_t r0, r1, r2, r3;
            LDSM4(r0, r1, r2, r3, stage + SB_HI + off);
            bHf[np * 2][0] = r0; bHf[np * 2][1] = r1;
            bHf[np * 2 + 1][0] = r2; bHf[np * 2 + 1][1] = r3;
            LDSM4(r0, r1, r2, r3, stage + SB_MID + off);
            bMf[np * 2][0] = r0; bMf[np * 2][1] = r1;
            bMf[np * 2 + 1][0] = r2; bMf[np * 2 + 1][1] = r3;
        }
#pragma unroll
        for (int mt = 0; mt < 2; mt++)
#pragma unroll
            for (int nt = 0; nt < 8; nt++) {
                mma_bf16(acc[mt][nt], aHf[mt], bHf[nt]);
                mma_bf16(acc[mt][nt], aHf[mt], bMf[nt]);
                mma_bf16(acc[mt][nt], aMf[mt], bHf[nt]);
            }
    }
}

__device__ __forceinline__ void load_chunk(uint32_t stage, int t, size_t koff,
                                           const char* aH, const char* aM,
                                           const char* bH, const char* bM, size_t ldb) {
#pragma unroll
    for (int i = 0; i < 4; i++) {
        int idx = t + i * 256;
        int r = idx >> 3, c16 = idx & 7;
        uint32_t doff = r * 128 + ((c16 ^ (r & 7)) << 4);
        size_t soff = (size_t)r * ldb + koff + c16 * 16;
        cp16(stage + SA_HI + doff, aH + soff);
        cp16(stage + SA_MID + doff, aM + soff);
        cp16(stage + SB_HI + doff, bH + soff);
        cp16(stage + SB_MID + doff, bM + soff);
    }
    CP_COMMIT();
}

__global__ void prep_h_kernel(const float* __restrict__ h,
                              __nv_bfloat16* __restrict__ hi, __nv_bfloat16* __restrict__ mid) {
    size_t idx = (size_t)blockIdx.x * 256 + threadIdx.x;
    int row = (int)(idx >> 7);
    float v = (row < 20000) ? h[idx] : 0.0f;
    __nv_bfloat16 hh = __float2bfloat16_rn(v);
    hi[idx] = hh;
    mid[idx] = __float2bfloat16_rn(v - __bfloat162float(hh));
}

__global__ void prep_w_kernel(const float* __restrict__ W, int K, int KP,
                              __nv_bfloat16* __restrict__ hi, __nv_bfloat16* __restrict__ mid) {
    int idx = blockIdx.x * 256 + threadIdx.x;
    int n = idx / KP, k = idx % KP;
    float v = (k < K) ? W[(size_t)k * HDIM + n] : 0.0f;
    __nv_bfloat16 h = __float2bfloat16_rn(v);
    hi[idx] = h;
    mid[idx] = __float2bfloat16_rn(v - __bfloat162float(h));
}

// C = A @ B^T (EPI=1: raw f32) or silu+limb-split (EPI=0). A:[rows,ld], B slice [256,ld].
template <int EPI>
__global__ void __launch_bounds__(256, 1) gemm_kernel(
    const __nv_bfloat16* __restrict__ Ahi, const __nv_bfloat16* __restrict__ Amid,
    const __nv_bfloat16* __restrict__ Bhi, const __nv_bfloat16* __restrict__ Bmid,
    int ld, int nchunks, void* __restrict__ C1, void* __restrict__ C2) {
    extern __shared__ char smem[];
    uint32_t sb = smem_u32(smem);
    int t = threadIdx.x, lane = t & 31, w = t >> 5;
    int row0 = blockIdx.y * 128, n0cta = blockIdx.x * 128;
    int wm = (w & 3) * 32, wn = (w >> 2) * 64;

    const char* aH = (const char*)(Ahi + (size_t)row0 * ld);
    const char* aM = (const char*)(Amid + (size_t)row0 * ld);
    const char* bH = (const char*)(Bhi + (size_t)n0cta * ld);
    const char* bM = (const char*)(Bmid + (size_t)n0cta * ld);
    const size_t ldb = (size_t)ld * 2;

    float acc[2][8][4];
#pragma unroll
    for (int i = 0; i < 2; i++)
#pragma unroll
        for (int j = 0; j < 8; j++)
#pragma unroll
            for (int q = 0; q < 4; q++) acc[i][j][q] = 0.0f;

    Frag f{lane & 15, lane >> 4, (lane & 7) + ((lane >> 4) << 3), (lane >> 3) & 1};

    load_chunk(sb, t, 0, aH, aM, bH, bM, ldb);
    for (int c = 0; c < nchunks; c++) {
        int nxt = c + 1;
        if (nxt < nchunks) {
            load_chunk(sb + (nxt & 1) * STAGE_BYTES, t, (size_t)nxt * 128, aH, aM, bH, bM, ldb);
            CP_WAIT1();
        } else {
            CP_WAIT0();
        }
        __syncthreads();
        mma_chunk(sb + (c & 1) * STAGE_BYTES, wm, wn, f, acc);
        __syncthreads();
    }

    int mrow = lane >> 2, ncol = (lane & 3) * 2;
#pragma unroll
    for (int mt = 0; mt < 2; mt++)
#pragma unroll
        for (int nt = 0; nt < 8; nt++) {
            int r = row0 + wm + mt * 16 + mrow;
            int cc = n0cta + wn + nt * 8 + ncol;
            if (EPI == 0) {
                uint32_t oh, om;
                silu_split2(acc[mt][nt][0], acc[mt][nt][1], &oh, &om);
                *(uint32_t*)((__nv_bfloat16*)C1 + (size_t)r * HDIM + cc) = oh;
                *(uint32_t*)((__nv_bfloat16*)C2 + (size_t)r * HDIM + cc) = om;
                silu_split2(acc[mt][nt][2], acc[mt][nt][3], &oh, &om);
                *(uint32_t*)((__nv_bfloat16*)C1 + (size_t)(r + 8) * HDIM + cc) = oh;
                *(uint32_t*)((__nv_bfloat16*)C2 + (size_t)(r + 8) * HDIM + cc) = om;
            } else {
                *(float2*)((float*)C1 + (size_t)r * HDIM + cc) =
                    make_float2(acc[mt][nt][0], acc[mt][nt][1]);
                *(float2*)((float*)C1 + (size_t)(r + 8) * HDIM + cc) =
                    make_float2(acc[mt][nt][2], acc[mt][nt][3]);
            }
        }
}

// L0: C = silu(rbf@W0c^T + Pa[iA] + Pb[iB] (+ Pc[iC])). A tile built in SMEM.
// MODE 0: edges, CH=2 (K=128: rbf100+pad). MODE 1: trips, CH=4 (rbf100|rbf100|cos|sin|pad).
template <int MODE>
__global__ void __launch_bounds__(256, 1) l0_kernel(
    const float* __restrict__ rA, const float* __restrict__ rB,
    const float* __restrict__ cosv, const float* __restrict__ sinv,
    const float* __restrict__ mu,
    const int* __restrict__ iA, const int* __restrict__ iB, const int* __restrict__ iC,
    const __nv_bfloat16* __restrict__ Bhi, const __nv_bfloat16* __restrict__ Bmid,
    const float* __restrict__ Pa, const float* __restrict__ Pb, const float* __restrict__ Pc,
    __nv_bfloat16* __restrict__ Chi, __nv_bfloat16* __restrict__ Cmid) {
    const int CH = MODE ? 4 : 2;
    const int KP = CH * 64;
    extern __shared__ char smem[];
    uint32_t sb = smem_u32(smem);
    int t = threadIdx.x, lane = t & 31, w = t >> 5;
    int row0 = blockIdx.y * 128, n0cta = blockIdx.x * 128;
    int wm = (w & 3) * 32, wn = (w >> 2) * 64;

    const char* bH = (const char*)(Bhi + (size_t)n0cta * KP);
    const char* bM = (const char*)(Bmid + (size_t)n0cta * KP);
    const size_t ldb = (size_t)KP * 2;

    // per-thread build params (row fixed per thread)
    int brow = t >> 1, kb = (t & 1) * 32;
    float ra = rA[row0 + brow];
    float rb = MODE ? rB[row0 + brow] : 0.0f;
    float cv = MODE ? cosv[row0 + brow] : 0.0f;
    float sv = MODE ? sinv[row0 + brow] : 0.0f;

    auto build_A = [&](int c, int s) {
        char* ah = smem + s * STAGE_BYTES + SA_HI;
        char* am = smem + s * STAGE_BYTES + SA_MID;
#pragma unroll
        for (int j = 0; j < 32; j++) {
            int kk = kb + j, k = c * 64 + kk;
            float v = 0.0f;
            if (MODE == 0) {
                if (k < 100) { float d = __ldg(mu + k) - ra; v = __expf(-10.0f * d * d); }
            } else {
                if (k < 100)      { float d = __ldg(mu + k) - ra; v = __expf(-10.0f * d * d); }
                else if (k < 200) { float d = __ldg(mu + k - 100) - rb; v = __expf(-10.0f * d * d); }
                else if (k == 200) v = cv;
                else if (k == 201) v = sv;
            }
            uint32_t off = brow * 128 + (((kk >> 3) ^ (brow & 7)) << 4) + ((kk & 7) * 2);
            split_store(ah, am, off, v);
        }
    };
    auto load_B = [&](int c, int s) {
        uint32_t stage = sb + s * STAGE_BYTES;
#pragma unroll
        for (int i = 0; i < 4; i++) {
            int idx = t + i * 256;
            int r = idx >> 3, c16 = idx & 7;
            uint32_t doff = r * 128 + ((c16 ^ (r & 7)) << 4);
            size_t soff = (size_t)r * ldb + (size_t)c * 128 + c16 * 16;
            cp16(stage + SB_HI + doff, bH + soff);
            cp16(stage + SB_MID + doff, bM + soff);
        }
        CP_COMMIT();
    };

    float acc[2][8][4];
#pragma unroll
    for (int i = 0; i < 2; i++)
#pragma unroll
        for (int j = 0; j < 8; j++)
#pragma unroll
            for (int q = 0; q < 4; q++) acc[i][j][q] = 0.0f;
    Frag f{lane & 15, lane >> 4, (lane & 7) + ((lane >> 4) << 3), (lane >> 3) & 1};

    build_A(0, 0);
    load_B(0, 0);
    for (int c = 0; c < CH; c++) {
        int nxt = c + 1;
        if (nxt < CH) {
            build_A(nxt, nxt & 1);
            load_B(nxt, nxt & 1);
            CP_WAIT1();
        } else {
            CP_WAIT0();
        }
        __syncthreads();
        mma_chunk(sb + (c & 1) * STAGE_BYTES, wm, wn, f, acc);
        __syncthreads();
    }

    // epilogue: + gathered P rows, silu, split
    int mrow = lane >> 2, ncol = (lane & 3) * 2;
    const float* pa[4];
    const float* pb[4];
    const float* pc[4];
#pragma unroll
    for (int rr = 0; rr < 4; rr++) {
        int r = row0 + wm + (rr >> 1) * 16 + (rr & 1) * 8 + mrow;
        pa[rr] = Pa + (size_t)iA[r] * HDIM;
        pb[rr] = Pb + (size_t)iB[r] * HDIM;
        if (MODE) pc[rr] = Pc + (size_t)iC[r] * HDIM;
    }
#pragma unroll
    for (int mt = 0; mt < 2; mt++)
#pragma unroll
        for (int nt = 0; nt < 8; nt++) {
            int cc = n0cta + wn + nt * 8 + ncol;
#pragma unroll
            for (int sr = 0; sr < 2; sr++) {
                int rr = mt * 2 + sr;
                int r = row0 + wm + mt * 16 + sr * 8 + mrow;
                float2 ga = *(const float2*)(pa[rr] + cc);
                float2 gb = *(const float2*)(pb[rr] + cc);
                float v0 = acc[mt][nt][sr * 2 + 0] + ga.x + gb.x;
                float v1 = acc[mt][nt][sr * 2 + 1] + ga.y + gb.y;
                if (MODE) {
                    float2 gc = *(const float2*)(pc[rr] + cc);
                    v0 += gc.x;
                    v1 += gc.y;
                }
                uint32_t oh, om;
                silu_split2(v0, v1, &oh, &om);
                *(uint32_t*)(Chi + (size_t)r * HDIM + cc) = oh;
                *(uint32_t*)(Cmid + (size_t)r * HDIM + cc) = om;
            }
        }
}

__global__ void __launch_bounds__(256) out_kernel(
    const __nv_bfloat16* __restrict__ Xhi, const __nv_bfloat16* __restrict__ Xmid,
    const float* __restrict__ W3, const float* __restrict__ b3, float* __restrict__ out) {
    __shared__ float Ws[HDIM * 3];
    int t = threadIdx.x;
    for (int i = t; i < HDIM * 3; i += 256) Ws[i] = W3[i];
    __syncthreads();
    int row = blockIdx.x * 8 + (t >> 5);
    int lane = t & 31;
    const uint32_t* ph = (const uint32_t*)Xhi + (size_t)row * 128;
    const uint32_t* pm = (const uint32_t*)Xmid + (size_t)row * 128;
    float s0 = 0.f, s1 = 0.f, s2 = 0.f;
#pragma unroll
    for (int i = 0; i < 4; i++) {
        uint32_t uh = ph[lane + i * 32], um = pm[lane + i * 32];
        __nv_bfloat162 bh = *reinterpret_cast<__nv_bfloat162*>(&uh);
        __nv_bfloat162 bm = *reinterpret_cast<__nv_bfloat162*>(&um);
        float x0 = __bfloat162float(bh.x) + __bfloat162float(bm.x);
        float x1 = __bfloat162float(bh.y) + __bfloat162float(bm.y);
        int k = 2 * (lane + i * 32);
        s0 = fmaf(x0, Ws[k * 3 + 0], s0); s1 = fmaf(x0, Ws[k * 3 + 1], s1);
        s2 = fmaf(x0, Ws[k * 3 + 2], s2);
        s0 = fmaf(x1, Ws[k * 3 + 3], s0); s1 = fmaf(x1, Ws[k * 3 + 4], s1);
        s2 = fmaf(x1, Ws[k * 3 + 5], s2);
    }
#pragma unroll
    for (int o = 16; o; o >>= 1) {
        s0 += __shfl_down_sync(0xffffffffu, s0, o);
        s1 += __shfl_down_sync(0xffffffffu, s1, o);
        s2 += __shfl_down_sync(0xffffffffu, s2, o);
    }
    if (lane == 0) {
        out[(size_t)row * 3 + 0] = s0 + b3[0];
        out[(size_t)row * 3 + 1] = s1 + b3[1];
        out[(size_t)row * 3 + 2] = s2 + b3[2];
    }
}

extern "C" void kernel_launch(void* const* d_in, const int* in_sizes, int n_in,
                              void* d_out, int out_size) {
    const float* h = (const float*)d_in[0];
    const int* src = (const int*)d_in[1];
    const int* dst = (const int*)d_in[2];
    const float* enorm = (const float*)d_in[3];
    const int* tsrc = (const int*)d_in[4];
    const int* tdi = (const int*)d_in[5];
    const int* tdj = (const int*)d_in[6];
    const float* nij = (const float*)d_in[7];
    const float* nik = (const float*)d_in[8];
    const float* cosv = (const float*)d_in[9];
    const float* sinv = (const float*)d_in[10];
    const float* mu = (const float*)d_in[11];
    const float* eW0 = (const float*)d_in[12];
    const float* eW1 = (const float*)d_in[13];
    const float* eW2 = (const float*)d_in[14];
    const float* eW3 = (const float*)d_in[15];
    const float* eb3 = (const float*)d_in[16];
    const float* tW0 = (const float*)d_in[17];
    const float* tW1 = (const float*)d_in[18];
    const float* tW2 = (const float*)d_in[19];
    const float* tW3 = (const float*)d_in[20];
    const float* tb3 = (const float*)d_in[21];
    float* out = (float*)d_out;

    __nv_bfloat16 *xH, *xM, *yH, *yM, *hH, *hM, *wH, *wM;
    float* P;
    cudaGetSymbolAddress((void**)&xH, g_x_hi);
    cudaGetSymbolAddress((void**)&xM, g_x_mid);
    cudaGetSymbolAddress((void**)&yH, g_y_hi);
    cudaGetSymbolAddress((void**)&yM, g_y_mid);
    cudaGetSymbolAddress((void**)&hH, g_h_hi);
    cudaGetSymbolAddress((void**)&hM, g_h_mid);
    cudaGetSymbolAddress((void**)&wH, g_w_hi);
    cudaGetSymbolAddress((void**)&wM, g_w_mid);
    cudaGetSymbolAddress((void**)&P, g_P);
    float *Pea = P, *Peb = P + PSZ, *Pta = P + 2 * PSZ, *Ptb = P + 3 * PSZ, *Ptc = P + 4 * PSZ;

    cudaFuncSetAttribute(gemm_kernel<0>, cudaFuncAttributeMaxDynamicSharedMemorySize, SMEM_GEMM);
    cudaFuncSetAttribute(gemm_kernel<1>, cudaFuncAttributeMaxDynamicSharedMemorySize, SMEM_GEMM);
    cudaFuncSetAttribute(l0_kernel<0>, cudaFuncAttributeMaxDynamicSharedMemorySize, SMEM_GEMM);
    cudaFuncSetAttribute(l0_kernel<1>, cudaFuncAttributeMaxDynamicSharedMemorySize, SMEM_GEMM);

    prep_h_kernel<<<(NPAD * FDIM) / 256, 256>>>(h, hH, hM);
    prep_w_kernel<<<128, 256>>>(eW0, 128, 128, wH + E0A, wM + E0A);
    prep_w_kernel<<<128, 256>>>(eW0 + 32768, 128, 128, wH + E0B, wM + E0B);
    prep_w_kernel<<<128, 256>>>(eW0 + 65536, 100, 128, wH + E0C, wM + E0C);
    prep_w_kernel<<<256, 256>>>(eW1, 256, 256, wH + E1, wM + E1);
    prep_w_kernel<<<256, 256>>>(eW2, 256, 256, wH + E2, wM + E2);
    prep_w_kernel<<<128, 256>>>(tW0, 128, 128, wH + T0A, wM + T0A);
    prep_w_kernel<<<128, 256>>>(tW0 + 32768, 128, 128, wH + T0B, wM + T0B);
    prep_w_kernel<<<128, 256>>>(tW0 + 65536, 128, 128, wH + T0C, wM + T0C);
    prep_w_kernel<<<256, 256>>>(tW0 + 98304, 202, 256, wH + T0D, wM + T0D);
    prep_w_kernel<<<256, 256>>>(tW1, 256, 256, wH + T1, wM + T1);
    prep_w_kernel<<<256, 256>>>(tW2, 256, 256, wH + T2, wM + T2);

    dim3 gp(2, NPAD / 128);
    gemm_kernel<1><<<gp, 256, SMEM_GEMM>>>(hH, hM, wH + E0A, wM + E0A, 128, 2, Pea, nullptr);
    gemm_kernel<1><<<gp, 256, SMEM_GEMM>>>(hH, hM, wH + E0B, wM + E0B, 128, 2, Peb, nullptr);
    gemm_kernel<1><<<gp, 256, SMEM_GEMM>>>(hH, hM, wH + T0A, wM + T0A, 128, 2, Pta, nullptr);
    gemm_kernel<1><<<gp, 256, SMEM_GEMM>>>(hH, hM, wH + T0B, wM + T0B, 128, 2, Ptb, nullptr);
    gemm_kernel<1><<<gp, 256, SMEM_GEMM>>>(hH, hM, wH + T0C, wM + T0C, 128, 2, Ptc, nullptr);

    dim3 ge(2, E_EDGES / 128), gt(2, T_TRIP / 128);
    l0_kernel<0><<<ge, 256, SMEM_GEMM>>>(enorm, nullptr, nullptr, nullptr, mu,
                                         src, dst, nullptr, wH + E0C, wM + E0C,
                                         Pea, Peb, nullptr, xH, xM);
    gemm_kernel<0><<<ge, 256, SMEM_GEMM>>>(xH, xM, wH + E1, wM + E1, 256, 4, yH, yM);
    gemm_kernel<0><<<ge, 256, SMEM_GEMM>>>(yH, yM, wH + E2, wM + E2, 256, 4, xH, xM);
    out_kernel<<<E_EDGES / 8, 256>>>(xH, xM, eW3, eb3, out);

    l0_kernel<1><<<gt, 256, SMEM_GEMM>>>(nij, nik, cosv, sinv, mu,
                                         tsrc, tdi, tdj, wH + T0D, wM + T0D,
                                         Pta, Ptb, Ptc, xH, xM);
    gemm_kernel<0><<<gt, 256, SMEM_GEMM>>>(xH, xM, wH + T1, wM + T1, 256, 4, yH, yM);
    gemm_kernel<0><<<gt, 256, SMEM_GEMM>>>(yH, yM, wH + T2, wM + T2, 256, 4, xH, xM);
    out_kernel<<<T_TRIP / 8, 256>>>(xH, xM, tW3, tb3, out + (size_t)E_EDGES * 3);
}

// round 8
// speedup vs baseline: 1.0627x; 1.0604x over previous
#include <cuda_runtime.h>
#include <cuda_bf16.h>
#include <cstdint>

#define FDIM 128
#define HDIM 256
#define E_EDGES 262144
#define T_TRIP 393216
#define NPAD 20096

#define SA_HI 0
#define SA_MID (16 * 1024)
#define SB_HI (32 * 1024)
#define SB_MID (48 * 1024)
#define STAGE_BYTES (64 * 1024)
#define NSTAGE 3
#define SMEM_GEMM (NSTAGE * STAGE_BYTES)

__device__ __nv_bfloat16 g_x_hi[(size_t)T_TRIP * HDIM];
__device__ __nv_bfloat16 g_x_mid[(size_t)T_TRIP * HDIM];
__device__ __nv_bfloat16 g_y_hi[(size_t)T_TRIP * HDIM];
__device__ __nv_bfloat16 g_y_mid[(size_t)T_TRIP * HDIM];
__device__ __nv_bfloat16 g_h_hi[(size_t)NPAD * FDIM];
__device__ __nv_bfloat16 g_h_mid[(size_t)NPAD * FDIM];
__device__ float g_P[5ull * NPAD * HDIM];
#define PSZ ((size_t)NPAD * HDIM)
#define E0A 0
#define E0B 32768
#define E0C 65536
#define E1 98304
#define E2 163840
#define T0A 229376
#define T0B 262144
#define T0C 294912
#define T0D 327680
#define T1 393216
#define T2 458752
__device__ __nv_bfloat16 g_w_hi[524288];
__device__ __nv_bfloat16 g_w_mid[524288];

__device__ __forceinline__ uint32_t smem_u32(const void* p) {
    uint32_t a;
    asm("{ .reg .u64 t; cvta.to.shared.u64 t, %1; cvt.u32.u64 %0, t; }" : "=r"(a) : "l"(p));
    return a;
}
__device__ __forceinline__ void cp16(uint32_t d, const void* s) {
    asm volatile("cp.async.cg.shared.global [%0], [%1], 16;" :: "r"(d), "l"(s));
}
#define CP_COMMIT() asm volatile("cp.async.commit_group;" ::: "memory")
#define CP_WAIT0() asm volatile("cp.async.wait_group 0;" ::: "memory")
#define CP_WAIT1() asm volatile("cp.async.wait_group 1;" ::: "memory")
#define LDSM4(r0, r1, r2, r3, a) \
    asm volatile("ldmatrix.sync.aligned.m8n8.x4.shared.b16 {%0,%1,%2,%3}, [%4];" \
                 : "=r"(r0), "=r"(r1), "=r"(r2), "=r"(r3) : "r"(a))

__device__ __forceinline__ void mma_bf16(float c[4], const uint32_t a[4], const uint32_t b[2]) {
    asm volatile(
        "mma.sync.aligned.m16n8k16.row.col.f32.bf16.bf16.f32 "
        "{%0,%1,%2,%3}, {%4,%5,%6,%7}, {%8,%9}, {%0,%1,%2,%3};"
        : "+f"(c[0]), "+f"(c[1]), "+f"(c[2]), "+f"(c[3])
        : "r"(a[0]), "r"(a[1]), "r"(a[2]), "r"(a[3]), "r"(b[0]), "r"(b[1]));
}
__device__ __forceinline__ float silu_f(float x) { return x / (1.0f + __expf(-x)); }
__device__ __forceinline__ uint32_t pkbf2(__nv_bfloat16 a, __nv_bfloat16 b) {
    __nv_bfloat162 v(a, b);
    return *reinterpret_cast<uint32_t*>(&v);
}
__device__ __forceinline__ void silu_split2(float v0, float v1, uint32_t* oh, uint32_t* om) {
    float a0 = silu_f(v0), a1 = silu_f(v1);
    __nv_bfloat16 h0 = __float2bfloat16_rn(a0), h1 = __float2bfloat16_rn(a1);
    *oh = pkbf2(h0, h1);
    *om = pkbf2(__float2bfloat16_rn(a0 - __bfloat162float(h0)),
                __float2bfloat16_rn(a1 - __bfloat162float(h1)));
}
__device__ __forceinline__ void split_store(char* bh, char* bm, uint32_t off, float v) {
    __nv_bfloat16 h = __float2bfloat16_rn(v);
    *(__nv_bfloat16*)(bh + off) = h;
    *(__nv_bfloat16*)(bm + off) = __float2bfloat16_rn(v - __bfloat162float(h));
}

struct Frag {
    int a_row, a_kh, b_row, b_kh;
};
__device__ __forceinline__ void mma_chunk(uint32_t stage, int wm, int wn, const Frag& f,
                                          float acc[2][8][4]) {
#pragma unroll
    for (int ks = 0; ks < 4; ks++) {
        uint32_t aHf[2][4], aMf[2][4], bHf[8][2], bMf[8][2];
#pragma unroll
        for (int mt = 0; mt < 2; mt++) {
            int r = wm + mt * 16 + f.a_row;
            uint32_t off = r * 128 + (((ks * 2 + f.a_kh) ^ (r & 7)) << 4);
            LDSM4(aHf[mt][0], aHf[mt][1], aHf[mt][2], aHf[mt][3], stage + SA_HI + off);
            LDSM4(aMf[mt][0], aMf[mt][1], aMf[mt][2], aMf[mt][3], stage + SA_MID + off);
        }
#pragma unroll
        for (int np = 0; np < 4; np++) {
            int r = wn + np * 16 + f.b_row;
            uint32_t off = r * 128 + (((ks * 2 + f.b_kh) ^ (r & 7)) << 4);
            uint32_t r0, r1, r2, r3;
            LDSM4(r0, r1, r2, r3, stage + SB_HI + off);
            bHf[np * 2][0] = r0; bHf[np * 2][1] = r1;
            bHf[np * 2 + 1][0] = r2; bHf[np * 2 + 1][1] = r3;
            LDSM4(r0, r1, r2, r3, stage + SB_MID + off);
            bMf[np * 2][0] = r0; bMf[np * 2][1] = r1;
            bMf[np * 2 + 1][0] = r2; bMf[np * 2 + 1][1] = r3;
        }
#pragma unroll
        for (int mt = 0; mt < 2; mt++)
#pragma unroll
            for (int nt = 0; nt < 8; nt++) {
                mma_bf16(acc[mt][nt], aHf[mt], bHf[nt]);
                mma_bf16(acc[mt][nt], aHf[mt], bMf[nt]);
                mma_bf16(acc[mt][nt], aMf[mt], bHf[nt]);
            }
    }
}

__device__ __forceinline__ void load_chunk(uint32_t stage, int t, size_t koff,
                                           const char* aH, const char* aM,
                                           const char* bH, const char* bM, size_t ldb) {
#pragma unroll
    for (int i = 0; i < 4; i++) {
        int idx = t + i * 256;
        int r = idx >> 3, c16 = idx & 7;
        uint32_t doff = r * 128 + ((c16 ^ (r & 7)) << 4);
        size_t soff = (size_t)r * ldb + koff + c16 * 16;
        cp16(stage + SA_HI + doff, aH + soff);
        cp16(stage + SA_MID + doff, aM + soff);
        cp16(stage + SB_HI + doff, bH + soff);
        cp16(stage + SB_MID + doff, bM + soff);
    }
    CP_COMMIT();
}

// Shared GEMM core: 3-stage cp.async pipeline, one barrier per chunk.
template <int EPI>
__device__ __forceinline__ void gemm_core(
    const __nv_bfloat16* Ahi, const __nv_bfloat16* Amid,
    const __nv_bfloat16* Bhi, const __nv_bfloat16* Bmid,
    int ld, int nchunks, void* C1, void* C2, int row0, int n0cta, char* smem) {
    uint32_t sb = smem_u32(smem);
    int t = threadIdx.x, lane = t & 31, w = t >> 5;
    int wm = (w & 3) * 32, wn = (w >> 2) * 64;

    const char* aH = (const char*)(Ahi + (size_t)row0 * ld);
    const char* aM = (const char*)(Amid + (size_t)row0 * ld);
    const char* bH = (const char*)(Bhi + (size_t)n0cta * ld);
    const char* bM = (const char*)(Bmid + (size_t)n0cta * ld);
    const size_t ldb = (size_t)ld * 2;

    float acc[2][8][4];
#pragma unroll
    for (int i = 0; i < 2; i++)
#pragma unroll
        for (int j = 0; j < 8; j++)
#pragma unroll
            for (int q = 0; q < 4; q++) acc[i][j][q] = 0.0f;
    Frag f{lane & 15, lane >> 4, (lane & 7) + ((lane >> 4) << 3), (lane >> 3) & 1};

    load_chunk(sb, t, 0, aH, aM, bH, bM, ldb);
    if (nchunks > 1) load_chunk(sb + STAGE_BYTES, t, 128, aH, aM, bH, bM, ldb);

    for (int c = 0; c < nchunks; c++) {
        if (c + 1 < nchunks) CP_WAIT1(); else CP_WAIT0();
        __syncthreads();
        if (c + 2 < nchunks)
            load_chunk(sb + ((c + 2) % NSTAGE) * STAGE_BYTES, t, (size_t)(c + 2) * 128,
                       aH, aM, bH, bM, ldb);
        mma_chunk(sb + (c % NSTAGE) * STAGE_BYTES, wm, wn, f, acc);
    }

    int mrow = lane >> 2, ncol = (lane & 3) * 2;
#pragma unroll
    for (int mt = 0; mt < 2; mt++)
#pragma unroll
        for (int nt = 0; nt < 8; nt++) {
            int r = row0 + wm + mt * 16 + mrow;
            int cc = n0cta + wn + nt * 8 + ncol;
            if (EPI == 0) {
                uint32_t oh, om;
                silu_split2(acc[mt][nt][0], acc[mt][nt][1], &oh, &om);
                *(uint32_t*)((__nv_bfloat16*)C1 + (size_t)r * HDIM + cc) = oh;
                *(uint32_t*)((__nv_bfloat16*)C2 + (size_t)r * HDIM + cc) = om;
                silu_split2(acc[mt][nt][2], acc[mt][nt][3], &oh, &om);
                *(uint32_t*)((__nv_bfloat16*)C1 + (size_t)(r + 8) * HDIM + cc) = oh;
                *(uint32_t*)((__nv_bfloat16*)C2 + (size_t)(r + 8) * HDIM + cc) = om;
            } else {
                *(float2*)((float*)C1 + (size_t)r * HDIM + cc) =
                    make_float2(acc[mt][nt][0], acc[mt][nt][1]);
                *(float2*)((float*)C1 + (size_t)(r + 8) * HDIM + cc) =
                    make_float2(acc[mt][nt][2], acc[mt][nt][3]);
            }
        }
}

template <int EPI>
__global__ void __launch_bounds__(256, 1) gemm_kernel(
    const __nv_bfloat16* __restrict__ Ahi, const __nv_bfloat16* __restrict__ Amid,
    const __nv_bfloat16* __restrict__ Bhi, const __nv_bfloat16* __restrict__ Bmid,
    int ld, int nchunks, void* __restrict__ C1, void* __restrict__ C2) {
    extern __shared__ char smem[];
    gemm_core<EPI>(Ahi, Amid, Bhi, Bmid, ld, nchunks, C1, C2,
                   blockIdx.y * 128, blockIdx.x * 128, smem);
}

// Fused 5-way P precompute: z selects weight slice / output.
struct PG {
    int boff[5];
    size_t coff[5];
};
__global__ void __launch_bounds__(256, 1) pgemm_kernel(
    const __nv_bfloat16* __restrict__ hH, const __nv_bfloat16* __restrict__ hM,
    const __nv_bfloat16* __restrict__ wH, const __nv_bfloat16* __restrict__ wM,
    float* __restrict__ P, PG pg) {
    extern __shared__ char smem[];
    int z = blockIdx.z;
    gemm_core<1>(hH, hM, wH + pg.boff[z], wM + pg.boff[z], 128, 2,
                 P + pg.coff[z], nullptr, blockIdx.y * 128, blockIdx.x * 128, smem);
}

__global__ void prep_h_kernel(const float* __restrict__ h,
                              __nv_bfloat16* __restrict__ hi, __nv_bfloat16* __restrict__ mid) {
    size_t idx = (size_t)blockIdx.x * 256 + threadIdx.x;
    int row = (int)(idx >> 7);
    float v = (row < 20000) ? h[idx] : 0.0f;
    __nv_bfloat16 hh = __float2bfloat16_rn(v);
    hi[idx] = hh;
    mid[idx] = __float2bfloat16_rn(v - __bfloat162float(hh));
}

// Fused weight prep: z selects one of 11 slices.
struct WS {
    const float* src[11];
    int K[11], KP[11], off[11];
};
__global__ void prep_w_kernel(WS S, __nv_bfloat16* __restrict__ hi,
                              __nv_bfloat16* __restrict__ mid) {
    int z = blockIdx.z;
    int KP = S.KP[z];
    if (blockIdx.x >= KP) return;
    int idx = blockIdx.x * 256 + threadIdx.x;
    int n = idx / KP, k = idx % KP;
    float v = (k < S.K[z]) ? S.src[z][(size_t)k * HDIM + n] : 0.0f;
    __nv_bfloat16 h = __float2bfloat16_rn(v);
    hi[S.off[z] + idx] = h;
    mid[S.off[z] + idx] = __float2bfloat16_rn(v - __bfloat162float(h));
}

// L0: C = silu(rbf@Wc^T + Pa[iA] + Pb[iB] (+Pc[iC])).
template <int MODE>
__global__ void __launch_bounds__(256, 1) l0_kernel(
    const float* __restrict__ rA, const float* __restrict__ rB,
    const float* __restrict__ cosv, const float* __restrict__ sinv,
    const float* __restrict__ mu,
    const int* __restrict__ iA, const int* __restrict__ iB, const int* __restrict__ iC,
    const __nv_bfloat16* __restrict__ Bhi, const __nv_bfloat16* __restrict__ Bmid,
    const float* __restrict__ Pa, const float* __restrict__ Pb, const float* __restrict__ Pc,
    __nv_bfloat16* __restrict__ Chi, __nv_bfloat16* __restrict__ Cmid) {
    const int CH = MODE ? 4 : 2;
    const int KP = CH * 64;
    extern __shared__ char smem[];
    uint32_t sb = smem_u32(smem);
    int t = threadIdx.x, lane = t & 31, w = t >> 5;
    int row0 = blockIdx.y * 128, n0cta = blockIdx.x * 128;
    int wm = (w & 3) * 32, wn = (w >> 2) * 64;

    const char* bH = (const char*)(Bhi + (size_t)n0cta * KP);
    const char* bM = (const char*)(Bmid + (size_t)n0cta * KP);
    const size_t ldb = (size_t)KP * 2;

    int brow = t >> 1, kb = (t & 1) * 32;
    float ra = rA[row0 + brow];
    float rb = MODE ? rB[row0 + brow] : 0.0f;
    float cv = MODE ? cosv[row0 + brow] : 0.0f;
    float sv = MODE ? sinv[row0 + brow] : 0.0f;

    auto build_A = [&](int c, int s) {
        char* ah = smem + s * STAGE_BYTES + SA_HI;
        char* am = smem + s * STAGE_BYTES + SA_MID;
#pragma unroll
        for (int j = 0; j < 32; j++) {
            int kk = kb + j, k = c * 64 + kk;
            float v = 0.0f;
            if (MODE == 0) {
                if (k < 100) { float d = __ldg(mu + k) - ra; v = __expf(-10.0f * d * d); }
            } else {
                if (k < 100)      { float d = __ldg(mu + k) - ra; v = __expf(-10.0f * d * d); }
                else if (k < 200) { float d = __ldg(mu + k - 100) - rb; v = __expf(-10.0f * d * d); }
                else if (k == 200) v = cv;
                else if (k == 201) v = sv;
            }
            uint32_t off = brow * 128 + (((kk >> 3) ^ (brow & 7)) << 4) + ((kk & 7) * 2);
            split_store(ah, am, off, v);
        }
    };
    auto load_B = [&](int c, int s) {
        uint32_t stage = sb + s * STAGE_BYTES;
#pragma unroll
        for (int i = 0; i < 4; i++) {
            int idx = t + i * 256;
            int r = idx >> 3, c16 = idx & 7;
            uint32_t doff = r * 128 + ((c16 ^ (r & 7)) << 4);
            size_t soff = (size_t)r * ldb + (size_t)c * 128 + c16 * 16;
            cp16(stage + SB_HI + doff, bH + soff);
            cp16(stage + SB_MID + doff, bM + soff);
        }
        CP_COMMIT();
    };

    float acc[2][8][4];
#pragma unroll
    for (int i = 0; i < 2; i++)
#pragma unroll
        for (int j = 0; j < 8; j++)
#pragma unroll
            for (int q = 0; q < 4; q++) acc[i][j][q] = 0.0f;
    Frag f{lane & 15, lane >> 4, (lane & 7) + ((lane >> 4) << 3), (lane >> 3) & 1};

    build_A(0, 0);
    load_B(0, 0);
    if (CH > 1) { build_A(1, 1); load_B(1, 1); }
    for (int c = 0; c < CH; c++) {
        if (c + 1 < CH) CP_WAIT1(); else CP_WAIT0();
        __syncthreads();
        if (c + 2 < CH) { build_A(c + 2, (c + 2) % NSTAGE); load_B(c + 2, (c + 2) % NSTAGE); }
        mma_chunk(sb + (c % NSTAGE) * STAGE_BYTES, wm, wn, f, acc);
    }

    int mrow = lane >> 2, ncol = (lane & 3) * 2;
    const float* pa[4];
    const float* pb[4];
    const float* pc[4];
#pragma unroll
    for (int rr = 0; rr < 4; rr++) {
        int r = row0 + wm + (rr >> 1) * 16 + (rr & 1) * 8 + mrow;
        pa[rr] = Pa + (size_t)iA[r] * HDIM;
        pb[rr] = Pb + (size_t)iB[r] * HDIM;
        if (MODE) pc[rr] = Pc + (size_t)iC[r] * HDIM;
    }
#pragma unroll
    for (int mt = 0; mt < 2; mt++)
#pragma unroll
        for (int nt = 0; nt < 8; nt++) {
            int cc = n0cta + wn + nt * 8 + ncol;
#pragma unroll
            for (int sr = 0; sr < 2; sr++) {
                int rr = mt * 2 + sr;
                int r = row0 + wm + mt * 16 + sr * 8 + mrow;
                float2 ga = *(const float2*)(pa[rr] + cc);
                float2 gb = *(const float2*)(pb[rr] + cc);
                float v0 = acc[mt][nt][sr * 2 + 0] + ga.x + gb.x;
                float v1 = acc[mt][nt][sr * 2 + 1] + ga.y + gb.y;
                if (MODE) {
                    float2 gc = *(const float2*)(pc[rr] + cc);
                    v0 += gc.x;
                    v1 += gc.y;
                }
                uint32_t oh, om;
                silu_split2(v0, v1, &oh, &om);
                *(uint32_t*)(Chi + (size_t)r * HDIM + cc) = oh;
                *(uint32_t*)(Cmid + (size_t)r * HDIM + cc) = om;
            }
        }
}

__global__ void __launch_bounds__(256) out_kernel(
    const __nv_bfloat16* __restrict__ Xhi, const __nv_bfloat16* __restrict__ Xmid,
    const float* __restrict__ W3, const float* __restrict__ b3, float* __restrict__ out) {
    __shared__ float Ws[HDIM * 3];
    int t = threadIdx.x;
    for (int i = t; i < HDIM * 3; i += 256) Ws[i] = W3[i];
    __syncthreads();
    int row = blockIdx.x * 8 + (t >> 5);
    int lane = t & 31;
    const uint32_t* ph = (const uint32_t*)Xhi + (size_t)row * 128;
    const uint32_t* pm = (const uint32_t*)Xmid + (size_t)row * 128;
    float s0 = 0.f, s1 = 0.f, s2 = 0.f;
#pragma unroll
    for (int i = 0; i < 4; i++) {
        uint32_t uh = ph[lane + i * 32], um = pm[lane + i * 32];
        __nv_bfloat162 bh = *reinterpret_cast<__nv_bfloat162*>(&uh);
        __nv_bfloat162 bm = *reinterpret_cast<__nv_bfloat162*>(&um);
        float x0 = __bfloat162float(bh.x) + __bfloat162float(bm.x);
        float x1 = __bfloat162float(bh.y) + __bfloat162float(bm.y);
        int k = 2 * (lane + i * 32);
        s0 = fmaf(x0, Ws[k * 3 + 0], s0); s1 = fmaf(x0, Ws[k * 3 + 1], s1);
        s2 = fmaf(x0, Ws[k * 3 + 2], s2);
        s0 = fmaf(x1, Ws[k * 3 + 3], s0); s1 = fmaf(x1, Ws[k * 3 + 4], s1);
        s2 = fmaf(x1, Ws[k * 3 + 5], s2);
    }
#pragma unroll
    for (int o = 16; o; o >>= 1) {
        s0 += __shfl_down_sync(0xffffffffu, s0, o);
        s1 += __shfl_down_sync(0xffffffffu, s1, o);
        s2 += __shfl_down_sync(0xffffffffu, s2, o);
    }
    if (lane == 0) {
        out[(size_t)row * 3 + 0] = s0 + b3[0];
        out[(size_t)row * 3 + 1] = s1 + b3[1];
        out[(size_t)row * 3 + 2] = s2 + b3[2];
    }
}

extern "C" void kernel_launch(void* const* d_in, const int* in_sizes, int n_in,
                              void* d_out, int out_size) {
    const float* h = (const float*)d_in[0];
    const int* src = (const int*)d_in[1];
    const int* dst = (const int*)d_in[2];
    const float* enorm = (const float*)d_in[3];
    const int* tsrc = (const int*)d_in[4];
    const int* tdi = (const int*)d_in[5];
    const int* tdj = (const int*)d_in[6];
    const float* nij = (const float*)d_in[7];
    const float* nik = (const float*)d_in[8];
    const float* cosv = (const float*)d_in[9];
    const float* sinv = (const float*)d_in[10];
    const float* mu = (const float*)d_in[11];
    const float* eW0 = (const float*)d_in[12];
    const float* eW1 = (const float*)d_in[13];
    const float* eW2 = (const float*)d_in[14];
    const float* eW3 = (const float*)d_in[15];
    const float* eb3 = (const float*)d_in[16];
    const float* tW0 = (const float*)d_in[17];
    const float* tW1 = (const float*)d_in[18];
    const float* tW2 = (const float*)d_in[19];
    const float* tW3 = (const float*)d_in[20];
    const float* tb3 = (const float*)d_in[21];
    float* out = (float*)d_out;

    __nv_bfloat16 *xH, *xM, *yH, *yM, *hH, *hM, *wH, *wM;
    float* P;
    cudaGetSymbolAddress((void**)&xH, g_x_hi);
    cudaGetSymbolAddress((void**)&xM, g_x_mid);
    cudaGetSymbolAddress((void**)&yH, g_y_hi);
    cudaGetSymbolAddress((void**)&yM, g_y_mid);
    cudaGetSymbolAddress((void**)&hH, g_h_hi);
    cudaGetSymbolAddress((void**)&hM, g_h_mid);
    cudaGetSymbolAddress((void**)&wH, g_w_hi);
    cudaGetSymbolAddress((void**)&wM, g_w_mid);
    cudaGetSymbolAddress((void**)&P, g_P);

    cudaFuncSetAttribute(gemm_kernel<0>, cudaFuncAttributeMaxDynamicSharedMemorySize, SMEM_GEMM);
    cudaFuncSetAttribute(gemm_kernel<1>, cudaFuncAttributeMaxDynamicSharedMemorySize, SMEM_GEMM);
    cudaFuncSetAttribute(pgemm_kernel, cudaFuncAttributeMaxDynamicSharedMemorySize, SMEM_GEMM);
    cudaFuncSetAttribute(l0_kernel<0>, cudaFuncAttributeMaxDynamicSharedMemorySize, SMEM_GEMM);
    cudaFuncSetAttribute(l0_kernel<1>, cudaFuncAttributeMaxDynamicSharedMemorySize, SMEM_GEMM);

    // 1. prep_h
    prep_h_kernel<<<(NPAD * FDIM) / 256, 256>>>(h, hH, hM);
    // 2. fused prep_w (11 slices)
    WS S;
    const float* srcs[11] = {eW0, eW0 + 32768, eW0 + 65536, eW1, eW2,
                             tW0, tW0 + 32768, tW0 + 65536, tW0 + 98304, tW1, tW2};
    int Ks[11] = {128, 128, 100, 256, 256, 128, 128, 128, 202, 256, 256};
    int KPs[11] = {128, 128, 128, 256, 256, 128, 128, 128, 256, 256, 256};
    int offs[11] = {E0A, E0B, E0C, E1, E2, T0A, T0B, T0C, T0D, T1, T2};
    for (int i = 0; i < 11; i++) { S.src[i] = srcs[i]; S.K[i] = Ks[i]; S.KP[i] = KPs[i]; S.off[i] = offs[i]; }
    prep_w_kernel<<<dim3(256, 1, 11), 256>>>(S, wH, wM);
    // 3. fused P gemms (5 slices)
    PG pg;
    int boffs[5] = {E0A, E0B, T0A, T0B, T0C};
    for (int i = 0; i < 5; i++) { pg.boff[i] = boffs[i]; pg.coff[i] = (size_t)i * PSZ; }
    pgemm_kernel<<<dim3(2, NPAD / 128, 5), 256, SMEM_GEMM>>>(hH, hM, wH, wM, P, pg);

    float *Pea = P, *Peb = P + PSZ, *Pta = P + 2 * PSZ, *Ptb = P + 3 * PSZ, *Ptc = P + 4 * PSZ;
    dim3 ge(2, E_EDGES / 128), gt(2, T_TRIP / 128);
    // 4-7: edge path (launch #6 = mid_e2 -> ncu capture target)
    l0_kernel<0><<<ge, 256, SMEM_GEMM>>>(enorm, nullptr, nullptr, nullptr, mu,
                                         src, dst, nullptr, wH + E0C, wM + E0C,
                                         Pea, Peb, nullptr, xH, xM);
    gemm_kernel<0><<<ge, 256, SMEM_GEMM>>>(xH, xM, wH + E1, wM + E1, 256, 4, yH, yM);
    gemm_kernel<0><<<ge, 256, SMEM_GEMM>>>(yH, yM, wH + E2, wM + E2, 256, 4, xH, xM);
    out_kernel<<<E_EDGES / 8, 256>>>(xH, xM, eW3, eb3, out);
    // 8-11: triplet path
    l0_kernel<1><<<gt, 256, SMEM_GEMM>>>(nij, nik, cosv, sinv, mu,
                                         tsrc, tdi, tdj, wH + T0D, wM + T0D,
                                         Pta, Ptb, Ptc, xH, xM);
    gemm_kernel<0><<<gt, 256, SMEM_GEMM>>>(xH, xM, wH + T1, wM + T1, 256, 4, yH, yM);
    gemm_kernel<0><<<gt, 256, SMEM_GEMM>>>(yH, yM, wH + T2, wM + T2, 256, 4, xH, xM);
    out_kernel<<<T_TRIP / 8, 256>>>(xH, xM, tW3, tb3, out + (size_t)E_EDGES * 3);
}

// round 9
// speedup vs baseline: 1.2731x; 1.1979x over previous
#include <cuda_runtime.h>
#include <cuda_bf16.h>
#include <cstdint>

#define FDIM 128
#define HDIM 256
#define E_EDGES 262144
#define T_TRIP 393216
#define NPAD 20096

// CTA tile 128x64, K-chunk 64. Stage = A(2x16KB) + B(2x8KB) = 48KB, 2 stages.
#define SA_HI 0
#define SA_MID (16 * 1024)
#define SB_HI (32 * 1024)
#define SB_MID (40 * 1024)
#define STAGE_BYTES (48 * 1024)
#define SMEM_GEMM (2 * STAGE_BYTES)

__device__ __nv_bfloat16 g_x_hi[(size_t)T_TRIP * HDIM];
__device__ __nv_bfloat16 g_x_mid[(size_t)T_TRIP * HDIM];
__device__ __nv_bfloat16 g_y_hi[(size_t)T_TRIP * HDIM];
__device__ __nv_bfloat16 g_y_mid[(size_t)T_TRIP * HDIM];
__device__ __nv_bfloat16 g_h_hi[(size_t)NPAD * FDIM];
__device__ __nv_bfloat16 g_h_mid[(size_t)NPAD * FDIM];
__device__ float g_P[5ull * NPAD * HDIM];
#define PSZ ((size_t)NPAD * HDIM)
#define E0A 0
#define E0B 32768
#define E0C 65536
#define E1 98304
#define E2 163840
#define T0A 229376
#define T0B 262144
#define T0C 294912
#define T0D 327680
#define T1 393216
#define T2 458752
__device__ __nv_bfloat16 g_w_hi[524288];
__device__ __nv_bfloat16 g_w_mid[524288];

__device__ __forceinline__ uint32_t smem_u32(const void* p) {
    uint32_t a;
    asm("{ .reg .u64 t; cvta.to.shared.u64 t, %1; cvt.u32.u64 %0, t; }" : "=r"(a) : "l"(p));
    return a;
}
__device__ __forceinline__ void cp16(uint32_t d, const void* s) {
    asm volatile("cp.async.cg.shared.global [%0], [%1], 16;" :: "r"(d), "l"(s));
}
#define CP_COMMIT() asm volatile("cp.async.commit_group;" ::: "memory")
#define CP_WAIT0() asm volatile("cp.async.wait_group 0;" ::: "memory")
#define CP_WAIT1() asm volatile("cp.async.wait_group 1;" ::: "memory")
#define LDSM4(r0, r1, r2, r3, a) \
    asm volatile("ldmatrix.sync.aligned.m8n8.x4.shared.b16 {%0,%1,%2,%3}, [%4];" \
                 : "=r"(r0), "=r"(r1), "=r"(r2), "=r"(r3) : "r"(a))

__device__ __forceinline__ void mma_bf16(float c[4], const uint32_t a[4], const uint32_t b[2]) {
    asm volatile(
        "mma.sync.aligned.m16n8k16.row.col.f32.bf16.bf16.f32 "
        "{%0,%1,%2,%3}, {%4,%5,%6,%7}, {%8,%9}, {%0,%1,%2,%3};"
        : "+f"(c[0]), "+f"(c[1]), "+f"(c[2]), "+f"(c[3])
        : "r"(a[0]), "r"(a[1]), "r"(a[2]), "r"(a[3]), "r"(b[0]), "r"(b[1]));
}
__device__ __forceinline__ float silu_f(float x) { return x / (1.0f + __expf(-x)); }
__device__ __forceinline__ uint32_t pkbf2(__nv_bfloat16 a, __nv_bfloat16 b) {
    __nv_bfloat162 v(a, b);
    return *reinterpret_cast<uint32_t*>(&v);
}
__device__ __forceinline__ void silu_split2(float v0, float v1, uint32_t* oh, uint32_t* om) {
    float a0 = silu_f(v0), a1 = silu_f(v1);
    __nv_bfloat16 h0 = __float2bfloat16_rn(a0), h1 = __float2bfloat16_rn(a1);
    *oh = pkbf2(h0, h1);
    *om = pkbf2(__float2bfloat16_rn(a0 - __bfloat162float(h0)),
                __float2bfloat16_rn(a1 - __bfloat162float(h1)));
}

struct Frag {
    int a_row, a_kh, b_row, b_kh;
};
// CTA 128x64, warp 32x32: acc[2 mt][4 nt][4]
__device__ __forceinline__ void mma_chunk(uint32_t stage, int wm, int wn, const Frag& f,
                                          float acc[2][4][4]) {
#pragma unroll
    for (int ks = 0; ks < 4; ks++) {
        uint32_t aHf[2][4], aMf[2][4], bHf[4][2], bMf[4][2];
#pragma unroll
        for (int mt = 0; mt < 2; mt++) {
            int r = wm + mt * 16 + f.a_row;
            uint32_t off = r * 128 + (((ks * 2 + f.a_kh) ^ (r & 7)) << 4);
            LDSM4(aHf[mt][0], aHf[mt][1], aHf[mt][2], aHf[mt][3], stage + SA_HI + off);
            LDSM4(aMf[mt][0], aMf[mt][1], aMf[mt][2], aMf[mt][3], stage + SA_MID + off);
        }
#pragma unroll
        for (int np = 0; np < 2; np++) {
            int r = wn + np * 16 + f.b_row;
            uint32_t off = r * 128 + (((ks * 2 + f.b_kh) ^ (r & 7)) << 4);
            uint32_t r0, r1, r2, r3;
            LDSM4(r0, r1, r2, r3, stage + SB_HI + off);
            bHf[np * 2][0] = r0; bHf[np * 2][1] = r1;
            bHf[np * 2 + 1][0] = r2; bHf[np * 2 + 1][1] = r3;
            LDSM4(r0, r1, r2, r3, stage + SB_MID + off);
            bMf[np * 2][0] = r0; bMf[np * 2][1] = r1;
            bMf[np * 2 + 1][0] = r2; bMf[np * 2 + 1][1] = r3;
        }
#pragma unroll
        for (int mt = 0; mt < 2; mt++)
#pragma unroll
            for (int nt = 0; nt < 4; nt++) {
                mma_bf16(acc[mt][nt], aHf[mt], bHf[nt]);
                mma_bf16(acc[mt][nt], aHf[mt], bMf[nt]);
                mma_bf16(acc[mt][nt], aMf[mt], bHf[nt]);
            }
    }
}

// A: 128 rows (1024 16B units/limb), B: 64 rows (512/limb)
__device__ __forceinline__ void load_chunk(uint32_t stage, int t, size_t koff,
                                           const char* aH, const char* aM,
                                           const char* bH, const char* bM, size_t ldb) {
#pragma unroll
    for (int i = 0; i < 4; i++) {
        int idx = t + i * 256;
        int r = idx >> 3, c16 = idx & 7;
        uint32_t doff = r * 128 + ((c16 ^ (r & 7)) << 4);
        size_t soff = (size_t)r * ldb + koff + c16 * 16;
        cp16(stage + SA_HI + doff, aH + soff);
        cp16(stage + SA_MID + doff, aM + soff);
    }
#pragma unroll
    for (int i = 0; i < 2; i++) {
        int idx = t + i * 256;
        int r = idx >> 3, c16 = idx & 7;
        uint32_t doff = r * 128 + ((c16 ^ (r & 7)) << 4);
        size_t soff = (size_t)r * ldb + koff + c16 * 16;
        cp16(stage + SB_HI + doff, bH + soff);
        cp16(stage + SB_MID + doff, bM + soff);
    }
    CP_COMMIT();
}

template <int EPI>
__device__ __forceinline__ void gemm_core(
    const __nv_bfloat16* Ahi, const __nv_bfloat16* Amid,
    const __nv_bfloat16* Bhi, const __nv_bfloat16* Bmid,
    int ld, int nchunks, void* C1, void* C2, int row0, int n0cta, char* smem) {
    uint32_t sb = smem_u32(smem);
    int t = threadIdx.x, lane = t & 31, w = t >> 5;
    int wm = (w & 3) * 32, wn = (w >> 2) * 32;

    const char* aH = (const char*)(Ahi + (size_t)row0 * ld);
    const char* aM = (const char*)(Amid + (size_t)row0 * ld);
    const char* bH = (const char*)(Bhi + (size_t)n0cta * ld);
    const char* bM = (const char*)(Bmid + (size_t)n0cta * ld);
    const size_t ldb = (size_t)ld * 2;

    float acc[2][4][4];
#pragma unroll
    for (int i = 0; i < 2; i++)
#pragma unroll
        for (int j = 0; j < 4; j++)
#pragma unroll
            for (int q = 0; q < 4; q++) acc[i][j][q] = 0.0f;
    Frag f{lane & 15, lane >> 4, (lane & 7) + ((lane >> 4) << 3), (lane >> 3) & 1};

    load_chunk(sb, t, 0, aH, aM, bH, bM, ldb);
    for (int c = 0; c < nchunks; c++) {
        if (c + 1 < nchunks) {
            load_chunk(sb + ((c + 1) & 1) * STAGE_BYTES, t, (size_t)(c + 1) * 128,
                       aH, aM, bH, bM, ldb);
            CP_WAIT1();
        } else {
            CP_WAIT0();
        }
        __syncthreads();
        mma_chunk(sb + (c & 1) * STAGE_BYTES, wm, wn, f, acc);
        __syncthreads();
    }

    int mrow = lane >> 2, ncol = (lane & 3) * 2;
#pragma unroll
    for (int mt = 0; mt < 2; mt++)
#pragma unroll
        for (int nt = 0; nt < 4; nt++) {
            int r = row0 + wm + mt * 16 + mrow;
            int cc = n0cta + wn + nt * 8 + ncol;
            if (EPI == 0) {
                uint32_t oh, om;
                silu_split2(acc[mt][nt][0], acc[mt][nt][1], &oh, &om);
                *(uint32_t*)((__nv_bfloat16*)C1 + (size_t)r * HDIM + cc) = oh;
                *(uint32_t*)((__nv_bfloat16*)C2 + (size_t)r * HDIM + cc) = om;
                silu_split2(acc[mt][nt][2], acc[mt][nt][3], &oh, &om);
                *(uint32_t*)((__nv_bfloat16*)C1 + (size_t)(r + 8) * HDIM + cc) = oh;
                *(uint32_t*)((__nv_bfloat16*)C2 + (size_t)(r + 8) * HDIM + cc) = om;
            } else {
                *(float2*)((float*)C1 + (size_t)r * HDIM + cc) =
                    make_float2(acc[mt][nt][0], acc[mt][nt][1]);
                *(float2*)((float*)C1 + (size_t)(r + 8) * HDIM + cc) =
                    make_float2(acc[mt][nt][2], acc[mt][nt][3]);
            }
        }
}

template <int EPI>
__global__ void __launch_bounds__(256, 2) gemm_kernel(
    const __nv_bfloat16* __restrict__ Ahi, const __nv_bfloat16* __restrict__ Amid,
    const __nv_bfloat16* __restrict__ Bhi, const __nv_bfloat16* __restrict__ Bmid,
    int ld, int nchunks, void* __restrict__ C1, void* __restrict__ C2) {
    extern __shared__ char smem[];
    gemm_core<EPI>(Ahi, Amid, Bhi, Bmid, ld, nchunks, C1, C2,
                   blockIdx.y * 128, blockIdx.x * 64, smem);
}

struct PG {
    int boff[5];
    size_t coff[5];
};
__global__ void __launch_bounds__(256, 2) pgemm_kernel(
    const __nv_bfloat16* __restrict__ hH, const __nv_bfloat16* __restrict__ hM,
    const __nv_bfloat16* __restrict__ wH, const __nv_bfloat16* __restrict__ wM,
    float* __restrict__ P, PG pg) {
    extern __shared__ char smem[];
    int z = blockIdx.z;
    gemm_core<1>(hH, hM, wH + pg.boff[z], wM + pg.boff[z], 128, 2,
                 P + pg.coff[z], nullptr, blockIdx.y * 128, blockIdx.x * 64, smem);
}

__global__ void prep_h_kernel(const float* __restrict__ h,
                              __nv_bfloat16* __restrict__ hi, __nv_bfloat16* __restrict__ mid) {
    size_t idx = (size_t)blockIdx.x * 256 + threadIdx.x;
    int row = (int)(idx >> 7);
    float v = (row < 20000) ? h[idx] : 0.0f;
    __nv_bfloat16 hh = __float2bfloat16_rn(v);
    hi[idx] = hh;
    mid[idx] = __float2bfloat16_rn(v - __bfloat162float(hh));
}

struct WS {
    const float* src[11];
    int K[11], KP[11], off[11];
};
__global__ void prep_w_kernel(WS S, __nv_bfloat16* __restrict__ hi,
                              __nv_bfloat16* __restrict__ mid) {
    int z = blockIdx.z;
    int KP = S.KP[z];
    if (blockIdx.x >= KP) return;
    int idx = blockIdx.x * 256 + threadIdx.x;
    int n = idx / KP, k = idx % KP;
    float v = (k < S.K[z]) ? S.src[z][(size_t)k * HDIM + n] : 0.0f;
    __nv_bfloat16 h = __float2bfloat16_rn(v);
    hi[S.off[z] + idx] = h;
    mid[S.off[z] + idx] = __float2bfloat16_rn(v - __bfloat162float(h));
}

template <int MODE>
__global__ void __launch_bounds__(256, 2) l0_kernel(
    const float* __restrict__ rA, const float* __restrict__ rB,
    const float* __restrict__ cosv, const float* __restrict__ sinv,
    const float* __restrict__ mu,
    const int* __restrict__ iA, const int* __restrict__ iB, const int* __restrict__ iC,
    const __nv_bfloat16* __restrict__ Bhi, const __nv_bfloat16* __restrict__ Bmid,
    const float* __restrict__ Pa, const float* __restrict__ Pb, const float* __restrict__ Pc,
    __nv_bfloat16* __restrict__ Chi, __nv_bfloat16* __restrict__ Cmid) {
    const int CH = MODE ? 4 : 2;
    const int KP = CH * 64;
    extern __shared__ char smem[];
    uint32_t sb = smem_u32(smem);
    int t = threadIdx.x, lane = t & 31, w = t >> 5;
    int row0 = blockIdx.y * 128, n0cta = blockIdx.x * 64;
    int wm = (w & 3) * 32, wn = (w >> 2) * 32;

    const char* bH = (const char*)(Bhi + (size_t)n0cta * KP);
    const char* bM = (const char*)(Bmid + (size_t)n0cta * KP);
    const size_t ldb = (size_t)KP * 2;

    int brow = t >> 1, kb = (t & 1) * 32;
    float ra = rA[row0 + brow];
    float rb = MODE ? rB[row0 + brow] : 0.0f;
    float cv = MODE ? cosv[row0 + brow] : 0.0f;
    float sv = MODE ? sinv[row0 + brow] : 0.0f;

    auto rbf_val = [&](int k) -> float {
        float v = 0.0f;
        if (MODE == 0) {
            if (k < 100) { float d = __ldg(mu + k) - ra; v = __expf(-10.0f * d * d); }
        } else {
            if (k < 100)      { float d = __ldg(mu + k) - ra; v = __expf(-10.0f * d * d); }
            else if (k < 200) { float d = __ldg(mu + k - 100) - rb; v = __expf(-10.0f * d * d); }
            else if (k == 200) v = cv;
            else if (k == 201) v = sv;
        }
        return v;
    };
    auto build_A = [&](int c, int s) {
        char* ah = smem + s * STAGE_BYTES + SA_HI;
        char* am = smem + s * STAGE_BYTES + SA_MID;
#pragma unroll
        for (int j = 0; j < 32; j += 2) {
            int kk = kb + j;
            float v0 = rbf_val(c * 64 + kk), v1 = rbf_val(c * 64 + kk + 1);
            __nv_bfloat16 h0 = __float2bfloat16_rn(v0), h1 = __float2bfloat16_rn(v1);
            uint32_t off = brow * 128 + (((kk >> 3) ^ (brow & 7)) << 4) + ((kk & 7) * 2);
            *(uint32_t*)(ah + off) = pkbf2(h0, h1);
            *(uint32_t*)(am + off) =
                pkbf2(__float2bfloat16_rn(v0 - __bfloat162float(h0)),
                      __float2bfloat16_rn(v1 - __bfloat162float(h1)));
        }
    };
    auto load_B = [&](int c, int s) {
        uint32_t stage = sb + s * STAGE_BYTES;
#pragma unroll
        for (int i = 0; i < 2; i++) {
            int idx = t + i * 256;
            int r = idx >> 3, c16 = idx & 7;
            uint32_t doff = r * 128 + ((c16 ^ (r & 7)) << 4);
            size_t soff = (size_t)r * ldb + (size_t)c * 128 + c16 * 16;
            cp16(stage + SB_HI + doff, bH + soff);
            cp16(stage + SB_MID + doff, bM + soff);
        }
        CP_COMMIT();
    };

    float acc[2][4][4];
#pragma unroll
    for (int i = 0; i < 2; i++)
#pragma unroll
        for (int j = 0; j < 4; j++)
#pragma unroll
            for (int q = 0; q < 4; q++) acc[i][j][q] = 0.0f;
    Frag f{lane & 15, lane >> 4, (lane & 7) + ((lane >> 4) << 3), (lane >> 3) & 1};

    build_A(0, 0);
    load_B(0, 0);
    for (int c = 0; c < CH; c++) {
        if (c + 1 < CH) {
            build_A(c + 1, (c + 1) & 1);
            load_B(c + 1, (c + 1) & 1);
            CP_WAIT1();
        } else {
            CP_WAIT0();
        }
        __syncthreads();
        mma_chunk(sb + (c & 1) * STAGE_BYTES, wm, wn, f, acc);
        __syncthreads();
    }

    int mrow = lane >> 2, ncol = (lane & 3) * 2;
    const float* pa[4];
    const float* pb[4];
    const float* pc[4];
#pragma unroll
    for (int rr = 0; rr < 4; rr++) {
        int r = row0 + wm + (rr >> 1) * 16 + (rr & 1) * 8 + mrow;
        pa[rr] = Pa + (size_t)iA[r] * HDIM;
        pb[rr] = Pb + (size_t)iB[r] * HDIM;
        if (MODE) pc[rr] = Pc + (size_t)iC[r] * HDIM;
    }
#pragma unroll
    for (int mt = 0; mt < 2; mt++)
#pragma unroll
        for (int nt = 0; nt < 4; nt++) {
            int cc = n0cta + wn + nt * 8 + ncol;
#pragma unroll
            for (int sr = 0; sr < 2; sr++) {
                int rr = mt * 2 + sr;
                int r = row0 + wm + mt * 16 + sr * 8 + mrow;
                float2 ga = *(const float2*)(pa[rr] + cc);
                float2 gb = *(const float2*)(pb[rr] + cc);
                float v0 = acc[mt][nt][sr * 2 + 0] + ga.x + gb.x;
                float v1 = acc[mt][nt][sr * 2 + 1] + ga.y + gb.y;
                if (MODE) {
                    float2 gc = *(const float2*)(pc[rr] + cc);
                    v0 += gc.x;
                    v1 += gc.y;
                }
                uint32_t oh, om;
                silu_split2(v0, v1, &oh, &om);
                *(uint32_t*)(Chi + (size_t)r * HDIM + cc) = oh;
                *(uint32_t*)(Cmid + (size_t)r * HDIM + cc) = om;
            }
        }
}

__global__ void __launch_bounds__(256) out_kernel(
    const __nv_bfloat16* __restrict__ Xhi, const __nv_bfloat16* __restrict__ Xmid,
    const float* __restrict__ W3, const float* __restrict__ b3, float* __restrict__ out) {
    __shared__ float Ws[HDIM * 3];
    int t = threadIdx.x;
    for (int i = t; i < HDIM * 3; i += 256) Ws[i] = W3[i];
    __syncthreads();
    int row = blockIdx.x * 8 + (t >> 5);
    int lane = t & 31;
    const uint32_t* ph = (const uint32_t*)Xhi + (size_t)row * 128;
    const uint32_t* pm = (const uint32_t*)Xmid + (size_t)row * 128;
    float s0 = 0.f, s1 = 0.f, s2 = 0.f;
#pragma unroll
    for (int i = 0; i < 4; i++) {
        uint32_t uh = ph[lane + i * 32], um = pm[lane + i * 32];
        __nv_bfloat162 bh = *reinterpret_cast<__nv_bfloat162*>(&uh);
        __nv_bfloat162 bm = *reinterpret_cast<__nv_bfloat162*>(&um);
        float x0 = __bfloat162float(bh.x) + __bfloat162float(bm.x);
        float x1 = __bfloat162float(bh.y) + __bfloat162float(bm.y);
        int k = 2 * (lane + i * 32);
        s0 = fmaf(x0, Ws[k * 3 + 0], s0); s1 = fmaf(x0, Ws[k * 3 + 1], s1);
        s2 = fmaf(x0, Ws[k * 3 + 2], s2);
        s0 = fmaf(x1, Ws[k * 3 + 3], s0); s1 = fmaf(x1, Ws[k * 3 + 4], s1);
        s2 = fmaf(x1, Ws[k * 3 + 5], s2);
    }
#pragma unroll
    for (int o = 16; o; o >>= 1) {
        s0 += __shfl_down_sync(0xffffffffu, s0, o);
        s1 += __shfl_down_sync(0xffffffffu, s1, o);
        s2 += __shfl_down_sync(0xffffffffu, s2, o);
    }
    if (lane == 0) {
        out[(size_t)row * 3 + 0] = s0 + b3[0];
        out[(size_t)row * 3 + 1] = s1 + b3[1];
        out[(size_t)row * 3 + 2] = s2 + b3[2];
    }
}

extern "C" void kernel_launch(void* const* d_in, const int* in_sizes, int n_in,
                              void* d_out, int out_size) {
    const float* h = (const float*)d_in[0];
    const int* src = (const int*)d_in[1];
    const int* dst = (const int*)d_in[2];
    const float* enorm = (const float*)d_in[3];
    const int* tsrc = (const int*)d_in[4];
    const int* tdi = (const int*)d_in[5];
    const int* tdj = (const int*)d_in[6];
    const float* nij = (const float*)d_in[7];
    const float* nik = (const float*)d_in[8];
    const float* cosv = (const float*)d_in[9];
    const float* sinv = (const float*)d_in[10];
    const float* mu = (const float*)d_in[11];
    const float* eW0 = (const float*)d_in[12];
    const float* eW1 = (const float*)d_in[13];
    const float* eW2 = (const float*)d_in[14];
    const float* eW3 = (const float*)d_in[15];
    const float* eb3 = (const float*)d_in[16];
    const float* tW0 = (const float*)d_in[17];
    const float* tW1 = (const float*)d_in[18];
    const float* tW2 = (const float*)d_in[19];
    const float* tW3 = (const float*)d_in[20];
    const float* tb3 = (const float*)d_in[21];
    float* out = (float*)d_out;

    __nv_bfloat16 *xH, *xM, *yH, *yM, *hH, *hM, *wH, *wM;
    float* P;
    cudaGetSymbolAddress((void**)&xH, g_x_hi);
    cudaGetSymbolAddress((void**)&xM, g_x_mid);
    cudaGetSymbolAddress((void**)&yH, g_y_hi);
    cudaGetSymbolAddress((void**)&yM, g_y_mid);
    cudaGetSymbolAddress((void**)&hH, g_h_hi);
    cudaGetSymbolAddress((void**)&hM, g_h_mid);
    cudaGetSymbolAddress((void**)&wH, g_w_hi);
    cudaGetSymbolAddress((void**)&wM, g_w_mid);
    cudaGetSymbolAddress((void**)&P, g_P);

    cudaFuncSetAttribute(gemm_kernel<0>, cudaFuncAttributeMaxDynamicSharedMemorySize, SMEM_GEMM);
    cudaFuncSetAttribute(gemm_kernel<1>, cudaFuncAttributeMaxDynamicSharedMemorySize, SMEM_GEMM);
    cudaFuncSetAttribute(pgemm_kernel, cudaFuncAttributeMaxDynamicSharedMemorySize, SMEM_GEMM);
    cudaFuncSetAttribute(l0_kernel<0>, cudaFuncAttributeMaxDynamicSharedMemorySize, SMEM_GEMM);
    cudaFuncSetAttribute(l0_kernel<1>, cudaFuncAttributeMaxDynamicSharedMemorySize, SMEM_GEMM);

    prep_h_kernel<<<(NPAD * FDIM) / 256, 256>>>(h, hH, hM);
    WS S;
    const float* srcs[11] = {eW0, eW0 + 32768, eW0 + 65536, eW1, eW2,
                             tW0, tW0 + 32768, tW0 + 65536, tW0 + 98304, tW1, tW2};
    int Ks[11] = {128, 128, 100, 256, 256, 128, 128, 128, 202, 256, 256};
    int KPs[11] = {128, 128, 128, 256, 256, 128, 128, 128, 256, 256, 256};
    int offs[11] = {E0A, E0B, E0C, E1, E2, T0A, T0B, T0C, T0D, T1, T2};
    for (int i = 0; i < 11; i++) { S.src[i] = srcs[i]; S.K[i] = Ks[i]; S.KP[i] = KPs[i]; S.off[i] = offs[i]; }
    prep_w_kernel<<<dim3(256, 1, 11), 256>>>(S, wH, wM);
    PG pg;
    int boffs[5] = {E0A, E0B, T0A, T0B, T0C};
    for (int i = 0; i < 5; i++) { pg.boff[i] = boffs[i]; pg.coff[i] = (size_t)i * PSZ; }
    pgemm_kernel<<<dim3(4, NPAD / 128, 5), 256, SMEM_GEMM>>>(hH, hM, wH, wM, P, pg);

    float *Pea = P, *Peb = P + PSZ, *Pta = P + 2 * PSZ, *Ptb = P + 3 * PSZ, *Ptc = P + 4 * PSZ;
    dim3 ge(4, E_EDGES / 128), gt(4, T_TRIP / 128);
    l0_kernel<0><<<ge, 256, SMEM_GEMM>>>(enorm, nullptr, nullptr, nullptr, mu,
                                         src, dst, nullptr, wH + E0C, wM + E0C,
                                         Pea, Peb, nullptr, xH, xM);
    gemm_kernel<0><<<ge, 256, SMEM_GEMM>>>(xH, xM, wH + E1, wM + E1, 256, 4, yH, yM);
    gemm_kernel<0><<<ge, 256, SMEM_GEMM>>>(yH, yM, wH + E2, wM + E2, 256, 4, xH, xM);
    out_kernel<<<E_EDGES / 8, 256>>>(xH, xM, eW3, eb3, out);
    l0_kernel<1><<<gt, 256, SMEM_GEMM>>>(nij, nik, cosv, sinv, mu,
                                         tsrc, tdi, tdj, wH + T0D, wM + T0D,
                                         Pta, Ptb, Ptc, xH, xM);
    gemm_kernel<0><<<gt, 256, SMEM_GEMM>>>(xH, xM, wH + T1, wM + T1, 256, 4, yH, yM);
    gemm_kernel<0><<<gt, 256, SMEM_GEMM>>>(yH, yM, wH + T2, wM + T2, 256, 4, xH, xM);
    out_kernel<<<T_TRIP / 8, 256>>>(xH, xM, tW3, tb3, out + (size_t)E_EDGES * 3);
}

// round 10
// speedup vs baseline: 1.8774x; 1.4747x over previous
#include <cuda_runtime.h>
#include <cuda_bf16.h>
#include <cstdint>

#define FDIM 128
#define HDIM 256
#define E_EDGES 262144
#define T_TRIP 393216
#define NPAD 20096
#define TABN 4096
#define TROWS 4097
#define TOFF ((size_t)TROWS * 256)

#define SA_HI 0
#define SA_MID (16 * 1024)
#define SB_HI (32 * 1024)
#define SB_MID (40 * 1024)
#define STAGE_BYTES (48 * 1024)
#define SMEM_GEMM (2 * STAGE_BYTES)

__device__ __nv_bfloat16 g_x_hi[(size_t)T_TRIP * HDIM];
__device__ __nv_bfloat16 g_x_mid[(size_t)T_TRIP * HDIM];
__device__ __nv_bfloat16 g_y_hi[(size_t)T_TRIP * HDIM];
__device__ __nv_bfloat16 g_y_mid[(size_t)T_TRIP * HDIM];
__device__ __nv_bfloat16 g_h_hi[(size_t)NPAD * FDIM];
__device__ __nv_bfloat16 g_h_mid[(size_t)NPAD * FDIM];
__device__ float g_P[5ull * NPAD * HDIM];
__device__ float g_T[3 * TOFF];
#define PSZ ((size_t)NPAD * HDIM)
#define E0A 0
#define E0B 32768
#define E1 98304
#define E2 163840
#define T0A 229376
#define T0B 262144
#define T0C 294912
#define T1 393216
#define T2 458752
__device__ __nv_bfloat16 g_w_hi[524288];
__device__ __nv_bfloat16 g_w_mid[524288];

__device__ __forceinline__ uint32_t smem_u32(const void* p) {
    uint32_t a;
    asm("{ .reg .u64 t; cvta.to.shared.u64 t, %1; cvt.u32.u64 %0, t; }" : "=r"(a) : "l"(p));
    return a;
}
__device__ __forceinline__ void cp16(uint32_t d, const void* s) {
    asm volatile("cp.async.cg.shared.global [%0], [%1], 16;" :: "r"(d), "l"(s));
}
#define CP_COMMIT() asm volatile("cp.async.commit_group;" ::: "memory")
#define CP_WAIT0() asm volatile("cp.async.wait_group 0;" ::: "memory")
#define CP_WAIT1() asm volatile("cp.async.wait_group 1;" ::: "memory")
#define LDSM4(r0, r1, r2, r3, a) \
    asm volatile("ldmatrix.sync.aligned.m8n8.x4.shared.b16 {%0,%1,%2,%3}, [%4];" \
                 : "=r"(r0), "=r"(r1), "=r"(r2), "=r"(r3) : "r"(a))

__device__ __forceinline__ void mma_bf16(float c[4], const uint32_t a[4], const uint32_t b[2]) {
    asm volatile(
        "mma.sync.aligned.m16n8k16.row.col.f32.bf16.bf16.f32 "
        "{%0,%1,%2,%3}, {%4,%5,%6,%7}, {%8,%9}, {%0,%1,%2,%3};"
        : "+f"(c[0]), "+f"(c[1]), "+f"(c[2]), "+f"(c[3])
        : "r"(a[0]), "r"(a[1]), "r"(a[2]), "r"(a[3]), "r"(b[0]), "r"(b[1]));
}
__device__ __forceinline__ float silu_f(float x) { return x / (1.0f + __expf(-x)); }
__device__ __forceinline__ uint32_t pkbf2(__nv_bfloat16 a, __nv_bfloat16 b) {
    __nv_bfloat162 v(a, b);
    return *reinterpret_cast<uint32_t*>(&v);
}
__device__ __forceinline__ void silu_split2(float v0, float v1, uint32_t* oh, uint32_t* om) {
    float a0 = silu_f(v0), a1 = silu_f(v1);
    __nv_bfloat16 h0 = __float2bfloat16_rn(a0), h1 = __float2bfloat16_rn(a1);
    *oh = pkbf2(h0, h1);
    *om = pkbf2(__float2bfloat16_rn(a0 - __bfloat162float(h0)),
                __float2bfloat16_rn(a1 - __bfloat162float(h1)));
}

struct Frag {
    int a_row, a_kh, b_row, b_kh;
};
__device__ __forceinline__ void mma_chunk(uint32_t stage, int wm, int wn, const Frag& f,
                                          float acc[2][4][4]) {
#pragma unroll
    for (int ks = 0; ks < 4; ks++) {
        uint32_t aHf[2][4], aMf[2][4], bHf[4][2], bMf[4][2];
#pragma unroll
        for (int mt = 0; mt < 2; mt++) {
            int r = wm + mt * 16 + f.a_row;
            uint32_t off = r * 128 + (((ks * 2 + f.a_kh) ^ (r & 7)) << 4);
            LDSM4(aHf[mt][0], aHf[mt][1], aHf[mt][2], aHf[mt][3], stage + SA_HI + off);
            LDSM4(aMf[mt][0], aMf[mt][1], aMf[mt][2], aMf[mt][3], stage + SA_MID + off);
        }
#pragma unroll
        for (int np = 0; np < 2; np++) {
            int r = wn + np * 16 + f.b_row;
            uint32_t off = r * 128 + (((ks * 2 + f.b_kh) ^ (r & 7)) << 4);
            uint32_t r0, r1, r2, r3;
            LDSM4(r0, r1, r2, r3, stage + SB_HI + off);
            bHf[np * 2][0] = r0; bHf[np * 2][1] = r1;
            bHf[np * 2 + 1][0] = r2; bHf[np * 2 + 1][1] = r3;
            LDSM4(r0, r1, r2, r3, stage + SB_MID + off);
            bMf[np * 2][0] = r0; bMf[np * 2][1] = r1;
            bMf[np * 2 + 1][0] = r2; bMf[np * 2 + 1][1] = r3;
        }
#pragma unroll
        for (int mt = 0; mt < 2; mt++)
#pragma unroll
            for (int nt = 0; nt < 4; nt++) {
                mma_bf16(acc[mt][nt], aHf[mt], bHf[nt]);
                mma_bf16(acc[mt][nt], aHf[mt], bMf[nt]);
                mma_bf16(acc[mt][nt], aMf[mt], bHf[nt]);
            }
    }
}

__device__ __forceinline__ void load_chunk(uint32_t stage, int t, size_t koff,
                                           const char* aH, const char* aM,
                                           const char* bH, const char* bM, size_t ldb) {
#pragma unroll
    for (int i = 0; i < 4; i++) {
        int idx = t + i * 256;
        int r = idx >> 3, c16 = idx & 7;
        uint32_t doff = r * 128 + ((c16 ^ (r & 7)) << 4);
        size_t soff = (size_t)r * ldb + koff + c16 * 16;
        cp16(stage + SA_HI + doff, aH + soff);
        cp16(stage + SA_MID + doff, aM + soff);
    }
#pragma unroll
    for (int i = 0; i < 2; i++) {
        int idx = t + i * 256;
        int r = idx >> 3, c16 = idx & 7;
        uint32_t doff = r * 128 + ((c16 ^ (r & 7)) << 4);
        size_t soff = (size_t)r * ldb + koff + c16 * 16;
        cp16(stage + SB_HI + doff, bH + soff);
        cp16(stage + SB_MID + doff, bM + soff);
    }
    CP_COMMIT();
}

template <int EPI>
__device__ __forceinline__ void gemm_core(
    const __nv_bfloat16* Ahi, const __nv_bfloat16* Amid,
    const __nv_bfloat16* Bhi, const __nv_bfloat16* Bmid,
    int ld, int nchunks, void* C1, void* C2, int row0, int n0cta, char* smem) {
    uint32_t sb = smem_u32(smem);
    int t = threadIdx.x, lane = t & 31, w = t >> 5;
    int wm = (w & 3) * 32, wn = (w >> 2) * 32;

    const char* aH = (const char*)(Ahi + (size_t)row0 * ld);
    const char* aM = (const char*)(Amid + (size_t)row0 * ld);
    const char* bH = (const char*)(Bhi + (size_t)n0cta * ld);
    const char* bM = (const char*)(Bmid + (size_t)n0cta * ld);
    const size_t ldb = (size_t)ld * 2;

    float acc[2][4][4];
#pragma unroll
    for (int i = 0; i < 2; i++)
#pragma unroll
        for (int j = 0; j < 4; j++)
#pragma unroll
            for (int q = 0; q < 4; q++) acc[i][j][q] = 0.0f;
    Frag f{lane & 15, lane >> 4, (lane & 7) + ((lane >> 4) << 3), (lane >> 3) & 1};

    load_chunk(sb, t, 0, aH, aM, bH, bM, ldb);
    for (int c = 0; c < nchunks; c++) {
        if (c + 1 < nchunks) {
            load_chunk(sb + ((c + 1) & 1) * STAGE_BYTES, t, (size_t)(c + 1) * 128,
                       aH, aM, bH, bM, ldb);
            CP_WAIT1();
        } else {
            CP_WAIT0();
        }
        __syncthreads();
        mma_chunk(sb + (c & 1) * STAGE_BYTES, wm, wn, f, acc);
        __syncthreads();
    }

    int mrow = lane >> 2, ncol = (lane & 3) * 2;
#pragma unroll
    for (int mt = 0; mt < 2; mt++)
#pragma unroll
        for (int nt = 0; nt < 4; nt++) {
            int r = row0 + wm + mt * 16 + mrow;
            int cc = n0cta + wn + nt * 8 + ncol;
            if (EPI == 0) {
                uint32_t oh, om;
                silu_split2(acc[mt][nt][0], acc[mt][nt][1], &oh, &om);
                *(uint32_t*)((__nv_bfloat16*)C1 + (size_t)r * HDIM + cc) = oh;
                *(uint32_t*)((__nv_bfloat16*)C2 + (size_t)r * HDIM + cc) = om;
                silu_split2(acc[mt][nt][2], acc[mt][nt][3], &oh, &om);
                *(uint32_t*)((__nv_bfloat16*)C1 + (size_t)(r + 8) * HDIM + cc) = oh;
                *(uint32_t*)((__nv_bfloat16*)C2 + (size_t)(r + 8) * HDIM + cc) = om;
            } else {
                *(float2*)((float*)C1 + (size_t)r * HDIM + cc) =
                    make_float2(acc[mt][nt][0], acc[mt][nt][1]);
                *(float2*)((float*)C1 + (size_t)(r + 8) * HDIM + cc) =
                    make_float2(acc[mt][nt][2], acc[mt][nt][3]);
            }
        }
}

template <int EPI>
__global__ void __launch_bounds__(256, 2) gemm_kernel(
    const __nv_bfloat16* __restrict__ Ahi, const __nv_bfloat16* __restrict__ Amid,
    const __nv_bfloat16* __restrict__ Bhi, const __nv_bfloat16* __restrict__ Bmid,
    int ld, int nchunks, void* __restrict__ C1, void* __restrict__ C2) {
    extern __shared__ char smem[];
    gemm_core<EPI>(Ahi, Amid, Bhi, Bmid, ld, nchunks, C1, C2,
                   blockIdx.y * 128, blockIdx.x * 64, smem);
}

struct PG {
    int boff[5];
    size_t coff[5];
};
__global__ void __launch_bounds__(256, 2) pgemm_kernel(
    const __nv_bfloat16* __restrict__ hH, const __nv_bfloat16* __restrict__ hM,
    const __nv_bfloat16* __restrict__ wH, const __nv_bfloat16* __restrict__ wM,
    float* __restrict__ P, PG pg) {
    extern __shared__ char smem[];
    int z = blockIdx.z;
    gemm_core<1>(hH, hM, wH + pg.boff[z], wM + pg.boff[z], 128, 2,
                 P + pg.coff[z], nullptr, blockIdx.y * 128, blockIdx.x * 64, smem);
}

__global__ void prep_h_kernel(const float* __restrict__ h,
                              __nv_bfloat16* __restrict__ hi, __nv_bfloat16* __restrict__ mid) {
    size_t idx = (size_t)blockIdx.x * 256 + threadIdx.x;
    int row = (int)(idx >> 7);
    float v = (row < 20000) ? h[idx] : 0.0f;
    __nv_bfloat16 hh = __float2bfloat16_rn(v);
    hi[idx] = hh;
    mid[idx] = __float2bfloat16_rn(v - __bfloat162float(hh));
}

struct WS {
    const float* src[9];
    int KP[9], off[9];
};
__global__ void prep_w_kernel(WS S, __nv_bfloat16* __restrict__ hi,
                              __nv_bfloat16* __restrict__ mid) {
    int z = blockIdx.z;
    int KP = S.KP[z];
    if (blockIdx.x >= KP) return;
    int idx = blockIdx.x * 256 + threadIdx.x;
    int n = idx / KP, k = idx % KP;
    float v = S.src[z][(size_t)k * HDIM + n];
    __nv_bfloat16 h = __float2bfloat16_rn(v);
    hi[S.off[z] + idx] = h;
    mid[S.off[z] + idx] = __float2bfloat16_rn(v - __bfloat162float(h));
}

// Build RBF projection tables: T[z][i][n] = sum_k exp(-10(mu_k - r_i)^2) W[k][n]
__global__ void table_kernel(const float* __restrict__ eW0, const float* __restrict__ tW0,
                             const float* __restrict__ mu, float* __restrict__ T) {
    extern __shared__ float sm[];  // [100*256] W + [32*100] rbf
    float* Wsm = sm;
    float* rbf = sm + 25600;
    int z = blockIdx.y;
    const float* Wsrc = (z == 0) ? eW0 + 65536 : ((z == 1) ? tW0 + 98304 : tW0 + 123904);
    float* Tout = g_T + (size_t)z * TOFF;
    (void)T;
    int t = threadIdx.x;
    for (int i = t; i < 25600; i += 256) Wsm[i] = Wsrc[i];
    int r0 = blockIdx.x * 32;
    for (int i = t; i < 3200; i += 256) {
        int rr = i / 100, k = i % 100;
        float r = (float)(r0 + rr) * (10.0f / (float)TABN);
        float d = __ldg(mu + k) - r;
        rbf[i] = expf(-10.0f * d * d);
    }
    __syncthreads();
    for (int rr = 0; rr < 32; rr++) {
        int row = r0 + rr;
        if (row > TABN) break;
        float acc = 0.0f;
#pragma unroll 4
        for (int k = 0; k < 100; k++) acc = fmaf(rbf[rr * 100 + k], Wsm[k * 256 + t], acc);
        Tout[(size_t)row * 256 + t] = acc;
    }
}

// L0 gather: x = silu(T[r] + Pa[iA] + Pb[iB] (+ T2[r2] + Pc[iC] + cv*wc + sv*ws))
template <int MODE>
__global__ void __launch_bounds__(256) l0g_kernel(
    const float* __restrict__ rA, const float* __restrict__ rB,
    const float* __restrict__ cosv, const float* __restrict__ sinv,
    const int* __restrict__ iA, const int* __restrict__ iB, const int* __restrict__ iC,
    const float* __restrict__ Ta, const float* __restrict__ Tb,
    const float* __restrict__ Wcs,
    const float* __restrict__ Pa, const float* __restrict__ Pb, const float* __restrict__ Pc,
    __nv_bfloat16* __restrict__ Chi, __nv_bfloat16* __restrict__ Cmid) {
    int w = threadIdx.x >> 5, lane = threadIdx.x & 31;
    int row = blockIdx.x * 8 + w;

    float ua = rA[row] * ((float)TABN / 10.0f);
    int ia = min((int)ua, TABN - 1);
    float fa = ua - (float)ia;
    const float4* t0 = (const float4*)(Ta + (size_t)ia * 256);
    const float4* pa = (const float4*)(Pa + (size_t)iA[row] * HDIM);
    const float4* pb = (const float4*)(Pb + (size_t)iB[row] * HDIM);

    const float4* u0 = nullptr;
    const float4* pc = nullptr;
    float fb = 0.0f, cv = 0.0f, sv = 0.0f;
    if (MODE) {
        float ub = rB[row] * ((float)TABN / 10.0f);
        int ib = min((int)ub, TABN - 1);
        fb = ub - (float)ib;
        u0 = (const float4*)(Tb + (size_t)ib * 256);
        pc = (const float4*)(Pc + (size_t)iC[row] * HDIM);
        cv = cosv[row];
        sv = sinv[row];
    }

#pragma unroll
    for (int g = 0; g < 2; g++) {
        int c4 = lane + g * 32;  // float4 group index, cols c4*4..c4*4+3
        float4 a0 = t0[c4], a1 = t0[c4 + 64];
        float4 A = pa[c4], B = pb[c4];
        float v[4];
        v[0] = a0.x + fa * (a1.x - a0.x) + A.x + B.x;
        v[1] = a0.y + fa * (a1.y - a0.y) + A.y + B.y;
        v[2] = a0.z + fa * (a1.z - a0.z) + A.z + B.z;
        v[3] = a0.w + fa * (a1.w - a0.w) + A.w + B.w;
        if (MODE) {
            float4 b0 = u0[c4], b1 = u0[c4 + 64];
            float4 C = pc[c4];
            float4 wc = ((const float4*)Wcs)[c4];
            float4 ws = ((const float4*)(Wcs + 256))[c4];
            v[0] += b0.x + fb * (b1.x - b0.x) + C.x + cv * wc.x + sv * ws.x;
            v[1] += b0.y + fb * (b1.y - b0.y) + C.y + cv * wc.y + sv * ws.y;
            v[2] += b0.z + fb * (b1.z - b0.z) + C.z + cv * wc.z + sv * ws.z;
            v[3] += b0.w + fb * (b1.w - b0.w) + C.w + cv * wc.w + sv * ws.w;
        }
        uint2 oh, om;
        silu_split2(v[0], v[1], &oh.x, &om.x);
        silu_split2(v[2], v[3], &oh.y, &om.y);
        *(uint2*)(Chi + (size_t)row * HDIM + c4 * 4) = oh;
        *(uint2*)(Cmid + (size_t)row * HDIM + c4 * 4) = om;
    }
}

__global__ void __launch_bounds__(256) out_kernel(
    const __nv_bfloat16* __restrict__ Xhi, const __nv_bfloat16* __restrict__ Xmid,
    const float* __restrict__ W3, const float* __restrict__ b3, float* __restrict__ out) {
    __shared__ float Ws[HDIM * 3];
    int t = threadIdx.x;
    for (int i = t; i < HDIM * 3; i += 256) Ws[i] = W3[i];
    __syncthreads();
    int row = blockIdx.x * 8 + (t >> 5);
    int lane = t & 31;
    const uint32_t* ph = (const uint32_t*)Xhi + (size_t)row * 128;
    const uint32_t* pm = (const uint32_t*)Xmid + (size_t)row * 128;
    float s0 = 0.f, s1 = 0.f, s2 = 0.f;
#pragma unroll
    for (int i = 0; i < 4; i++) {
        uint32_t uh = ph[lane + i * 32], um = pm[lane + i * 32];
        __nv_bfloat162 bh = *reinterpret_cast<__nv_bfloat162*>(&uh);
        __nv_bfloat162 bm = *reinterpret_cast<__nv_bfloat162*>(&um);
        float x0 = __bfloat162float(bh.x) + __bfloat162float(bm.x);
        float x1 = __bfloat162float(bh.y) + __bfloat162float(bm.y);
        int k = 2 * (lane + i * 32);
        s0 = fmaf(x0, Ws[k * 3 + 0], s0); s1 = fmaf(x0, Ws[k * 3 + 1], s1);
        s2 = fmaf(x0, Ws[k * 3 + 2], s2);
        s0 = fmaf(x1, Ws[k * 3 + 3], s0); s1 = fmaf(x1, Ws[k * 3 + 4], s1);
        s2 = fmaf(x1, Ws[k * 3 + 5], s2);
    }
#pragma unroll
    for (int o = 16; o; o >>= 1) {
        s0 += __shfl_down_sync(0xffffffffu, s0, o);
        s1 += __shfl_down_sync(0xffffffffu, s1, o);
        s2 += __shfl_down_sync(0xffffffffu, s2, o);
    }
    if (lane == 0) {
        out[(size_t)row * 3 + 0] = s0 + b3[0];
        out[(size_t)row * 3 + 1] = s1 + b3[1];
        out[(size_t)row * 3 + 2] = s2 + b3[2];
    }
}

extern "C" void kernel_launch(void* const* d_in, const int* in_sizes, int n_in,
                              void* d_out, int out_size) {
    const float* h = (const float*)d_in[0];
    const int* src = (const int*)d_in[1];
    const int* dst = (const int*)d_in[2];
    const float* enorm = (const float*)d_in[3];
    const int* tsrc = (const int*)d_in[4];
    const int* tdi = (const int*)d_in[5];
    const int* tdj = (const int*)d_in[6];
    const float* nij = (const float*)d_in[7];
    const float* nik = (const float*)d_in[8];
    const float* cosv = (const float*)d_in[9];
    const float* sinv = (const float*)d_in[10];
    const float* mu = (const float*)d_in[11];
    const float* eW0 = (const float*)d_in[12];
    const float* eW1 = (const float*)d_in[13];
    const float* eW2 = (const float*)d_in[14];
    const float* eW3 = (const float*)d_in[15];
    const float* eb3 = (const float*)d_in[16];
    const float* tW0 = (const float*)d_in[17];
    const float* tW1 = (const float*)d_in[18];
    const float* tW2 = (const float*)d_in[19];
    const float* tW3 = (const float*)d_in[20];
    const float* tb3 = (const float*)d_in[21];
    float* out = (float*)d_out;

    __nv_bfloat16 *xH, *xM, *yH, *yM, *hH, *hM, *wH, *wM;
    float *P, *T;
    cudaGetSymbolAddress((void**)&xH, g_x_hi);
    cudaGetSymbolAddress((void**)&xM, g_x_mid);
    cudaGetSymbolAddress((void**)&yH, g_y_hi);
    cudaGetSymbolAddress((void**)&yM, g_y_mid);
    cudaGetSymbolAddress((void**)&hH, g_h_hi);
    cudaGetSymbolAddress((void**)&hM, g_h_mid);
    cudaGetSymbolAddress((void**)&wH, g_w_hi);
    cudaGetSymbolAddress((void**)&wM, g_w_mid);
    cudaGetSymbolAddress((void**)&P, g_P);
    cudaGetSymbolAddress((void**)&T, g_T);

    cudaFuncSetAttribute(gemm_kernel<0>, cudaFuncAttributeMaxDynamicSharedMemorySize, SMEM_GEMM);
    cudaFuncSetAttribute(gemm_kernel<1>, cudaFuncAttributeMaxDynamicSharedMemorySize, SMEM_GEMM);
    cudaFuncSetAttribute(pgemm_kernel, cudaFuncAttributeMaxDynamicSharedMemorySize, SMEM_GEMM);
    cudaFuncSetAttribute(table_kernel, cudaFuncAttributeMaxDynamicSharedMemorySize, 115200);

    // 1. prep_h
    prep_h_kernel<<<(NPAD * FDIM) / 256, 256>>>(h, hH, hM);
    // 2. fused prep_w (9 full-K slices)
    WS S;
    const float* srcs[9] = {eW0, eW0 + 32768, eW1, eW2, tW0, tW0 + 32768, tW0 + 65536, tW1, tW2};
    int KPs[9] = {128, 128, 256, 256, 128, 128, 128, 256, 256};
    int offs[9] = {E0A, E0B, E1, E2, T0A, T0B, T0C, T1, T2};
    for (int i = 0; i < 9; i++) { S.src[i] = srcs[i]; S.KP[i] = KPs[i]; S.off[i] = offs[i]; }
    prep_w_kernel<<<dim3(256, 1, 9), 256>>>(S, wH, wM);
    // 3. fused P gemms
    PG pg;
    int boffs[5] = {E0A, E0B, T0A, T0B, T0C};
    for (int i = 0; i < 5; i++) { pg.boff[i] = boffs[i]; pg.coff[i] = (size_t)i * PSZ; }
    pgemm_kernel<<<dim3(4, NPAD / 128, 5), 256, SMEM_GEMM>>>(hH, hM, wH, wM, P, pg);
    // 4. RBF projection tables
    table_kernel<<<dim3((TROWS + 31) / 32, 3), 256, 115200>>>(eW0, tW0, mu, T);

    float *Pea = P, *Peb = P + PSZ, *Pta = P + 2 * PSZ, *Ptb = P + 3 * PSZ, *Ptc = P + 4 * PSZ;
    dim3 ge(4, E_EDGES / 128), gt(4, T_TRIP / 128);
    // 5-8: edge path (launch #6 = mid_e1 -> ncu capture)
    l0g_kernel<0><<<E_EDGES / 8, 256>>>(enorm, nullptr, nullptr, nullptr,
                                        src, dst, nullptr, T, nullptr, nullptr,
                                        Pea, Peb, nullptr, xH, xM);
    gemm_kernel<0><<<ge, 256, SMEM_GEMM>>>(xH, xM, wH + E1, wM + E1, 256, 4, yH, yM);
    gemm_kernel<0><<<ge, 256, SMEM_GEMM>>>(yH, yM, wH + E2, wM + E2, 256, 4, xH, xM);
    out_kernel<<<E_EDGES / 8, 256>>>(xH, xM, eW3, eb3, out);
    // 9-12: triplet path
    l0g_kernel<1><<<T_TRIP / 8, 256>>>(nij, nik, cosv, sinv,
                                       tsrc, tdi, tdj, T + TOFF, T + 2 * TOFF,
                                       tW0 + 149504, Pta, Ptb, Ptc, xH, xM);
    gemm_kernel<0><<<gt, 256, SMEM_GEMM>>>(xH, xM, wH + T1, wM + T1, 256, 4, yH, yM);
    gemm_kernel<0><<<gt, 256, SMEM_GEMM>>>(yH, yM, wH + T2, wM + T2, 256, 4, xH, xM);
    out_kernel<<<T_TRIP / 8, 256>>>(xH, xM, tW3, tb3, out + (size_t)E_EDGES * 3);
}

// round 11
// speedup vs baseline: 2.2434x; 1.1950x over previous
#include <cuda_runtime.h>
#include <cuda_fp16.h>
#include <cstdint>

#define FDIM 128
#define HDIM 256
#define E_EDGES 262144
#define T_TRIP 393216
#define NPAD 20096
#define TABN 4096
#define TROWS 4097
#define TOFF ((size_t)TROWS * 256)

// A fp16 2-limb (2x16KB) + B fp16 1-limb (8KB) per 64-K chunk
#define SA_HI 0
#define SA_MID (16 * 1024)
#define SB (32 * 1024)
#define STAGE_BYTES (40 * 1024)
#define SMEM_GEMM (2 * STAGE_BYTES)

__device__ __half g_x_hi[(size_t)T_TRIP * HDIM];
__device__ __half g_x_mid[(size_t)T_TRIP * HDIM];
__device__ __half g_y_hi[(size_t)T_TRIP * HDIM];
__device__ __half g_y_mid[(size_t)T_TRIP * HDIM];
__device__ __half g_h_hi[(size_t)NPAD * FDIM];
__device__ __half g_h_mid[(size_t)NPAD * FDIM];
__device__ float g_P[5ull * NPAD * HDIM];
__device__ float g_T[3 * TOFF];
#define PSZ ((size_t)NPAD * HDIM)
#define E0A 0
#define E0B 32768
#define E1 98304
#define E2 163840
#define T0A 229376
#define T0B 262144
#define T0C 294912
#define T1 393216
#define T2 458752
__device__ __half g_w[524288];

__device__ __forceinline__ uint32_t smem_u32(const void* p) {
    uint32_t a;
    asm("{ .reg .u64 t; cvta.to.shared.u64 t, %1; cvt.u32.u64 %0, t; }" : "=r"(a) : "l"(p));
    return a;
}
__device__ __forceinline__ void cp16(uint32_t d, const void* s) {
    asm volatile("cp.async.cg.shared.global [%0], [%1], 16;" :: "r"(d), "l"(s));
}
#define CP_COMMIT() asm volatile("cp.async.commit_group;" ::: "memory")
#define CP_WAIT0() asm volatile("cp.async.wait_group 0;" ::: "memory")
#define CP_WAIT1() asm volatile("cp.async.wait_group 1;" ::: "memory")
#define LDSM4(r0, r1, r2, r3, a) \
    asm volatile("ldmatrix.sync.aligned.m8n8.x4.shared.b16 {%0,%1,%2,%3}, [%4];" \
                 : "=r"(r0), "=r"(r1), "=r"(r2), "=r"(r3) : "r"(a))

__device__ __forceinline__ void mma_f16(float c[4], const uint32_t a[4], const uint32_t b[2]) {
    asm volatile(
        "mma.sync.aligned.m16n8k16.row.col.f32.f16.f16.f32 "
        "{%0,%1,%2,%3}, {%4,%5,%6,%7}, {%8,%9}, {%0,%1,%2,%3};"
        : "+f"(c[0]), "+f"(c[1]), "+f"(c[2]), "+f"(c[3])
        : "r"(a[0]), "r"(a[1]), "r"(a[2]), "r"(a[3]), "r"(b[0]), "r"(b[1]));
}
__device__ __forceinline__ float silu_f(float x) { return x / (1.0f + __expf(-x)); }
__device__ __forceinline__ uint32_t pkhf2(__half a, __half b) {
    __half2 v(a, b);
    return *reinterpret_cast<uint32_t*>(&v);
}
__device__ __forceinline__ void silu_split2(float v0, float v1, uint32_t* oh, uint32_t* om) {
    float a0 = silu_f(v0), a1 = silu_f(v1);
    __half h0 = __float2half_rn(a0), h1 = __float2half_rn(a1);
    *oh = pkhf2(h0, h1);
    *om = pkhf2(__float2half_rn(a0 - __half2float(h0)),
                __float2half_rn(a1 - __half2float(h1)));
}

struct Frag {
    int a_row, a_kh, b_row, b_kh;
};
__device__ __forceinline__ void mma_chunk(uint32_t stage, int wm, int wn, const Frag& f,
                                          float acc[2][4][4]) {
#pragma unroll
    for (int ks = 0; ks < 4; ks++) {
        uint32_t aHf[2][4], aMf[2][4], bF[4][2];
#pragma unroll
        for (int mt = 0; mt < 2; mt++) {
            int r = wm + mt * 16 + f.a_row;
            uint32_t off = r * 128 + (((ks * 2 + f.a_kh) ^ (r & 7)) << 4);
            LDSM4(aHf[mt][0], aHf[mt][1], aHf[mt][2], aHf[mt][3], stage + SA_HI + off);
            LDSM4(aMf[mt][0], aMf[mt][1], aMf[mt][2], aMf[mt][3], stage + SA_MID + off);
        }
#pragma unroll
        for (int np = 0; np < 2; np++) {
            int r = wn + np * 16 + f.b_row;
            uint32_t off = r * 128 + (((ks * 2 + f.b_kh) ^ (r & 7)) << 4);
            uint32_t r0, r1, r2, r3;
            LDSM4(r0, r1, r2, r3, stage + SB + off);
            bF[np * 2][0] = r0; bF[np * 2][1] = r1;
            bF[np * 2 + 1][0] = r2; bF[np * 2 + 1][1] = r3;
        }
#pragma unroll
        for (int mt = 0; mt < 2; mt++)
#pragma unroll
            for (int nt = 0; nt < 4; nt++) {
                mma_f16(acc[mt][nt], aHf[mt], bF[nt]);
                mma_f16(acc[mt][nt], aMf[mt], bF[nt]);
            }
    }
}

__device__ __forceinline__ void load_chunk(uint32_t stage, int t, size_t koff,
                                           const char* aH, const char* aM,
                                           const char* bW, size_t ldb) {
#pragma unroll
    for (int i = 0; i < 4; i++) {
        int idx = t + i * 256;
        int r = idx >> 3, c16 = idx & 7;
        uint32_t doff = r * 128 + ((c16 ^ (r & 7)) << 4);
        size_t soff = (size_t)r * ldb + koff + c16 * 16;
        cp16(stage + SA_HI + doff, aH + soff);
        cp16(stage + SA_MID + doff, aM + soff);
    }
#pragma unroll
    for (int i = 0; i < 2; i++) {
        int idx = t + i * 256;
        int r = idx >> 3, c16 = idx & 7;
        uint32_t doff = r * 128 + ((c16 ^ (r & 7)) << 4);
        size_t soff = (size_t)r * ldb + koff + c16 * 16;
        cp16(stage + SB + doff, bW + soff);
    }
    CP_COMMIT();
}

template <int EPI>
__device__ __forceinline__ void gemm_core(
    const __half* Ahi, const __half* Amid, const __half* Bw,
    int ld, int nchunks, void* C1, void* C2, int row0, int n0cta, char* smem) {
    uint32_t sb = smem_u32(smem);
    int t = threadIdx.x, lane = t & 31, w = t >> 5;
    int wm = (w & 3) * 32, wn = (w >> 2) * 32;

    const char* aH = (const char*)(Ahi + (size_t)row0 * ld);
    const char* aM = (const char*)(Amid + (size_t)row0 * ld);
    const char* bW = (const char*)(Bw + (size_t)n0cta * ld);
    const size_t ldb = (size_t)ld * 2;

    float acc[2][4][4];
#pragma unroll
    for (int i = 0; i < 2; i++)
#pragma unroll
        for (int j = 0; j < 4; j++)
#pragma unroll
            for (int q = 0; q < 4; q++) acc[i][j][q] = 0.0f;
    Frag f{lane & 15, lane >> 4, (lane & 7) + ((lane >> 4) << 3), (lane >> 3) & 1};

    load_chunk(sb, t, 0, aH, aM, bW, ldb);
    for (int c = 0; c < nchunks; c++) {
        if (c + 1 < nchunks) {
            load_chunk(sb + ((c + 1) & 1) * STAGE_BYTES, t, (size_t)(c + 1) * 128,
                       aH, aM, bW, ldb);
            CP_WAIT1();
        } else {
            CP_WAIT0();
        }
        __syncthreads();
        mma_chunk(sb + (c & 1) * STAGE_BYTES, wm, wn, f, acc);
        __syncthreads();
    }

    int mrow = lane >> 2, ncol = (lane & 3) * 2;
#pragma unroll
    for (int mt = 0; mt < 2; mt++)
#pragma unroll
        for (int nt = 0; nt < 4; nt++) {
            int r = row0 + wm + mt * 16 + mrow;
            int cc = n0cta + wn + nt * 8 + ncol;
            if (EPI == 0) {
                uint32_t oh, om;
                silu_split2(acc[mt][nt][0], acc[mt][nt][1], &oh, &om);
                *(uint32_t*)((__half*)C1 + (size_t)r * HDIM + cc) = oh;
                *(uint32_t*)((__half*)C2 + (size_t)r * HDIM + cc) = om;
                silu_split2(acc[mt][nt][2], acc[mt][nt][3], &oh, &om);
                *(uint32_t*)((__half*)C1 + (size_t)(r + 8) * HDIM + cc) = oh;
                *(uint32_t*)((__half*)C2 + (size_t)(r + 8) * HDIM + cc) = om;
            } else {
                *(float2*)((float*)C1 + (size_t)r * HDIM + cc) =
                    make_float2(acc[mt][nt][0], acc[mt][nt][1]);
                *(float2*)((float*)C1 + (size_t)(r + 8) * HDIM + cc) =
                    make_float2(acc[mt][nt][2], acc[mt][nt][3]);
            }
        }
}

template <int EPI>
__global__ void __launch_bounds__(256, 2) gemm_kernel(
    const __half* __restrict__ Ahi, const __half* __restrict__ Amid,
    const __half* __restrict__ Bw,
    int ld, int nchunks, void* __restrict__ C1, void* __restrict__ C2) {
    extern __shared__ char smem[];
    gemm_core<EPI>(Ahi, Amid, Bw, ld, nchunks, C1, C2,
                   blockIdx.y * 128, blockIdx.x * 64, smem);
}

struct PG {
    int boff[5];
    size_t coff[5];
};
__global__ void __launch_bounds__(256, 2) pgemm_kernel(
    const __half* __restrict__ hH, const __half* __restrict__ hM,
    const __half* __restrict__ wW, float* __restrict__ P, PG pg) {
    extern __shared__ char smem[];
    int z = blockIdx.z;
    gemm_core<1>(hH, hM, wW + pg.boff[z], 128, 2,
                 P + pg.coff[z], nullptr, blockIdx.y * 128, blockIdx.x * 64, smem);
}

__global__ void prep_h_kernel(const float* __restrict__ h,
                              __half* __restrict__ hi, __half* __restrict__ mid) {
    size_t idx = (size_t)blockIdx.x * 256 + threadIdx.x;
    int row = (int)(idx >> 7);
    float v = (row < 20000) ? h[idx] : 0.0f;
    __half hh = __float2half_rn(v);
    hi[idx] = hh;
    mid[idx] = __float2half_rn(v - __half2float(hh));
}

struct WS {
    const float* src[9];
    int KP[9], off[9];
};
__global__ void prep_w_kernel(WS S, __half* __restrict__ w) {
    int z = blockIdx.z;
    int KP = S.KP[z];
    if (blockIdx.x >= KP) return;
    int idx = blockIdx.x * 256 + threadIdx.x;
    int n = idx / KP, k = idx % KP;
    w[S.off[z] + idx] = __float2half_rn(S.src[z][(size_t)k * HDIM + n]);
}

__global__ void table_kernel(const float* __restrict__ eW0, const float* __restrict__ tW0,
                             const float* __restrict__ mu) {
    extern __shared__ float sm[];
    float* Wsm = sm;
    float* rbf = sm + 25600;
    int z = blockIdx.y;
    const float* Wsrc = (z == 0) ? eW0 + 65536 : ((z == 1) ? tW0 + 98304 : tW0 + 123904);
    float* Tout = g_T + (size_t)z * TOFF;
    int t = threadIdx.x;
    for (int i = t; i < 25600; i += 256) Wsm[i] = Wsrc[i];
    int r0 = blockIdx.x * 32;
    for (int i = t; i < 3200; i += 256) {
        int rr = i / 100, k = i % 100;
        float r = (float)(r0 + rr) * (10.0f / (float)TABN);
        float d = __ldg(mu + k) - r;
        rbf[i] = expf(-10.0f * d * d);
    }
    __syncthreads();
    for (int rr = 0; rr < 32; rr++) {
        int row = r0 + rr;
        if (row > TABN) break;
        float acc = 0.0f;
#pragma unroll 4
        for (int k = 0; k < 100; k++) acc = fmaf(rbf[rr * 100 + k], Wsm[k * 256 + t], acc);
        Tout[(size_t)row * 256 + t] = acc;
    }
}

template <int MODE>
__global__ void __launch_bounds__(256) l0g_kernel(
    const float* __restrict__ rA, const float* __restrict__ rB,
    const float* __restrict__ cosv, const float* __restrict__ sinv,
    const int* __restrict__ iA, const int* __restrict__ iB, const int* __restrict__ iC,
    const float* __restrict__ Ta, const float* __restrict__ Tb,
    const float* __restrict__ Wcs,
    const float* __restrict__ Pa, const float* __restrict__ Pb, const float* __restrict__ Pc,
    __half* __restrict__ Chi, __half* __restrict__ Cmid) {
    int w = threadIdx.x >> 5, lane = threadIdx.x & 31;
    int row = blockIdx.x * 8 + w;

    float ua = rA[row] * ((float)TABN / 10.0f);
    int ia = min((int)ua, TABN - 1);
    float fa = ua - (float)ia;
    const float4* t0 = (const float4*)(Ta + (size_t)ia * 256);
    const float4* pa = (const float4*)(Pa + (size_t)iA[row] * HDIM);
    const float4* pb = (const float4*)(Pb + (size_t)iB[row] * HDIM);

    const float4* u0 = nullptr;
    const float4* pc = nullptr;
    float fb = 0.0f, cv = 0.0f, sv = 0.0f;
    if (MODE) {
        float ub = rB[row] * ((float)TABN / 10.0f);
        int ib = min((int)ub, TABN - 1);
        fb = ub - (float)ib;
        u0 = (const float4*)(Tb + (size_t)ib * 256);
        pc = (const float4*)(Pc + (size_t)iC[row] * HDIM);
        cv = cosv[row];
        sv = sinv[row];
    }

#pragma unroll
    for (int g = 0; g < 2; g++) {
        int c4 = lane + g * 32;
        float4 a0 = t0[c4], a1 = t0[c4 + 64];
        float4 A = pa[c4], B = pb[c4];
        float v[4];
        v[0] = a0.x + fa * (a1.x - a0.x) + A.x + B.x;
        v[1] = a0.y + fa * (a1.y - a0.y) + A.y + B.y;
        v[2] = a0.z + fa * (a1.z - a0.z) + A.z + B.z;
        v[3] = a0.w + fa * (a1.w - a0.w) + A.w + B.w;
        if (MODE) {
            float4 b0 = u0[c4], b1 = u0[c4 + 64];
            float4 C = pc[c4];
            float4 wc = ((const float4*)Wcs)[c4];
            float4 ws = ((const float4*)(Wcs + 256))[c4];
            v[0] += b0.x + fb * (b1.x - b0.x) + C.x + cv * wc.x + sv * ws.x;
            v[1] += b0.y + fb * (b1.y - b0.y) + C.y + cv * wc.y + sv * ws.y;
            v[2] += b0.z + fb * (b1.z - b0.z) + C.z + cv * wc.z + sv * ws.z;
            v[3] += b0.w + fb * (b1.w - b0.w) + C.w + cv * wc.w + sv * ws.w;
        }
        uint2 oh, om;
        silu_split2(v[0], v[1], &oh.x, &om.x);
        silu_split2(v[2], v[3], &oh.y, &om.y);
        *(uint2*)(Chi + (size_t)row * HDIM + c4 * 4) = oh;
        *(uint2*)(Cmid + (size_t)row * HDIM + c4 * 4) = om;
    }
}

__global__ void __launch_bounds__(256) out_kernel(
    const __half* __restrict__ Xhi, const __half* __restrict__ Xmid,
    const float* __restrict__ W3, const float* __restrict__ b3, float* __restrict__ out) {
    __shared__ float Ws[HDIM * 3];
    int t = threadIdx.x;
    for (int i = t; i < HDIM * 3; i += 256) Ws[i] = W3[i];
    __syncthreads();
    int row = blockIdx.x * 8 + (t >> 5);
    int lane = t & 31;
    const uint32_t* ph = (const uint32_t*)Xhi + (size_t)row * 128;
    const uint32_t* pm = (const uint32_t*)Xmid + (size_t)row * 128;
    float s0 = 0.f, s1 = 0.f, s2 = 0.f;
#pragma unroll
    for (int i = 0; i < 4; i++) {
        uint32_t uh = ph[lane + i * 32], um = pm[lane + i * 32];
        __half2 bh = *reinterpret_cast<__half2*>(&uh);
        __half2 bm = *reinterpret_cast<__half2*>(&um);
        float x0 = __half2float(bh.x) + __half2float(bm.x);
        float x1 = __half2float(bh.y) + __half2float(bm.y);
        int k = 2 * (lane + i * 32);
        s0 = fmaf(x0, Ws[k * 3 + 0], s0); s1 = fmaf(x0, Ws[k * 3 + 1], s1);
        s2 = fmaf(x0, Ws[k * 3 + 2], s2);
        s0 = fmaf(x1, Ws[k * 3 + 3], s0); s1 = fmaf(x1, Ws[k * 3 + 4], s1);
        s2 = fmaf(x1, Ws[k * 3 + 5], s2);
    }
#pragma unroll
    for (int o = 16; o; o >>= 1) {
        s0 += __shfl_down_sync(0xffffffffu, s0, o);
        s1 += __shfl_down_sync(0xffffffffu, s1, o);
        s2 += __shfl_down_sync(0xffffffffu, s2, o);
    }
    if (lane == 0) {
        out[(size_t)row * 3 + 0] = s0 + b3[0];
        out[(size_t)row * 3 + 1] = s1 + b3[1];
        out[(size_t)row * 3 + 2] = s2 + b3[2];
    }
}

extern "C" void kernel_launch(void* const* d_in, const int* in_sizes, int n_in,
                              void* d_out, int out_size) {
    const float* h = (const float*)d_in[0];
    const int* src = (const int*)d_in[1];
    const int* dst = (const int*)d_in[2];
    const float* enorm = (const float*)d_in[3];
    const int* tsrc = (const int*)d_in[4];
    const int* tdi = (const int*)d_in[5];
    const int* tdj = (const int*)d_in[6];
    const float* nij = (const float*)d_in[7];
    const float* nik = (const float*)d_in[8];
    const float* cosv = (const float*)d_in[9];
    const float* sinv = (const float*)d_in[10];
    const float* mu = (const float*)d_in[11];
    const float* eW0 = (const float*)d_in[12];
    const float* eW1 = (const float*)d_in[13];
    const float* eW2 = (const float*)d_in[14];
    const float* eW3 = (const float*)d_in[15];
    const float* eb3 = (const float*)d_in[16];
    const float* tW0 = (const float*)d_in[17];
    const float* tW1 = (const float*)d_in[18];
    const float* tW2 = (const float*)d_in[19];
    const float* tW3 = (const float*)d_in[20];
    const float* tb3 = (const float*)d_in[21];
    float* out = (float*)d_out;

    __half *xH, *xM, *yH, *yM, *hH, *hM, *wW;
    float *P, *T;
    cudaGetSymbolAddress((void**)&xH, g_x_hi);
    cudaGetSymbolAddress((void**)&xM, g_x_mid);
    cudaGetSymbolAddress((void**)&yH, g_y_hi);
    cudaGetSymbolAddress((void**)&yM, g_y_mid);
    cudaGetSymbolAddress((void**)&hH, g_h_hi);
    cudaGetSymbolAddress((void**)&hM, g_h_mid);
    cudaGetSymbolAddress((void**)&wW, g_w);
    cudaGetSymbolAddress((void**)&P, g_P);
    cudaGetSymbolAddress((void**)&T, g_T);

    cudaFuncSetAttribute(gemm_kernel<0>, cudaFuncAttributeMaxDynamicSharedMemorySize, SMEM_GEMM);
    cudaFuncSetAttribute(gemm_kernel<1>, cudaFuncAttributeMaxDynamicSharedMemorySize, SMEM_GEMM);
    cudaFuncSetAttribute(pgemm_kernel, cudaFuncAttributeMaxDynamicSharedMemorySize, SMEM_GEMM);
    cudaFuncSetAttribute(table_kernel, cudaFuncAttributeMaxDynamicSharedMemorySize, 115200);

    prep_h_kernel<<<(NPAD * FDIM) / 256, 256>>>(h, hH, hM);
    WS S;
    const float* srcs[9] = {eW0, eW0 + 32768, eW1, eW2, tW0, tW0 + 32768, tW0 + 65536, tW1, tW2};
    int KPs[9] = {128, 128, 256, 256, 128, 128, 128, 256, 256};
    int offs[9] = {E0A, E0B, E1, E2, T0A, T0B, T0C, T1, T2};
    for (int i = 0; i < 9; i++) { S.src[i] = srcs[i]; S.KP[i] = KPs[i]; S.off[i] = offs[i]; }
    prep_w_kernel<<<dim3(256, 1, 9), 256>>>(S, wW);
    PG pg;
    int boffs[5] = {E0A, E0B, T0A, T0B, T0C};
    for (int i = 0; i < 5; i++) { pg.boff[i] = boffs[i]; pg.coff[i] = (size_t)i * PSZ; }
    pgemm_kernel<<<dim3(4, NPAD / 128, 5), 256, SMEM_GEMM>>>(hH, hM, wW, P, pg);
    table_kernel<<<dim3((TROWS + 31) / 32, 3), 256, 115200>>>(eW0, tW0, mu);

    float *Pea = P, *Peb = P + PSZ, *Pta = P + 2 * PSZ, *Ptb = P + 3 * PSZ, *Ptc = P + 4 * PSZ;
    dim3 ge(4, E_EDGES / 128), gt(4, T_TRIP / 128);
    l0g_kernel<0><<<E_EDGES / 8, 256>>>(enorm, nullptr, nullptr, nullptr,
                                        src, dst, nullptr, T, nullptr, nullptr,
                                        Pea, Peb, nullptr, xH, xM);
    gemm_kernel<0><<<ge, 256, SMEM_GEMM>>>(xH, xM, wW + E1, 256, 4, yH, yM);
    gemm_kernel<0><<<ge, 256, SMEM_GEMM>>>(yH, yM, wW + E2, 256, 4, xH, xM);
    out_kernel<<<E_EDGES / 8, 256>>>(xH, xM, eW3, eb3, out);
    l0g_kernel<1><<<T_TRIP / 8, 256>>>(nij, nik, cosv, sinv,
                                       tsrc, tdi, tdj, T + TOFF, T + 2 * TOFF,
                                       tW0 + 149504, Pta, Ptb, Ptc, xH, xM);
    gemm_kernel<0><<<gt, 256, SMEM_GEMM>>>(xH, xM, wW + T1, 256, 4, yH, yM);
    gemm_kernel<0><<<gt, 256, SMEM_GEMM>>>(yH, yM, wW + T2, 256, 4, xH, xM);
    out_kernel<<<T_TRIP / 8, 256>>>(xH, xM, tW3, tb3, out + (size_t)E_EDGES * 3);
}

// round 12
// speedup vs baseline: 2.7677x; 1.2337x over previous
#include <cuda_runtime.h>
#include <cuda_fp16.h>
#include <cstdint>

#define FDIM 128
#define HDIM 256
#define E_EDGES 262144
#define T_TRIP 393216
#define NPAD 20096
#define TABN 4096
#define TROWS 4097
#define TOFF ((size_t)TROWS * 256)

// CTA 128x128: A fp16 2-limb (2x16KB) + B fp16 1-limb (16KB) per 64-K chunk
#define SA_HI 0
#define SA_MID (16 * 1024)
#define SB (32 * 1024)
#define STAGE_BYTES (48 * 1024)
#define SMEM_GEMM (2 * STAGE_BYTES)

__device__ __half g_x_hi[(size_t)T_TRIP * HDIM];
__device__ __half g_x_mid[(size_t)T_TRIP * HDIM];
__device__ __half g_y_hi[(size_t)T_TRIP * HDIM];
__device__ __half g_y_mid[(size_t)T_TRIP * HDIM];
__device__ __half g_h_hi[(size_t)NPAD * FDIM];
__device__ __half g_h_mid[(size_t)NPAD * FDIM];
__device__ float g_P[5ull * NPAD * HDIM];
__device__ float g_T[3 * TOFF];
__device__ float g_scr[(size_t)T_TRIP * 6];
#define PSZ ((size_t)NPAD * HDIM)
#define E0A 0
#define E0B 32768
#define E1 98304
#define E2 163840
#define T0A 229376
#define T0B 262144
#define T0C 294912
#define T1 393216
#define T2 458752
__device__ __half g_w[524288];

__device__ __forceinline__ uint32_t smem_u32(const void* p) {
    uint32_t a;
    asm("{ .reg .u64 t; cvta.to.shared.u64 t, %1; cvt.u32.u64 %0, t; }" : "=r"(a) : "l"(p));
    return a;
}
__device__ __forceinline__ void cp16(uint32_t d, const void* s) {
    asm volatile("cp.async.cg.shared.global [%0], [%1], 16;" :: "r"(d), "l"(s));
}
#define CP_COMMIT() asm volatile("cp.async.commit_group;" ::: "memory")
#define CP_WAIT0() asm volatile("cp.async.wait_group 0;" ::: "memory")
#define CP_WAIT1() asm volatile("cp.async.wait_group 1;" ::: "memory")
#define LDSM4(r0, r1, r2, r3, a) \
    asm volatile("ldmatrix.sync.aligned.m8n8.x4.shared.b16 {%0,%1,%2,%3}, [%4];" \
                 : "=r"(r0), "=r"(r1), "=r"(r2), "=r"(r3) : "r"(a))

__device__ __forceinline__ void mma_f16(float c[4], const uint32_t a[4], const uint32_t b[2]) {
    asm volatile(
        "mma.sync.aligned.m16n8k16.row.col.f32.f16.f16.f32 "
        "{%0,%1,%2,%3}, {%4,%5,%6,%7}, {%8,%9}, {%0,%1,%2,%3};"
        : "+f"(c[0]), "+f"(c[1]), "+f"(c[2]), "+f"(c[3])
        : "r"(a[0]), "r"(a[1]), "r"(a[2]), "r"(a[3]), "r"(b[0]), "r"(b[1]));
}
__device__ __forceinline__ float silu_f(float x) { return x / (1.0f + __expf(-x)); }
__device__ __forceinline__ uint32_t pkhf2(__half a, __half b) {
    __half2 v(a, b);
    return *reinterpret_cast<uint32_t*>(&v);
}
__device__ __forceinline__ void silu_split2(float v0, float v1, uint32_t* oh, uint32_t* om) {
    float a0 = silu_f(v0), a1 = silu_f(v1);
    __half h0 = __float2half_rn(a0), h1 = __float2half_rn(a1);
    *oh = pkhf2(h0, h1);
    *om = pkhf2(__float2half_rn(a0 - __half2float(h0)),
                __float2half_rn(a1 - __half2float(h1)));
}

struct Frag {
    int a_row, a_kh, b_row, b_kh;
};
// CTA 128x128, warp 32x64: acc[2 mt][8 nt][4]
__device__ __forceinline__ void mma_chunk(uint32_t stage, int wm, int wn, const Frag& f,
                                          float acc[2][8][4]) {
#pragma unroll
    for (int ks = 0; ks < 4; ks++) {
        uint32_t aHf[2][4], aMf[2][4], bF[8][2];
#pragma unroll
        for (int mt = 0; mt < 2; mt++) {
            int r = wm + mt * 16 + f.a_row;
            uint32_t off = r * 128 + (((ks * 2 + f.a_kh) ^ (r & 7)) << 4);
            LDSM4(aHf[mt][0], aHf[mt][1], aHf[mt][2], aHf[mt][3], stage + SA_HI + off);
            LDSM4(aMf[mt][0], aMf[mt][1], aMf[mt][2], aMf[mt][3], stage + SA_MID + off);
        }
#pragma unroll
        for (int np = 0; np < 4; np++) {
            int r = wn + np * 16 + f.b_row;
            uint32_t off = r * 128 + (((ks * 2 + f.b_kh) ^ (r & 7)) << 4);
            uint32_t r0, r1, r2, r3;
            LDSM4(r0, r1, r2, r3, stage + SB + off);
            bF[np * 2][0] = r0; bF[np * 2][1] = r1;
            bF[np * 2 + 1][0] = r2; bF[np * 2 + 1][1] = r3;
        }
#pragma unroll
        for (int mt = 0; mt < 2; mt++)
#pragma unroll
            for (int nt = 0; nt < 8; nt++) {
                mma_f16(acc[mt][nt], aHf[mt], bF[nt]);
                mma_f16(acc[mt][nt], aMf[mt], bF[nt]);
            }
    }
}

// A: 128 rows x 2 limbs, B: 128 rows x 1 limb (each 1024 / 1024 16B units)
__device__ __forceinline__ void load_chunk(uint32_t stage, int t, size_t koff,
                                           const char* aH, const char* aM,
                                           const char* bW, size_t ldb) {
#pragma unroll
    for (int i = 0; i < 4; i++) {
        int idx = t + i * 256;
        int r = idx >> 3, c16 = idx & 7;
        uint32_t doff = r * 128 + ((c16 ^ (r & 7)) << 4);
        size_t soff = (size_t)r * ldb + koff + c16 * 16;
        cp16(stage + SA_HI + doff, aH + soff);
        cp16(stage + SA_MID + doff, aM + soff);
        cp16(stage + SB + doff, bW + soff);
    }
    CP_COMMIT();
}

// EPI: 0 = silu+fp16 limb split, 1 = raw f32, 2 = fused out-layer (W3 partials)
template <int EPI>
__device__ __forceinline__ void gemm_core(
    const __half* Ahi, const __half* Amid, const __half* Bw,
    int ld, int nchunks, void* C1, void* C2, const float* W3,
    int row0, int n0cta, int cblk, char* smem) {
    uint32_t sb = smem_u32(smem);
    int t = threadIdx.x, lane = t & 31, w = t >> 5;
    int wm = (w & 3) * 32, wn = (w >> 2) * 64;

    const char* aH = (const char*)(Ahi + (size_t)row0 * ld);
    const char* aM = (const char*)(Amid + (size_t)row0 * ld);
    const char* bW = (const char*)(Bw + (size_t)n0cta * ld);
    const size_t ldb = (size_t)ld * 2;

    float acc[2][8][4];
#pragma unroll
    for (int i = 0; i < 2; i++)
#pragma unroll
        for (int j = 0; j < 8; j++)
#pragma unroll
            for (int q = 0; q < 4; q++) acc[i][j][q] = 0.0f;
    Frag f{lane & 15, lane >> 4, (lane & 7) + ((lane >> 4) << 3), (lane >> 3) & 1};

    load_chunk(sb, t, 0, aH, aM, bW, ldb);
    for (int c = 0; c < nchunks; c++) {
        if (c + 1 < nchunks) {
            load_chunk(sb + ((c + 1) & 1) * STAGE_BYTES, t, (size_t)(c + 1) * 128,
                       aH, aM, bW, ldb);
            CP_WAIT1();
        } else {
            CP_WAIT0();
        }
        __syncthreads();
        mma_chunk(sb + (c & 1) * STAGE_BYTES, wm, wn, f, acc);
        __syncthreads();
    }

    int mrow = lane >> 2, ncol = (lane & 3) * 2;
    if (EPI == 2) {
        // Fused out-layer: partial[row][3] = sum_cols silu(acc) * W3[col][:]
        float* w3s = (float*)smem;            // 384 floats: W3 rows n0cta..+127
        float* rsum = (float*)smem + 384;     // 128*3 floats
        for (int i = t; i < 384; i += 256) w3s[i] = W3[n0cta * 3 + i];
        for (int i = t; i < 384; i += 256) rsum[i] = 0.0f;
        __syncthreads();
        float part[4][3];
#pragma unroll
        for (int rs = 0; rs < 4; rs++)
#pragma unroll
            for (int o = 0; o < 3; o++) part[rs][o] = 0.0f;
#pragma unroll
        for (int mt = 0; mt < 2; mt++)
#pragma unroll
            for (int nt = 0; nt < 8; nt++)
#pragma unroll
                for (int sr = 0; sr < 2; sr++)
#pragma unroll
                    for (int e = 0; e < 2; e++) {
                        int cl = wn + nt * 8 + ncol + e;
                        float v = silu_f(acc[mt][nt][sr * 2 + e]);
#pragma unroll
                        for (int o = 0; o < 3; o++)
                            part[mt * 2 + sr][o] = fmaf(v, w3s[cl * 3 + o], part[mt * 2 + sr][o]);
                    }
#pragma unroll
        for (int rs = 0; rs < 4; rs++)
#pragma unroll
            for (int o = 0; o < 3; o++) {
                part[rs][o] += __shfl_xor_sync(0xffffffffu, part[rs][o], 1);
                part[rs][o] += __shfl_xor_sync(0xffffffffu, part[rs][o], 2);
            }
        // two-phase deterministic cross-warp (wn half) reduce
        if ((w >> 2) == 0 && (lane & 3) == 0) {
#pragma unroll
            for (int rs = 0; rs < 4; rs++) {
                int r = wm + (rs >> 1) * 16 + (rs & 1) * 8 + mrow;
#pragma unroll
                for (int o = 0; o < 3; o++) rsum[r * 3 + o] = part[rs][o];
            }
        }
        __syncthreads();
        if ((w >> 2) == 1 && (lane & 3) == 0) {
#pragma unroll
            for (int rs = 0; rs < 4; rs++) {
                int r = wm + (rs >> 1) * 16 + (rs & 1) * 8 + mrow;
#pragma unroll
                for (int o = 0; o < 3; o++) rsum[r * 3 + o] += part[rs][o];
            }
        }
        __syncthreads();
        float* scr = (float*)C1;
        for (int i = t; i < 384; i += 256) {
            int r = i / 3, o = i % 3;
            scr[((size_t)(row0 + r) * 2 + cblk) * 3 + o] = rsum[i];
        }
        return;
    }
#pragma unroll
    for (int mt = 0; mt < 2; mt++)
#pragma unroll
        for (int nt = 0; nt < 8; nt++) {
            int r = row0 + wm + mt * 16 + mrow;
            int cc = n0cta + wn + nt * 8 + ncol;
            if (EPI == 0) {
                uint32_t oh, om;
                silu_split2(acc[mt][nt][0], acc[mt][nt][1], &oh, &om);
                *(uint32_t*)((__half*)C1 + (size_t)r * HDIM + cc) = oh;
                *(uint32_t*)((__half*)C2 + (size_t)r * HDIM + cc) = om;
                silu_split2(acc[mt][nt][2], acc[mt][nt][3], &oh, &om);
                *(uint32_t*)((__half*)C1 + (size_t)(r + 8) * HDIM + cc) = oh;
                *(uint32_t*)((__half*)C2 + (size_t)(r + 8) * HDIM + cc) = om;
            } else {
                *(float2*)((float*)C1 + (size_t)r * HDIM + cc) =
                    make_float2(acc[mt][nt][0], acc[mt][nt][1]);
                *(float2*)((float*)C1 + (size_t)(r + 8) * HDIM + cc) =
                    make_float2(acc[mt][nt][2], acc[mt][nt][3]);
            }
        }
}

template <int EPI>
__global__ void __launch_bounds__(256, 2) gemm_kernel(
    const __half* __restrict__ Ahi, const __half* __restrict__ Amid,
    const __half* __restrict__ Bw,
    int ld, int nchunks, void* __restrict__ C1, void* __restrict__ C2,
    const float* __restrict__ W3) {
    extern __shared__ char smem[];
    gemm_core<EPI>(Ahi, Amid, Bw, ld, nchunks, C1, C2, W3,
                   blockIdx.y * 128, blockIdx.x * 128, blockIdx.x, smem);
}

struct PG {
    int boff[5];
    size_t coff[5];
};
__global__ void __launch_bounds__(256, 2) pgemm_kernel(
    const __half* __restrict__ hH, const __half* __restrict__ hM,
    const __half* __restrict__ wW, float* __restrict__ P, PG pg) {
    extern __shared__ char smem[];
    int z = blockIdx.z;
    gemm_core<1>(hH, hM, wW + pg.boff[z], 128, 2,
                 P + pg.coff[z], nullptr, nullptr,
                 blockIdx.y * 128, blockIdx.x * 128, blockIdx.x, smem);
}

__global__ void prep_h_kernel(const float* __restrict__ h,
                              __half* __restrict__ hi, __half* __restrict__ mid) {
    size_t idx = (size_t)blockIdx.x * 256 + threadIdx.x;
    int row = (int)(idx >> 7);
    float v = (row < 20000) ? h[idx] : 0.0f;
    __half hh = __float2half_rn(v);
    hi[idx] = hh;
    mid[idx] = __float2half_rn(v - __half2float(hh));
}

struct WS {
    const float* src[9];
    int KP[9], off[9];
};
__global__ void prep_w_kernel(WS S, __half* __restrict__ w) {
    int z = blockIdx.z;
    int KP = S.KP[z];
    if (blockIdx.x >= KP) return;
    int idx = blockIdx.x * 256 + threadIdx.x;
    int n = idx / KP, k = idx % KP;
    w[S.off[z] + idx] = __float2half_rn(S.src[z][(size_t)k * HDIM + n]);
}

// Tables: block = 32 rows x 64 cols, threads = 64 cols x 4 row-lanes
__global__ void table_kernel(const float* __restrict__ eW0, const float* __restrict__ tW0,
                             const float* __restrict__ mu) {
    __shared__ float Wsm[100 * 64];
    __shared__ float rbf[32 * 100];
    int z = blockIdx.z, cb = blockIdx.y, r0 = blockIdx.x * 32;
    const float* Wsrc = ((z == 0) ? eW0 + 65536 : ((z == 1) ? tW0 + 98304 : tW0 + 123904))
                        + cb * 64;
    float* Tout = g_T + (size_t)z * TOFF + cb * 64;
    int t = threadIdx.x;
    for (int i = t; i < 6400; i += 256) {
        int k = i >> 6, c = i & 63;
        Wsm[i] = Wsrc[k * 256 + c];
    }
    for (int i = t; i < 3200; i += 256) {
        int rr = i / 100, k = i % 100;
        float r = (float)(r0 + rr) * (10.0f / (float)TABN);
        float d = __ldg(mu + k) - r;
        rbf[i] = expf(-10.0f * d * d);
    }
    __syncthreads();
    int col = t & 63, rl = t >> 6;
#pragma unroll
    for (int p = 0; p < 8; p++) {
        int rr = rl + p * 4, row = r0 + rr;
        if (row > TABN) break;
        float acc = 0.0f;
#pragma unroll 4
        for (int k = 0; k < 100; k++) acc = fmaf(rbf[rr * 100 + k], Wsm[k * 64 + col], acc);
        Tout[(size_t)row * 256 + col] = acc;
    }
}

template <int MODE>
__global__ void __launch_bounds__(256) l0g_kernel(
    const float* __restrict__ rA, const float* __restrict__ rB,
    const float* __restrict__ cosv, const float* __restrict__ sinv,
    const int* __restrict__ iA, const int* __restrict__ iB, const int* __restrict__ iC,
    const float* __restrict__ Ta, const float* __restrict__ Tb,
    const float* __restrict__ Wcs,
    const float* __restrict__ Pa, const float* __restrict__ Pb, const float* __restrict__ Pc,
    __half* __restrict__ Chi, __half* __restrict__ Cmid) {
    int w = threadIdx.x >> 5, lane = threadIdx.x & 31;
    int row = blockIdx.x * 8 + w;

    float ua = rA[row] * ((float)TABN / 10.0f);
    int ia = min((int)ua, TABN - 1);
    float fa = ua - (float)ia;
    const float4* t0 = (const float4*)(Ta + (size_t)ia * 256);
    const float4* pa = (const float4*)(Pa + (size_t)iA[row] * HDIM);
    const float4* pb = (const float4*)(Pb + (size_t)iB[row] * HDIM);

    const float4* u0 = nullptr;
    const float4* pc = nullptr;
    float fb = 0.0f, cv = 0.0f, sv = 0.0f;
    if (MODE) {
        float ub = rB[row] * ((float)TABN / 10.0f);
        int ib = min((int)ub, TABN - 1);
        fb = ub - (float)ib;
        u0 = (const float4*)(Tb + (size_t)ib * 256);
        pc = (const float4*)(Pc + (size_t)iC[row] * HDIM);
        cv = cosv[row];
        sv = sinv[row];
    }

#pragma unroll
    for (int g = 0; g < 2; g++) {
        int c4 = lane + g * 32;
        float4 a0 = t0[c4], a1 = t0[c4 + 64];
        float4 A = pa[c4], B = pb[c4];
        float v[4];
        v[0] = a0.x + fa * (a1.x - a0.x) + A.x + B.x;
        v[1] = a0.y + fa * (a1.y - a0.y) + A.y + B.y;
        v[2] = a0.z + fa * (a1.z - a0.z) + A.z + B.z;
        v[3] = a0.w + fa * (a1.w - a0.w) + A.w + B.w;
        if (MODE) {
            float4 b0 = u0[c4], b1 = u0[c4 + 64];
            float4 C = pc[c4];
            float4 wc = ((const float4*)Wcs)[c4];
            float4 ws = ((const float4*)(Wcs + 256))[c4];
            v[0] += b0.x + fb * (b1.x - b0.x) + C.x + cv * wc.x + sv * ws.x;
            v[1] += b0.y + fb * (b1.y - b0.y) + C.y + cv * wc.y + sv * ws.y;
            v[2] += b0.z + fb * (b1.z - b0.z) + C.z + cv * wc.z + sv * ws.z;
            v[3] += b0.w + fb * (b1.w - b0.w) + C.w + cv * wc.w + sv * ws.w;
        }
        uint2 oh, om;
        silu_split2(v[0], v[1], &oh.x, &om.x);
        silu_split2(v[2], v[3], &oh.y, &om.y);
        *(uint2*)(Chi + (size_t)row * HDIM + c4 * 4) = oh;
        *(uint2*)(Cmid + (size_t)row * HDIM + c4 * 4) = om;
    }
}

__global__ void sum_kernel(const float* __restrict__ scr, const float* __restrict__ b3,
                           float* __restrict__ out, int n3) {
    int i = blockIdx.x * 256 + threadIdx.x;
    if (i >= n3) return;
    int row = i / 3, o = i % 3;
    out[i] = scr[row * 6 + o] + scr[row * 6 + 3 + o] + b3[o];
}

extern "C" void kernel_launch(void* const* d_in, const int* in_sizes, int n_in,
                              void* d_out, int out_size) {
    const float* h = (const float*)d_in[0];
    const int* src = (const int*)d_in[1];
    const int* dst = (const int*)d_in[2];
    const float* enorm = (const float*)d_in[3];
    const int* tsrc = (const int*)d_in[4];
    const int* tdi = (const int*)d_in[5];
    const int* tdj = (const int*)d_in[6];
    const float* nij = (const float*)d_in[7];
    const float* nik = (const float*)d_in[8];
    const float* cosv = (const float*)d_in[9];
    const float* sinv = (const float*)d_in[10];
    const float* mu = (const float*)d_in[11];
    const float* eW0 = (const float*)d_in[12];
    const float* eW1 = (const float*)d_in[13];
    const float* eW2 = (const float*)d_in[14];
    const float* eW3 = (const float*)d_in[15];
    const float* eb3 = (const float*)d_in[16];
    const float* tW0 = (const float*)d_in[17];
    const float* tW1 = (const float*)d_in[18];
    const float* tW2 = (const float*)d_in[19];
    const float* tW3 = (const float*)d_in[20];
    const float* tb3 = (const float*)d_in[21];
    float* out = (float*)d_out;

    __half *xH, *xM, *yH, *yM, *hH, *hM, *wW;
    float *P, *T, *scr;
    cudaGetSymbolAddress((void**)&xH, g_x_hi);
    cudaGetSymbolAddress((void**)&xM, g_x_mid);
    cudaGetSymbolAddress((void**)&yH, g_y_hi);
    cudaGetSymbolAddress((void**)&yM, g_y_mid);
    cudaGetSymbolAddress((void**)&hH, g_h_hi);
    cudaGetSymbolAddress((void**)&hM, g_h_mid);
    cudaGetSymbolAddress((void**)&wW, g_w);
    cudaGetSymbolAddress((void**)&P, g_P);
    cudaGetSymbolAddress((void**)&T, g_T);
    cudaGetSymbolAddress((void**)&scr, g_scr);

    cudaFuncSetAttribute(gemm_kernel<0>, cudaFuncAttributeMaxDynamicSharedMemorySize, SMEM_GEMM);
    cudaFuncSetAttribute(gemm_kernel<2>, cudaFuncAttributeMaxDynamicSharedMemorySize, SMEM_GEMM);
    cudaFuncSetAttribute(pgemm_kernel, cudaFuncAttributeMaxDynamicSharedMemorySize, SMEM_GEMM);

    prep_h_kernel<<<(NPAD * FDIM) / 256, 256>>>(h, hH, hM);
    WS S;
    const float* srcs[9] = {eW0, eW0 + 32768, eW1, eW2, tW0, tW0 + 32768, tW0 + 65536, tW1, tW2};
    int KPs[9] = {128, 128, 256, 256, 128, 128, 128, 256, 256};
    int offs[9] = {E0A, E0B, E1, E2, T0A, T0B, T0C, T1, T2};
    for (int i = 0; i < 9; i++) { S.src[i] = srcs[i]; S.KP[i] = KPs[i]; S.off[i] = offs[i]; }
    prep_w_kernel<<<dim3(256, 1, 9), 256>>>(S, wW);
    PG pg;
    int boffs[5] = {E0A, E0B, T0A, T0B, T0C};
    for (int i = 0; i < 5; i++) { pg.boff[i] = boffs[i]; pg.coff[i] = (size_t)i * PSZ; }
    pgemm_kernel<<<dim3(2, NPAD / 128, 5), 256, SMEM_GEMM>>>(hH, hM, wW, P, pg);
    table_kernel<<<dim3((TROWS + 31) / 32, 4, 3), 256>>>(eW0, tW0, mu);

    float *Pea = P, *Peb = P + PSZ, *Pta = P + 2 * PSZ, *Ptb = P + 3 * PSZ, *Ptc = P + 4 * PSZ;
    dim3 ge(2, E_EDGES / 128), gt(2, T_TRIP / 128);
    // edge path (launch #6 = mid gemm -> ncu capture)
    l0g_kernel<0><<<E_EDGES / 8, 256>>>(enorm, nullptr, nullptr, nullptr,
                                        src, dst, nullptr, T, nullptr, nullptr,
                                        Pea, Peb, nullptr, xH, xM);
    gemm_kernel<0><<<ge, 256, SMEM_GEMM>>>(xH, xM, wW + E1, 256, 4, yH, yM, nullptr);
    gemm_kernel<2><<<ge, 256, SMEM_GEMM>>>(yH, yM, wW + E2, 256, 4, scr, nullptr, eW3);
    sum_kernel<<<(E_EDGES * 3 + 255) / 256, 256>>>(scr, eb3, out, E_EDGES * 3);
    // triplet path
    l0g_kernel<1><<<T_TRIP / 8, 256>>>(nij, nik, cosv, sinv,
                                       tsrc, tdi, tdj, T + TOFF, T + 2 * TOFF,
                                       tW0 + 149504, Pta, Ptb, Ptc, xH, xM);
    gemm_kernel<0><<<gt, 256, SMEM_GEMM>>>(xH, xM, wW + T1, 256, 4, yH, yM, nullptr);
    gemm_kernel<2><<<gt, 256, SMEM_GEMM>>>(yH, yM, wW + T2, 256, 4, scr, nullptr, tW3);
    sum_kernel<<<(T_TRIP * 3 + 255) / 256, 256>>>(scr, tb3, out + (size_t)E_EDGES * 3,
                                                  T_TRIP * 3);
}

// round 13
// speedup vs baseline: 2.9157x; 1.0535x over previous
#include <cuda_runtime.h>
#include <cuda_fp16.h>
#include <cstdint>

#define FDIM 128
#define HDIM 256
#define E_EDGES 262144
#define T_TRIP 393216
#define NPAD 20096
#define TABN 4096
#define TROWS 4097
#define TOFF ((size_t)TROWS * 256)

// CTA 128x128: A fp16 2-limb (2x16KB) + B fp16 1-limb (16KB) per 64-K chunk
#define SA_HI 0
#define SA_MID (16 * 1024)
#define SB (32 * 1024)
#define STAGE_BYTES (48 * 1024)
#define SMEM_GEMM (2 * STAGE_BYTES)

__device__ __half g_x_hi[(size_t)T_TRIP * HDIM];
__device__ __half g_x_mid[(size_t)T_TRIP * HDIM];
__device__ __half g_y_hi[(size_t)T_TRIP * HDIM];
__device__ __half g_y_mid[(size_t)T_TRIP * HDIM];
__device__ __half g_h_hi[(size_t)NPAD * FDIM];
__device__ __half g_h_mid[(size_t)NPAD * FDIM];
__device__ float g_P[5ull * NPAD * HDIM];
__device__ float g_T[3 * TOFF];
__device__ float g_scr[(size_t)T_TRIP * 6];
#define PSZ ((size_t)NPAD * HDIM)
#define E0A 0
#define E0B 32768
#define E1 98304
#define E2 163840
#define T0A 229376
#define T0B 262144
#define T0C 294912
#define T1 393216
#define T2 458752
__device__ __half g_w[524288];

__device__ __forceinline__ uint32_t smem_u32(const void* p) {
    uint32_t a;
    asm("{ .reg .u64 t; cvta.to.shared.u64 t, %1; cvt.u32.u64 %0, t; }" : "=r"(a) : "l"(p));
    return a;
}
__device__ __forceinline__ void cp16(uint32_t d, const void* s) {
    asm volatile("cp.async.cg.shared.global [%0], [%1], 16;" :: "r"(d), "l"(s));
}
#define CP_COMMIT() asm volatile("cp.async.commit_group;" ::: "memory")
#define CP_WAIT0() asm volatile("cp.async.wait_group 0;" ::: "memory")
#define CP_WAIT1() asm volatile("cp.async.wait_group 1;" ::: "memory")
#define LDSM4(r0, r1, r2, r3, a) \
    asm volatile("ldmatrix.sync.aligned.m8n8.x4.shared.b16 {%0,%1,%2,%3}, [%4];" \
                 : "=r"(r0), "=r"(r1), "=r"(r2), "=r"(r3) : "r"(a))

__device__ __forceinline__ void mma_f16(float c[4], const uint32_t a[4], const uint32_t b[2]) {
    asm volatile(
        "mma.sync.aligned.m16n8k16.row.col.f32.f16.f16.f32 "
        "{%0,%1,%2,%3}, {%4,%5,%6,%7}, {%8,%9}, {%0,%1,%2,%3};"
        : "+f"(c[0]), "+f"(c[1]), "+f"(c[2]), "+f"(c[3])
        : "r"(a[0]), "r"(a[1]), "r"(a[2]), "r"(a[3]), "r"(b[0]), "r"(b[1]));
}
__device__ __forceinline__ float silu_f(float x) { return x / (1.0f + __expf(-x)); }
__device__ __forceinline__ uint32_t pkhf2(__half a, __half b) {
    __half2 v(a, b);
    return *reinterpret_cast<uint32_t*>(&v);
}
__device__ __forceinline__ void silu_split2(float v0, float v1, uint32_t* oh, uint32_t* om) {
    float a0 = silu_f(v0), a1 = silu_f(v1);
    __half h0 = __float2half_rn(a0), h1 = __float2half_rn(a1);
    *oh = pkhf2(h0, h1);
    *om = pkhf2(__float2half_rn(a0 - __half2float(h0)),
                __float2half_rn(a1 - __half2float(h1)));
}

struct Frag {
    int a_row, a_kh, b_row, b_kh;
};
__device__ __forceinline__ void mma_chunk(uint32_t stage, int wm, int wn, const Frag& f,
                                          float acc[2][8][4]) {
#pragma unroll
    for (int ks = 0; ks < 4; ks++) {
        uint32_t aHf[2][4], aMf[2][4], bF[8][2];
#pragma unroll
        for (int mt = 0; mt < 2; mt++) {
            int r = wm + mt * 16 + f.a_row;
            uint32_t off = r * 128 + (((ks * 2 + f.a_kh) ^ (r & 7)) << 4);
            LDSM4(aHf[mt][0], aHf[mt][1], aHf[mt][2], aHf[mt][3], stage + SA_HI + off);
            LDSM4(aMf[mt][0], aMf[mt][1], aMf[mt][2], aMf[mt][3], stage + SA_MID + off);
        }
#pragma unroll
        for (int np = 0; np < 4; np++) {
            int r = wn + np * 16 + f.b_row;
            uint32_t off = r * 128 + (((ks * 2 + f.b_kh) ^ (r & 7)) << 4);
            uint32_t r0, r1, r2, r3;
            LDSM4(r0, r1, r2, r3, stage + SB + off);
            bF[np * 2][0] = r0; bF[np * 2][1] = r1;
            bF[np * 2 + 1][0] = r2; bF[np * 2 + 1][1] = r3;
        }
#pragma unroll
        for (int mt = 0; mt < 2; mt++)
#pragma unroll
            for (int nt = 0; nt < 8; nt++) {
                mma_f16(acc[mt][nt], aHf[mt], bF[nt]);
                mma_f16(acc[mt][nt], aMf[mt], bF[nt]);
            }
    }
}

__device__ __forceinline__ void load_chunk(uint32_t stage, int t, size_t koff,
                                           const char* aH, const char* aM,
                                           const char* bW, size_t ldb) {
#pragma unroll
    for (int i = 0; i < 4; i++) {
        int idx = t + i * 256;
        int r = idx >> 3, c16 = idx & 7;
        uint32_t doff = r * 128 + ((c16 ^ (r & 7)) << 4);
        size_t soff = (size_t)r * ldb + koff + c16 * 16;
        cp16(stage + SA_HI + doff, aH + soff);
        cp16(stage + SA_MID + doff, aM + soff);
        cp16(stage + SB + doff, bW + soff);
    }
    CP_COMMIT();
}

// EPI: 0 = silu+fp16 limb split, 1 = raw f32, 2 = fused out-layer (W3 partials)
template <int EPI, int NC>
__device__ __forceinline__ void gemm_core(
    const __half* Ahi, const __half* Amid, const __half* Bw,
    int ld, void* C1, void* C2, const float* W3,
    int row0, int n0cta, int cblk, char* smem) {
    uint32_t sb = smem_u32(smem);
    int t = threadIdx.x, lane = t & 31, w = t >> 5;
    int wm = (w & 3) * 32, wn = (w >> 2) * 64;

    const char* aH = (const char*)(Ahi + (size_t)row0 * ld);
    const char* aM = (const char*)(Amid + (size_t)row0 * ld);
    const char* bW = (const char*)(Bw + (size_t)n0cta * ld);
    const size_t ldb = (size_t)ld * 2;

    float acc[2][8][4];
#pragma unroll
    for (int i = 0; i < 2; i++)
#pragma unroll
        for (int j = 0; j < 8; j++)
#pragma unroll
            for (int q = 0; q < 4; q++) acc[i][j][q] = 0.0f;
    Frag f{lane & 15, lane >> 4, (lane & 7) + ((lane >> 4) << 3), (lane >> 3) & 1};

    load_chunk(sb, t, 0, aH, aM, bW, ldb);
#pragma unroll
    for (int c = 0; c < NC; c++) {
        if (c + 1 < NC) {
            load_chunk(sb + ((c + 1) & 1) * STAGE_BYTES, t, (size_t)(c + 1) * 128,
                       aH, aM, bW, ldb);
            CP_WAIT1();
        } else {
            CP_WAIT0();
        }
        __syncthreads();
        mma_chunk(sb + (c & 1) * STAGE_BYTES, wm, wn, f, acc);
        __syncthreads();
    }

    int mrow = lane >> 2, ncol = (lane & 3) * 2;
    if (EPI == 2) {
        float* w3s = (float*)smem;
        float* rsum = (float*)smem + 384;
        for (int i = t; i < 384; i += 256) w3s[i] = W3[n0cta * 3 + i];
        for (int i = t; i < 384; i += 256) rsum[i] = 0.0f;
        __syncthreads();
        float part[4][3];
#pragma unroll
        for (int rs = 0; rs < 4; rs++)
#pragma unroll
            for (int o = 0; o < 3; o++) part[rs][o] = 0.0f;
#pragma unroll
        for (int mt = 0; mt < 2; mt++)
#pragma unroll
            for (int nt = 0; nt < 8; nt++)
#pragma unroll
                for (int sr = 0; sr < 2; sr++)
#pragma unroll
                    for (int e = 0; e < 2; e++) {
                        int cl = wn + nt * 8 + ncol + e;
                        float v = silu_f(acc[mt][nt][sr * 2 + e]);
#pragma unroll
                        for (int o = 0; o < 3; o++)
                            part[mt * 2 + sr][o] = fmaf(v, w3s[cl * 3 + o], part[mt * 2 + sr][o]);
                    }
#pragma unroll
        for (int rs = 0; rs < 4; rs++)
#pragma unroll
            for (int o = 0; o < 3; o++) {
                part[rs][o] += __shfl_xor_sync(0xffffffffu, part[rs][o], 1);
                part[rs][o] += __shfl_xor_sync(0xffffffffu, part[rs][o], 2);
            }
        if ((w >> 2) == 0 && (lane & 3) == 0) {
#pragma unroll
            for (int rs = 0; rs < 4; rs++) {
                int r = wm + (rs >> 1) * 16 + (rs & 1) * 8 + mrow;
#pragma unroll
                for (int o = 0; o < 3; o++) rsum[r * 3 + o] = part[rs][o];
            }
        }
        __syncthreads();
        if ((w >> 2) == 1 && (lane & 3) == 0) {
#pragma unroll
            for (int rs = 0; rs < 4; rs++) {
                int r = wm + (rs >> 1) * 16 + (rs & 1) * 8 + mrow;
#pragma unroll
                for (int o = 0; o < 3; o++) rsum[r * 3 + o] += part[rs][o];
            }
        }
        __syncthreads();
        float* scr = (float*)C1;
        for (int i = t; i < 384; i += 256) {
            int r = i / 3, o = i % 3;
            scr[((size_t)(row0 + r) * 2 + cblk) * 3 + o] = rsum[i];
        }
        return;
    }
#pragma unroll
    for (int mt = 0; mt < 2; mt++)
#pragma unroll
        for (int nt = 0; nt < 8; nt++) {
            int r = row0 + wm + mt * 16 + mrow;
            int cc = n0cta + wn + nt * 8 + ncol;
            if (EPI == 0) {
                uint32_t oh, om;
                silu_split2(acc[mt][nt][0], acc[mt][nt][1], &oh, &om);
                *(uint32_t*)((__half*)C1 + (size_t)r * HDIM + cc) = oh;
                *(uint32_t*)((__half*)C2 + (size_t)r * HDIM + cc) = om;
                silu_split2(acc[mt][nt][2], acc[mt][nt][3], &oh, &om);
                *(uint32_t*)((__half*)C1 + (size_t)(r + 8) * HDIM + cc) = oh;
                *(uint32_t*)((__half*)C2 + (size_t)(r + 8) * HDIM + cc) = om;
            } else {
                *(float2*)((float*)C1 + (size_t)r * HDIM + cc) =
                    make_float2(acc[mt][nt][0], acc[mt][nt][1]);
                *(float2*)((float*)C1 + (size_t)(r + 8) * HDIM + cc) =
                    make_float2(acc[mt][nt][2], acc[mt][nt][3]);
            }
        }
}

template <int EPI, int NC>
__global__ void __launch_bounds__(256, 2) gemm_kernel(
    const __half* __restrict__ Ahi, const __half* __restrict__ Amid,
    const __half* __restrict__ Bw,
    int ld, void* __restrict__ C1, void* __restrict__ C2,
    const float* __restrict__ W3) {
    extern __shared__ char smem[];
    gemm_core<EPI, NC>(Ahi, Amid, Bw, ld, C1, C2, W3,
                       blockIdx.y * 128, blockIdx.x * 128, blockIdx.x, smem);
}

struct PG {
    int boff[5];
    size_t coff[5];
};
__global__ void __launch_bounds__(256, 2) pgemm_kernel(
    const __half* __restrict__ hH, const __half* __restrict__ hM,
    const __half* __restrict__ wW, float* __restrict__ P, PG pg) {
    extern __shared__ char smem[];
    int z = blockIdx.z;
    gemm_core<1, 2>(hH, hM, wW + pg.boff[z], 128,
                    P + pg.coff[z], nullptr, nullptr,
                    blockIdx.y * 128, blockIdx.x * 128, blockIdx.x, smem);
}

__global__ void prep_h_kernel(const float* __restrict__ h,
                              __half* __restrict__ hi, __half* __restrict__ mid) {
    size_t idx = (size_t)blockIdx.x * 256 + threadIdx.x;
    int row = (int)(idx >> 7);
    float v = (row < 20000) ? h[idx] : 0.0f;
    __half hh = __float2half_rn(v);
    hi[idx] = hh;
    mid[idx] = __float2half_rn(v - __half2float(hh));
}

struct WS {
    const float* src[9];
    int KP[9], off[9];
};
__global__ void prep_w_kernel(WS S, __half* __restrict__ w) {
    int z = blockIdx.z;
    int KP = S.KP[z];
    if (blockIdx.x >= KP) return;
    int idx = blockIdx.x * 256 + threadIdx.x;
    int n = idx / KP, k = idx % KP;
    w[S.off[z] + idx] = __float2half_rn(S.src[z][(size_t)k * HDIM + n]);
}

// Tables, k-outer: thread = (col, row-lane), 8 row accumulators, 1 W-LDS per k.
__global__ void table_kernel(const float* __restrict__ eW0, const float* __restrict__ tW0,
                             const float* __restrict__ mu) {
    __shared__ float Wsm[100 * 64];
    __shared__ float rbf[32 * 100];
    int z = blockIdx.z, cb = blockIdx.y, r0 = blockIdx.x * 32;
    const float* Wsrc = ((z == 0) ? eW0 + 65536 : ((z == 1) ? tW0 + 98304 : tW0 + 123904))
                        + cb * 64;
    float* Tout = g_T + (size_t)z * TOFF + cb * 64;
    int t = threadIdx.x;
    for (int i = t; i < 6400; i += 256) {
        int k = i >> 6, c = i & 63;
        Wsm[i] = Wsrc[k * 256 + c];
    }
    for (int i = t; i < 3200; i += 256) {
        int rr = i / 100, k = i % 100;
        float r = (float)(r0 + rr) * (10.0f / (float)TABN);
        float d = __ldg(mu + k) - r;
        rbf[i] = expf(-10.0f * d * d);
    }
    __syncthreads();
    int col = t & 63, rl = t >> 6;
    float acc[8];
#pragma unroll
    for (int p = 0; p < 8; p++) acc[p] = 0.0f;
#pragma unroll 4
    for (int k = 0; k < 100; k++) {
        float wv = Wsm[k * 64 + col];
#pragma unroll
        for (int p = 0; p < 8; p++)
            acc[p] = fmaf(rbf[(rl + p * 4) * 100 + k], wv, acc[p]);
    }
#pragma unroll
    for (int p = 0; p < 8; p++) {
        int row = r0 + rl + p * 4;
        if (row <= TABN) Tout[(size_t)row * 256 + col] = acc[p];
    }
}

template <int MODE>
__global__ void __launch_bounds__(256) l0g_kernel(
    const float* __restrict__ rA, const float* __restrict__ rB,
    const float* __restrict__ cosv, const float* __restrict__ sinv,
    const int* __restrict__ iA, const int* __restrict__ iB, const int* __restrict__ iC,
    const float* __restrict__ Ta, const float* __restrict__ Tb,
    const float* __restrict__ Wcs,
    const float* __restrict__ Pa, const float* __restrict__ Pb, const float* __restrict__ Pc,
    __half* __restrict__ Chi, __half* __restrict__ Cmid) {
    int w = threadIdx.x >> 5, lane = threadIdx.x & 31;
    int row = blockIdx.x * 8 + w;

    float ua = rA[row] * ((float)TABN / 10.0f);
    int ia = min((int)ua, TABN - 1);
    float fa = ua - (float)ia;
    const float4* t0 = (const float4*)(Ta + (size_t)ia * 256);
    const float4* pa = (const float4*)(Pa + (size_t)iA[row] * HDIM);
    const float4* pb = (const float4*)(Pb + (size_t)iB[row] * HDIM);

    const float4* u0 = nullptr;
    const float4* pc = nullptr;
    float fb = 0.0f, cv = 0.0f, sv = 0.0f;
    if (MODE) {
        float ub = rB[row] * ((float)TABN / 10.0f);
        int ib = min((int)ub, TABN - 1);
        fb = ub - (float)ib;
        u0 = (const float4*)(Tb + (size_t)ib * 256);
        pc = (const float4*)(Pc + (size_t)iC[row] * HDIM);
        cv = cosv[row];
        sv = sinv[row];
    }

#pragma unroll
    for (int g = 0; g < 2; g++) {
        int c4 = lane + g * 32;
        float4 a0 = t0[c4], a1 = t0[c4 + 64];
        float4 A = pa[c4], B = pb[c4];
        float v[4];
        v[0] = a0.x + fa * (a1.x - a0.x) + A.x + B.x;
        v[1] = a0.y + fa * (a1.y - a0.y) + A.y + B.y;
        v[2] = a0.z + fa * (a1.z - a0.z) + A.z + B.z;
        v[3] = a0.w + fa * (a1.w - a0.w) + A.w + B.w;
        if (MODE) {
            float4 b0 = u0[c4], b1 = u0[c4 + 64];
            float4 C = pc[c4];
            float4 wc = ((const float4*)Wcs)[c4];
            float4 ws = ((const float4*)(Wcs + 256))[c4];
            v[0] += b0.x + fb * (b1.x - b0.x) + C.x + cv * wc.x + sv * ws.x;
            v[1] += b0.y + fb * (b1.y - b0.y) + C.y + cv * wc.y + sv * ws.y;
            v[2] += b0.z + fb * (b1.z - b0.z) + C.z + cv * wc.z + sv * ws.z;
            v[3] += b0.w + fb * (b1.w - b0.w) + C.w + cv * wc.w + sv * ws.w;
        }
        uint2 oh, om;
        silu_split2(v[0], v[1], &oh.x, &om.x);
        silu_split2(v[2], v[3], &oh.y, &om.y);
        *(uint2*)(Chi + (size_t)row * HDIM + c4 * 4) = oh;
        *(uint2*)(Cmid + (size_t)row * HDIM + c4 * 4) = om;
    }
}

__global__ void sum_kernel(const float* __restrict__ scr, const float* __restrict__ b3,
                           float* __restrict__ out, int n3) {
    int i = blockIdx.x * 256 + threadIdx.x;
    if (i >= n3) return;
    int row = i / 3, o = i % 3;
    out[i] = scr[row * 6 + o] + scr[row * 6 + 3 + o] + b3[o];
}

extern "C" void kernel_launch(void* const* d_in, const int* in_sizes, int n_in,
                              void* d_out, int out_size) {
    const float* h = (const float*)d_in[0];
    const int* src = (const int*)d_in[1];
    const int* dst = (const int*)d_in[2];
    const float* enorm = (const float*)d_in[3];
    const int* tsrc = (const int*)d_in[4];
    const int* tdi = (const int*)d_in[5];
    const int* tdj = (const int*)d_in[6];
    const float* nij = (const float*)d_in[7];
    const float* nik = (const float*)d_in[8];
    const float* cosv = (const float*)d_in[9];
    const float* sinv = (const float*)d_in[10];
    const float* mu = (const float*)d_in[11];
    const float* eW0 = (const float*)d_in[12];
    const float* eW1 = (const float*)d_in[13];
    const float* eW2 = (const float*)d_in[14];
    const float* eW3 = (const float*)d_in[15];
    const float* eb3 = (const float*)d_in[16];
    const float* tW0 = (const float*)d_in[17];
    const float* tW1 = (const float*)d_in[18];
    const float* tW2 = (const float*)d_in[19];
    const float* tW3 = (const float*)d_in[20];
    const float* tb3 = (const float*)d_in[21];
    float* out = (float*)d_out;

    __half *xH, *xM, *yH, *yM, *hH, *hM, *wW;
    float *P, *T, *scr;
    cudaGetSymbolAddress((void**)&xH, g_x_hi);
    cudaGetSymbolAddress((void**)&xM, g_x_mid);
    cudaGetSymbolAddress((void**)&yH, g_y_hi);
    cudaGetSymbolAddress((void**)&yM, g_y_mid);
    cudaGetSymbolAddress((void**)&hH, g_h_hi);
    cudaGetSymbolAddress((void**)&hM, g_h_mid);
    cudaGetSymbolAddress((void**)&wW, g_w);
    cudaGetSymbolAddress((void**)&P, g_P);
    cudaGetSymbolAddress((void**)&T, g_T);
    cudaGetSymbolAddress((void**)&scr, g_scr);

    cudaFuncSetAttribute((const void*)gemm_kernel<0, 4>,
                         cudaFuncAttributeMaxDynamicSharedMemorySize, SMEM_GEMM);
    cudaFuncSetAttribute((const void*)gemm_kernel<2, 4>,
                         cudaFuncAttributeMaxDynamicSharedMemorySize, SMEM_GEMM);
    cudaFuncSetAttribute((const void*)pgemm_kernel,
                         cudaFuncAttributeMaxDynamicSharedMemorySize, SMEM_GEMM);

    WS S;
    const float* srcs[9] = {eW0, eW0 + 32768, eW1, eW2, tW0, tW0 + 32768, tW0 + 65536, tW1, tW2};
    int KPs[9] = {128, 128, 256, 256, 128, 128, 128, 256, 256};
    int offs[9] = {E0A, E0B, E1, E2, T0A, T0B, T0C, T1, T2};
    for (int i = 0; i < 9; i++) { S.src[i] = srcs[i]; S.KP[i] = KPs[i]; S.off[i] = offs[i]; }
    // launch order: 4th = pgemm (ncu capture target)
    prep_w_kernel<<<dim3(256, 1, 9), 256>>>(S, wW);
    prep_h_kernel<<<(NPAD * FDIM) / 256, 256>>>(h, hH, hM);
    table_kernel<<<dim3((TROWS + 31) / 32, 4, 3), 256>>>(eW0, tW0, mu);
    PG pg;
    int boffs[5] = {E0A, E0B, T0A, T0B, T0C};
    for (int i = 0; i < 5; i++) { pg.boff[i] = boffs[i]; pg.coff[i] = (size_t)i * PSZ; }
    pgemm_kernel<<<dim3(2, NPAD / 128, 5), 256, SMEM_GEMM>>>(hH, hM, wW, P, pg);

    float *Pea = P, *Peb = P + PSZ, *Pta = P + 2 * PSZ, *Ptb = P + 3 * PSZ, *Ptc = P + 4 * PSZ;
    dim3 ge(2, E_EDGES / 128), gt(2, T_TRIP / 128);
    l0g_kernel<0><<<E_EDGES / 8, 256>>>(enorm, nullptr, nullptr, nullptr,
                                        src, dst, nullptr, T, nullptr, nullptr,
                                        Pea, Peb, nullptr, xH, xM);
    gemm_kernel<0, 4><<<ge, 256, SMEM_GEMM>>>(xH, xM, wW + E1, 256, yH, yM, nullptr);
    gemm_kernel<2, 4><<<ge, 256, SMEM_GEMM>>>(yH, yM, wW + E2, 256, scr, nullptr, eW3);
    sum_kernel<<<(E_EDGES * 3 + 255) / 256, 256>>>(scr, eb3, out, E_EDGES * 3);
    l0g_kernel<1><<<T_TRIP / 8, 256>>>(nij, nik, cosv, sinv,
                                       tsrc, tdi, tdj, T + TOFF, T + 2 * TOFF,
                                       tW0 + 149504, Pta, Ptb, Ptc, xH, xM);
    gemm_kernel<0, 4><<<gt, 256, SMEM_GEMM>>>(xH, xM, wW + T1, 256, yH, yM, nullptr);
    gemm_kernel<2, 4><<<gt, 256, SMEM_GEMM>>>(yH, yM, wW + T2, 256, scr, nullptr, tW3);
    sum_kernel<<<(T_TRIP * 3 + 255) / 256, 256>>>(scr, tb3, out + (size_t)E_EDGES * 3,
                                                  T_TRIP * 3);
}